// round 2
// baseline (speedup 1.0000x reference)
#include <cuda_runtime.h>
#include <math.h>

#define BB 4
#define CC 64
#define CI 16
#define PP 4096
#define NCOL 64
#define TP 128

// ---------------- scratch (device globals; no allocations allowed) ----------
__device__ float g_q[BB*PP*CI];      // [b][p][o]
__device__ float g_k[BB*CI*PP];      // [b][o][p]
__device__ float g_v[BB*CC*PP];      // [b][c][p]
__device__ float g_out[BB*CC*PP];    // pre-gate output
__device__ float g_sum[BB*CC];
__device__ unsigned g_maxk[BB*CC];
__device__ float g_gate[BB*CC];

// monotone float<->uint key for atomicMax on floats (any sign)
__device__ __forceinline__ unsigned fkey(float f) {
    unsigned u = __float_as_uint(f);
    return (u & 0x80000000u) ? ~u : (u | 0x80000000u);
}
__device__ __forceinline__ float funkey(unsigned k) {
    unsigned u = (k & 0x80000000u) ? (k & 0x7FFFFFFFu) : ~k;
    return __uint_as_float(u);
}

// ---------------- K1: q/k/v projections -------------------------------------
// grid (PP/128, BB), 256 threads. thread = (p_local = tid&127, half = tid>>7)
__global__ void qkv_kernel(const float* __restrict__ ftr,
                           const float* __restrict__ wq, const float* __restrict__ bq,
                           const float* __restrict__ wk, const float* __restrict__ bk,
                           const float* __restrict__ wv, const float* __restrict__ bv)
{
    __shared__ float ws[96*64];   // rows: 0-15 wq, 16-31 wk, 32-95 wv
    __shared__ float bs[96];
    int tid = threadIdx.x;
    for (int i = tid; i < 16*64; i += 256) ws[i] = wq[i];
    for (int i = tid; i < 16*64; i += 256) ws[16*64 + i] = wk[i];
    for (int i = tid; i < 64*64; i += 256) ws[32*64 + i] = wv[i];
    if (tid < 16) bs[tid] = bq[tid];
    else if (tid < 32) bs[tid] = bk[tid - 16];
    else if (tid < 96) bs[tid] = bv[tid - 32];
    // zero SE reduction buffers once (this kernel finishes before attn starts)
    if (blockIdx.x == 0 && blockIdx.y == 0 && tid < BB*CC) {
        g_sum[tid] = 0.0f;
        g_maxk[tid] = 0u;
    }
    __syncthreads();

    int b = blockIdx.y;
    int p = blockIdx.x * 128 + (tid & 127);
    int half = tid >> 7;
    const float* x = ftr + (size_t)b*CC*PP + p;

    float acc[48];
#pragma unroll
    for (int i = 0; i < 48; i++) acc[i] = 0.0f;

    if (half == 0) {
        for (int c = 0; c < 64; c++) {
            float xc = x[(size_t)c*PP];
#pragma unroll
            for (int i = 0; i < 48; i++) acc[i] += ws[i*64 + c] * xc;
        }
        float* qp = g_q + ((size_t)b*PP + p)*CI;
#pragma unroll
        for (int o = 0; o < 16; o++) qp[o] = acc[o] + bs[o];
#pragma unroll
        for (int o = 0; o < 16; o++) g_k[((size_t)b*CI + o)*PP + p] = acc[16 + o] + bs[16 + o];
#pragma unroll
        for (int c2 = 0; c2 < 16; c2++) g_v[((size_t)b*CC + c2)*PP + p] = acc[32 + c2] + bs[32 + c2];
    } else {
        for (int c = 0; c < 64; c++) {
            float xc = x[(size_t)c*PP];
#pragma unroll
            for (int i = 0; i < 48; i++) acc[i] += ws[(48 + i)*64 + c] * xc;
        }
#pragma unroll
        for (int i = 0; i < 48; i++) g_v[((size_t)b*CC + 16 + i)*PP + p] = acc[i] + bs[48 + i];
    }
}

// ---------------- K2: streaming (flash-style) attention ----------------------
struct Smem2 {
    float q[TP][CI];        // 8 KB
    float v[CC][TP];        // 32 KB
    float s[TP][NCOL];      // 32 KB (scores, then exp weights)
    float red_m[4][NCOL];   // 1 KB
    float red_l[4][NCOL];   // 1 KB
};

extern __shared__ char smem_raw[];

// grid (PP/NCOL, BB), 256 threads. thread: j = tid&63 (column), g = tid>>6 (channel group of 16)
__global__ void attn_kernel(const float* __restrict__ ftr, const float* __restrict__ delta)
{
    Smem2& sm = *reinterpret_cast<Smem2*>(smem_raw);
    int tid = threadIdx.x;
    int j = tid & 63;
    int g = tid >> 6;
    int b = blockIdx.y;
    int col = blockIdx.x * NCOL + j;

    float kj[CI];
#pragma unroll
    for (int o = 0; o < CI; o++) kj[o] = g_k[((size_t)b*CI + o)*PP + col];

    float acc[16];
#pragma unroll
    for (int i = 0; i < 16; i++) acc[i] = 0.0f;
    float m = -INFINITY, l = 0.0f;

    const float* qbase = g_q + (size_t)b*PP*CI;
    const float* vbase = g_v + (size_t)b*CC*PP;

    for (int t = 0; t < PP/TP; t++) {
        int p0 = t * TP;
        // load q tile (2048 floats) — contiguous
        {
            const float4* qsrc = reinterpret_cast<const float4*>(qbase + (size_t)p0*CI);
            float4* qdst = reinterpret_cast<float4*>(&sm.q[0][0]);
            qdst[tid] = qsrc[tid];
            qdst[tid + 256] = qsrc[tid + 256];
        }
        // load v tile (64 rows x 128 floats)
#pragma unroll
        for (int r = 0; r < 8; r++) {
            int idx = r*256 + tid;      // float4 index, 0..2047
            int row = idx >> 5;
            int cp = idx & 31;
            reinterpret_cast<float4*>(&sm.v[row][0])[cp] =
                reinterpret_cast<const float4*>(vbase + (size_t)row*PP + p0)[cp];
        }
        __syncthreads();

        // scores for p in [g*32, g*32+32), column j
        float lmax = -INFINITY;
#pragma unroll 4
        for (int i = 0; i < 32; i++) {
            int p = g*32 + i;
            const float* qp = &sm.q[p][0];
            float s = 0.0f;
#pragma unroll
            for (int o = 0; o < 16; o++) s += qp[o] * kj[o];
            sm.s[p][j] = s;
            lmax = fmaxf(lmax, s);
        }
        sm.red_m[g][j] = lmax;
        __syncthreads();

        float mt = fmaxf(fmaxf(sm.red_m[0][j], sm.red_m[1][j]),
                         fmaxf(sm.red_m[2][j], sm.red_m[3][j]));
        float mnew = fmaxf(m, mt);
        float scale = __expf(m - mnew);     // first tile: exp(-inf)=0
#pragma unroll
        for (int i = 0; i < 16; i++) acc[i] *= scale;

        float lp = 0.0f;
#pragma unroll 4
        for (int i = 0; i < 32; i++) {
            int p = g*32 + i;
            float e = __expf(sm.s[p][j] - mnew);
            sm.s[p][j] = e;
            lp += e;
        }
        sm.red_l[g][j] = lp;
        __syncthreads();

        l = l*scale + (sm.red_l[0][j] + sm.red_l[1][j] + sm.red_l[2][j] + sm.red_l[3][j]);
        m = mnew;

        // G update: acc[cc] += sum_p v[c][p] * e[p][j]
        for (int p = 0; p < TP; p += 4) {
            float e0 = sm.s[p + 0][j];
            float e1 = sm.s[p + 1][j];
            float e2 = sm.s[p + 2][j];
            float e3 = sm.s[p + 3][j];
#pragma unroll
            for (int cc = 0; cc < 16; cc++) {
                const float4 v4 = *reinterpret_cast<const float4*>(&sm.v[g*16 + cc][p]);
                acc[cc] = fmaf(v4.x, e0, acc[cc]);
                acc[cc] = fmaf(v4.y, e1, acc[cc]);
                acc[cc] = fmaf(v4.z, e2, acc[cc]);
                acc[cc] = fmaf(v4.w, e3, acc[cc]);
            }
        }
        __syncthreads();
    }

    // epilogue: out = delta * G/l + ftr ; feed SE pooling reductions
    float inv_l = 1.0f / l;
    float dlt = delta[0];
    float outv[16];
    const float* fb = ftr + ((size_t)b*CC + g*16)*PP + col;
#pragma unroll
    for (int cc = 0; cc < 16; cc++) {
        float o = dlt * acc[cc] * inv_l + fb[(size_t)cc*PP];
        outv[cc] = o;
        g_out[((size_t)b*CC + g*16 + cc)*PP + col] = o;
    }
    unsigned lane = tid & 31;
#pragma unroll
    for (int cc = 0; cc < 16; cc++) {
        float s = outv[cc];
        float mx = outv[cc];
#pragma unroll
        for (int off = 16; off; off >>= 1) {
            s += __shfl_xor_sync(0xffffffffu, s, off);
            mx = fmaxf(mx, __shfl_xor_sync(0xffffffffu, mx, off));
        }
        if (lane == 0) {
            atomicAdd(&g_sum[b*CC + g*16 + cc], s);
            atomicMax(&g_maxk[b*CC + g*16 + cc], fkey(mx));
        }
    }
}

// ---------------- K3: SE gate -------------------------------------------------
__global__ void gate_kernel(const float* __restrict__ w_avg1, const float* __restrict__ w_avg2,
                            const float* __restrict__ w_max1, const float* __restrict__ w_max2)
{
    __shared__ float h_avg[BB][CI], h_max[BB][CI];
    __shared__ float favg[BB][CC], fmaxv[BB][CC];
    int tid = threadIdx.x;   // 256
    int b = tid >> 6, c = tid & 63;
    favg[b][c] = g_sum[tid] * (1.0f / (float)PP);
    fmaxv[b][c] = funkey(g_maxk[tid]);
    __syncthreads();
    if (tid < 128) {
        int bb = tid >> 5;
        int rest = tid & 31;
        int branch = rest >> 4;
        int o = rest & 15;
        const float* w1 = branch ? w_max1 : w_avg1;
        const float* f = branch ? &fmaxv[bb][0] : &favg[bb][0];
        float h = 0.0f;
        for (int cc2 = 0; cc2 < 64; cc2++) h += w1[o*64 + cc2] * f[cc2];
        h = fmaxf(h, 0.0f);
        if (branch) h_max[bb][o] = h; else h_avg[bb][o] = h;
    }
    __syncthreads();
    float a = 0.0f, mm = 0.0f;
#pragma unroll
    for (int o = 0; o < 16; o++) {
        a  += w_avg2[c*16 + o] * h_avg[b][o];
        mm += w_max2[c*16 + o] * h_max[b][o];
    }
    g_gate[tid] = 1.0f / (1.0f + __expf(-(a + mm)));
}

// ---------------- K4: apply gate ---------------------------------------------
__global__ void final_kernel(float* __restrict__ out)
{
    int idx = blockIdx.x * 256 + threadIdx.x;   // float4 index, total 262144
    float4 v = reinterpret_cast<const float4*>(g_out)[idx];
    float gval = g_gate[idx >> 10];   // (idx*4)/PP, PP=4096
    v.x *= gval; v.y *= gval; v.z *= gval; v.w *= gval;
    reinterpret_cast<float4*>(out)[idx] = v;
}

// ---------------- launch ------------------------------------------------------
extern "C" void kernel_launch(void* const* d_in, const int* in_sizes, int n_in,
                              void* d_out, int out_size)
{
    const float* ftr    = (const float*)d_in[0];
    const float* wq     = (const float*)d_in[1];
    const float* bq     = (const float*)d_in[2];
    const float* wk     = (const float*)d_in[3];
    const float* bk     = (const float*)d_in[4];
    const float* wv     = (const float*)d_in[5];
    const float* bv     = (const float*)d_in[6];
    const float* delta  = (const float*)d_in[7];
    const float* w_avg1 = (const float*)d_in[8];
    const float* w_avg2 = (const float*)d_in[9];
    const float* w_max1 = (const float*)d_in[10];
    const float* w_max2 = (const float*)d_in[11];
    float* out = (float*)d_out;

    cudaFuncSetAttribute(attn_kernel, cudaFuncAttributeMaxDynamicSharedMemorySize,
                         (int)sizeof(Smem2));

    qkv_kernel<<<dim3(PP/128, BB), 256>>>(ftr, wq, bq, wk, bk, wv, bv);
    attn_kernel<<<dim3(PP/NCOL, BB), 256, sizeof(Smem2)>>>(ftr, delta);
    gate_kernel<<<1, 256>>>(w_avg1, w_avg2, w_max1, w_max2);
    final_kernel<<<1024, 256>>>(out);
}

// round 3
// speedup vs baseline: 1.0223x; 1.0223x over previous
#include <cuda_runtime.h>
#include <math.h>

#define BB 4
#define CC 64
#define CI 16
#define PP 4096
#define NCOL 64
#define TP 128

typedef unsigned long long ull;

// ---------------- scratch (device globals; no allocations allowed) ----------
__device__ float g_q[BB*PP*CI];      // [b][p][o]
__device__ float g_k[BB*CI*PP];      // [b][o][p]
__device__ float g_v[BB*CC*PP];      // [b][c][p]
__device__ float g_out[BB*CC*PP];    // pre-gate output
__device__ float g_sum[BB*CC];
__device__ unsigned g_maxk[BB*CC];
__device__ float g_gate[BB*CC];

// monotone float<->uint key for atomicMax on floats (any sign)
__device__ __forceinline__ unsigned fkey(float f) {
    unsigned u = __float_as_uint(f);
    return (u & 0x80000000u) ? ~u : (u | 0x80000000u);
}
__device__ __forceinline__ float funkey(unsigned k) {
    unsigned u = (k & 0x80000000u) ? (k & 0x7FFFFFFFu) : ~k;
    return __uint_as_float(u);
}

// ---------------- packed f32x2 helpers ---------------------------------------
__device__ __forceinline__ ull fma2(ull a, ull b, ull c) {
    ull d;
    asm("fma.rn.f32x2 %0, %1, %2, %3;" : "=l"(d) : "l"(a), "l"(b), "l"(c));
    return d;
}
__device__ __forceinline__ ull mul2(ull a, ull b) {
    ull d;
    asm("mul.rn.f32x2 %0, %1, %2;" : "=l"(d) : "l"(a), "l"(b));
    return d;
}
__device__ __forceinline__ ull pack2(float lo, float hi) {
    ull d;
    asm("mov.b64 %0, {%1, %2};" : "=l"(d) : "f"(lo), "f"(hi));
    return d;
}
__device__ __forceinline__ float2 unpack2(ull v) {
    float lo, hi;
    asm("mov.b64 {%0, %1}, %2;" : "=f"(lo), "=f"(hi) : "l"(v));
    return make_float2(lo, hi);
}

// ---------------- K1: q/k/v projections -------------------------------------
__global__ void qkv_kernel(const float* __restrict__ ftr,
                           const float* __restrict__ wq, const float* __restrict__ bq,
                           const float* __restrict__ wk, const float* __restrict__ bk,
                           const float* __restrict__ wv, const float* __restrict__ bv)
{
    __shared__ float ws[96*64];   // rows: 0-15 wq, 16-31 wk, 32-95 wv
    __shared__ float bs[96];
    int tid = threadIdx.x;
    for (int i = tid; i < 16*64; i += 256) ws[i] = wq[i];
    for (int i = tid; i < 16*64; i += 256) ws[16*64 + i] = wk[i];
    for (int i = tid; i < 64*64; i += 256) ws[32*64 + i] = wv[i];
    if (tid < 16) bs[tid] = bq[tid];
    else if (tid < 32) bs[tid] = bk[tid - 16];
    else if (tid < 96) bs[tid] = bv[tid - 32];
    if (blockIdx.x == 0 && blockIdx.y == 0 && tid < BB*CC) {
        g_sum[tid] = 0.0f;
        g_maxk[tid] = 0u;
    }
    __syncthreads();

    int b = blockIdx.y;
    int p = blockIdx.x * 128 + (tid & 127);
    int half = tid >> 7;
    const float* x = ftr + (size_t)b*CC*PP + p;

    float acc[48];
#pragma unroll
    for (int i = 0; i < 48; i++) acc[i] = 0.0f;

    if (half == 0) {
        for (int c = 0; c < 64; c++) {
            float xc = x[(size_t)c*PP];
#pragma unroll
            for (int i = 0; i < 48; i++) acc[i] += ws[i*64 + c] * xc;
        }
        float* qp = g_q + ((size_t)b*PP + p)*CI;
#pragma unroll
        for (int o = 0; o < 16; o++) qp[o] = acc[o] + bs[o];
#pragma unroll
        for (int o = 0; o < 16; o++) g_k[((size_t)b*CI + o)*PP + p] = acc[16 + o] + bs[16 + o];
#pragma unroll
        for (int c2 = 0; c2 < 16; c2++) g_v[((size_t)b*CC + c2)*PP + p] = acc[32 + c2] + bs[32 + c2];
    } else {
        for (int c = 0; c < 64; c++) {
            float xc = x[(size_t)c*PP];
#pragma unroll
            for (int i = 0; i < 48; i++) acc[i] += ws[(48 + i)*64 + c] * xc;
        }
#pragma unroll
        for (int i = 0; i < 48; i++) g_v[((size_t)b*CC + 16 + i)*PP + p] = acc[i] + bs[48 + i];
    }
}

// ---------------- K2: streaming (flash-style) attention ----------------------
struct Smem2 {
    float q[TP][CI];          // 8 KB   (rows 16B-aligned: 64B each)
    float v[CC][TP];          // 32 KB
    float2 se[TP/2][NCOL];    // 32 KB  packed (e[p],e[p+1]) pairs per column
    float red_m[4][NCOL];     // 1 KB
    float red_l[4][NCOL];     // 1 KB
};

extern __shared__ char smem_raw[];

// grid (PP/NCOL, BB), 256 threads. thread: j = tid&63 (column), g = tid>>6 (channel group of 16)
__global__ void __launch_bounds__(256, 2)
attn_kernel(const float* __restrict__ ftr, const float* __restrict__ delta)
{
    Smem2& sm = *reinterpret_cast<Smem2*>(smem_raw);
    int tid = threadIdx.x;
    int j = tid & 63;
    int g = tid >> 6;
    int b = blockIdx.y;
    int col = blockIdx.x * NCOL + j;

    // k column, pre-packed into 8 f32x2 pairs
    ull kj2[8];
#pragma unroll
    for (int o = 0; o < 8; o++) {
        float klo = g_k[((size_t)b*CI + 2*o    )*PP + col];
        float khi = g_k[((size_t)b*CI + 2*o + 1)*PP + col];
        kj2[o] = pack2(klo, khi);
    }

    ull acc2[16];
#pragma unroll
    for (int i = 0; i < 16; i++) acc2[i] = 0ull;
    float m = -INFINITY, l = 0.0f;

    const float* qbase = g_q + (size_t)b*PP*CI;
    const float* vbase = g_v + (size_t)b*CC*PP;

    for (int t = 0; t < PP/TP; t++) {
        int p0 = t * TP;
        // load q tile (2048 floats) — contiguous
        {
            const float4* qsrc = reinterpret_cast<const float4*>(qbase + (size_t)p0*CI);
            float4* qdst = reinterpret_cast<float4*>(&sm.q[0][0]);
            qdst[tid] = qsrc[tid];
            qdst[tid + 256] = qsrc[tid + 256];
        }
        // load v tile (64 rows x 128 floats)
#pragma unroll
        for (int r = 0; r < 8; r++) {
            int idx = r*256 + tid;      // float4 index, 0..2047
            int row = idx >> 5;
            int cp = idx & 31;
            reinterpret_cast<float4*>(&sm.v[row][0])[cp] =
                reinterpret_cast<const float4*>(vbase + (size_t)row*PP + p0)[cp];
        }
        __syncthreads();

        // ---- phase 1: raw scores for p in [g*32, g*32+32), column j (packed dot) ----
        float lmax = -INFINITY;
#pragma unroll 2
        for (int i = 0; i < 32; i += 2) {
            float sv[2];
#pragma unroll
            for (int u = 0; u < 2; u++) {
                int p = g*32 + i + u;
                const ulonglong2* qrow = reinterpret_cast<const ulonglong2*>(&sm.q[p][0]);
                ulonglong2 qA = qrow[0];
                ulonglong2 qB = qrow[1];
                ull s2 = mul2(qA.x, kj2[0]);
                s2 = fma2(qA.y, kj2[1], s2);
                s2 = fma2(qB.x, kj2[2], s2);
                s2 = fma2(qB.y, kj2[3], s2);
                ulonglong2 qC = qrow[2];
                ulonglong2 qD = qrow[3];
                s2 = fma2(qC.x, kj2[4], s2);
                s2 = fma2(qC.y, kj2[5], s2);
                s2 = fma2(qD.x, kj2[6], s2);
                s2 = fma2(qD.y, kj2[7], s2);
                float2 sp = unpack2(s2);
                sv[u] = sp.x + sp.y;
                lmax = fmaxf(lmax, sv[u]);
            }
            sm.se[(g*32 + i) >> 1][j] = make_float2(sv[0], sv[1]);
        }
        sm.red_m[g][j] = lmax;
        __syncthreads();

        float mt = fmaxf(fmaxf(sm.red_m[0][j], sm.red_m[1][j]),
                         fmaxf(sm.red_m[2][j], sm.red_m[3][j]));
        float mnew = fmaxf(m, mt);
        float scale = __expf(m - mnew);     // first tile: exp(-inf)=0
        ull scale2 = pack2(scale, scale);
#pragma unroll
        for (int i = 0; i < 16; i++) acc2[i] = mul2(acc2[i], scale2);

        // ---- phase 2: exponentiate my 32 scores in place ----
        float lp = 0.0f;
#pragma unroll 4
        for (int i2 = 0; i2 < 16; i2++) {
            int p2 = g*16 + i2;
            float2 sp = sm.se[p2][j];
            float e0 = __expf(sp.x - mnew);
            float e1 = __expf(sp.y - mnew);
            sm.se[p2][j] = make_float2(e0, e1);
            lp += e0 + e1;
        }
        sm.red_l[g][j] = lp;
        __syncthreads();

        l = l*scale + (sm.red_l[0][j] + sm.red_l[1][j] + sm.red_l[2][j] + sm.red_l[3][j]);
        m = mnew;

        // ---- G update (packed): acc2[cc] += v2[p pair] * e2[p pair] ----
        for (int p = 0; p < TP; p += 4) {
            int p2 = p >> 1;
            ull e01 = reinterpret_cast<const ull*>(&sm.se[p2    ][0])[j];
            ull e23 = reinterpret_cast<const ull*>(&sm.se[p2 + 1][0])[j];
#pragma unroll
            for (int cc = 0; cc < 16; cc++) {
                ulonglong2 vv = *reinterpret_cast<const ulonglong2*>(&sm.v[g*16 + cc][p]);
                acc2[cc] = fma2(vv.x, e01, acc2[cc]);
                acc2[cc] = fma2(vv.y, e23, acc2[cc]);
            }
        }
        __syncthreads();
    }

    // epilogue: out = delta * G/l + ftr ; feed SE pooling reductions
    float inv_l = 1.0f / l;
    float dlt = delta[0];
    float outv[16];
    const float* fb = ftr + ((size_t)b*CC + g*16)*PP + col;
#pragma unroll
    for (int cc = 0; cc < 16; cc++) {
        float2 a = unpack2(acc2[cc]);
        float o = dlt * (a.x + a.y) * inv_l + fb[(size_t)cc*PP];
        outv[cc] = o;
        g_out[((size_t)b*CC + g*16 + cc)*PP + col] = o;
    }
    unsigned lane = tid & 31;
#pragma unroll
    for (int cc = 0; cc < 16; cc++) {
        float s = outv[cc];
        float mx = outv[cc];
#pragma unroll
        for (int off = 16; off; off >>= 1) {
            s += __shfl_xor_sync(0xffffffffu, s, off);
            mx = fmaxf(mx, __shfl_xor_sync(0xffffffffu, mx, off));
        }
        if (lane == 0) {
            atomicAdd(&g_sum[b*CC + g*16 + cc], s);
            atomicMax(&g_maxk[b*CC + g*16 + cc], fkey(mx));
        }
    }
}

// ---------------- K3: SE gate -------------------------------------------------
__global__ void gate_kernel(const float* __restrict__ w_avg1, const float* __restrict__ w_avg2,
                            const float* __restrict__ w_max1, const float* __restrict__ w_max2)
{
    __shared__ float h_avg[BB][CI], h_max[BB][CI];
    __shared__ float favg[BB][CC], fmaxv[BB][CC];
    int tid = threadIdx.x;   // 256
    int b = tid >> 6, c = tid & 63;
    favg[b][c] = g_sum[tid] * (1.0f / (float)PP);
    fmaxv[b][c] = funkey(g_maxk[tid]);
    __syncthreads();
    if (tid < 128) {
        int bb = tid >> 5;
        int rest = tid & 31;
        int branch = rest >> 4;
        int o = rest & 15;
        const float* w1 = branch ? w_max1 : w_avg1;
        const float* f = branch ? &fmaxv[bb][0] : &favg[bb][0];
        float h = 0.0f;
        for (int cc2 = 0; cc2 < 64; cc2++) h += w1[o*64 + cc2] * f[cc2];
        h = fmaxf(h, 0.0f);
        if (branch) h_max[bb][o] = h; else h_avg[bb][o] = h;
    }
    __syncthreads();
    float a = 0.0f, mm = 0.0f;
#pragma unroll
    for (int o = 0; o < 16; o++) {
        a  += w_avg2[c*16 + o] * h_avg[b][o];
        mm += w_max2[c*16 + o] * h_max[b][o];
    }
    g_gate[tid] = 1.0f / (1.0f + __expf(-(a + mm)));
}

// ---------------- K4: apply gate ---------------------------------------------
__global__ void final_kernel(float* __restrict__ out)
{
    // 262144 float4s total; 512 blocks x 256 threads x 2 float4 (MLP=2)
    int base = blockIdx.x * 512 + threadIdx.x;
    float4 v0 = reinterpret_cast<const float4*>(g_out)[base];
    float4 v1 = reinterpret_cast<const float4*>(g_out)[base + 256];
    float gv0 = g_gate[base >> 10];
    float gv1 = g_gate[(base + 256) >> 10];
    v0.x *= gv0; v0.y *= gv0; v0.z *= gv0; v0.w *= gv0;
    v1.x *= gv1; v1.y *= gv1; v1.z *= gv1; v1.w *= gv1;
    reinterpret_cast<float4*>(out)[base] = v0;
    reinterpret_cast<float4*>(out)[base + 256] = v1;
}

// ---------------- launch ------------------------------------------------------
extern "C" void kernel_launch(void* const* d_in, const int* in_sizes, int n_in,
                              void* d_out, int out_size)
{
    const float* ftr    = (const float*)d_in[0];
    const float* wq     = (const float*)d_in[1];
    const float* bq     = (const float*)d_in[2];
    const float* wk     = (const float*)d_in[3];
    const float* bk     = (const float*)d_in[4];
    const float* wv     = (const float*)d_in[5];
    const float* bv     = (const float*)d_in[6];
    const float* delta  = (const float*)d_in[7];
    const float* w_avg1 = (const float*)d_in[8];
    const float* w_avg2 = (const float*)d_in[9];
    const float* w_max1 = (const float*)d_in[10];
    const float* w_max2 = (const float*)d_in[11];
    float* out = (float*)d_out;

    cudaFuncSetAttribute(attn_kernel, cudaFuncAttributeMaxDynamicSharedMemorySize,
                         (int)sizeof(Smem2));

    qkv_kernel<<<dim3(PP/128, BB), 256>>>(ftr, wq, bq, wk, bk, wv, bv);
    attn_kernel<<<dim3(PP/NCOL, BB), 256, sizeof(Smem2)>>>(ftr, delta);
    gate_kernel<<<1, 256>>>(w_avg1, w_avg2, w_max1, w_max2);
    final_kernel<<<512, 256>>>(out);
}

// round 4
// speedup vs baseline: 2.4547x; 2.4012x over previous
#include <cuda_runtime.h>
#include <math.h>

#define BB 4
#define CC 64
#define CI 16
#define PP 4096
#define NCOL 64
#define TP 128

// ---------------- scratch (device globals; no allocations allowed) ----------
__device__ float g_q[BB*PP*CI];      // [b][p][o]
__device__ float g_k[BB*CI*PP];      // [b][o][p]
__device__ float g_v[BB*CC*PP];      // [b][c][p]
__device__ float g_out[BB*CC*PP];    // pre-gate output
__device__ float g_sum[BB*CC];       // per (b,c) spatial sum
__device__ float g_fmax[BB*CC];      // per (b,c) spatial max
__device__ float g_gate[BB*CC];

// ---------------- tf32 / mma helpers -----------------------------------------
__device__ __forceinline__ unsigned tf32cvt(float f) {
    unsigned r;
    asm("cvt.rna.tf32.f32 %0, %1;" : "=r"(r) : "f"(f));
    return r;
}
__device__ __forceinline__ void mma8(float c[4],
                                     unsigned a0, unsigned a1, unsigned a2, unsigned a3,
                                     unsigned b0, unsigned b1)
{
    asm volatile(
        "mma.sync.aligned.m16n8k8.row.col.f32.tf32.tf32.f32 "
        "{%0,%1,%2,%3},{%4,%5,%6,%7},{%8,%9},{%0,%1,%2,%3};"
        : "+f"(c[0]), "+f"(c[1]), "+f"(c[2]), "+f"(c[3])
        : "r"(a0), "r"(a1), "r"(a2), "r"(a3), "r"(b0), "r"(b1));
}

// ---------------- K1: q/k/v projections -------------------------------------
__global__ void qkv_kernel(const float* __restrict__ ftr,
                           const float* __restrict__ wq, const float* __restrict__ bq,
                           const float* __restrict__ wk, const float* __restrict__ bk,
                           const float* __restrict__ wv, const float* __restrict__ bv)
{
    __shared__ float ws[96*64];   // rows: 0-15 wq, 16-31 wk, 32-95 wv
    __shared__ float bs[96];
    int tid = threadIdx.x;
    for (int i = tid; i < 16*64; i += 256) ws[i] = wq[i];
    for (int i = tid; i < 16*64; i += 256) ws[16*64 + i] = wk[i];
    for (int i = tid; i < 64*64; i += 256) ws[32*64 + i] = wv[i];
    if (tid < 16) bs[tid] = bq[tid];
    else if (tid < 32) bs[tid] = bk[tid - 16];
    else if (tid < 96) bs[tid] = bv[tid - 32];
    __syncthreads();

    int b = blockIdx.y;
    int p = blockIdx.x * 128 + (tid & 127);
    int half = tid >> 7;
    const float* x = ftr + (size_t)b*CC*PP + p;

    float acc[48];
#pragma unroll
    for (int i = 0; i < 48; i++) acc[i] = 0.0f;

    if (half == 0) {
        for (int c = 0; c < 64; c++) {
            float xc = x[(size_t)c*PP];
#pragma unroll
            for (int i = 0; i < 48; i++) acc[i] += ws[i*64 + c] * xc;
        }
        float* qp = g_q + ((size_t)b*PP + p)*CI;
#pragma unroll
        for (int o = 0; o < 16; o++) qp[o] = acc[o] + bs[o];
#pragma unroll
        for (int o = 0; o < 16; o++) g_k[((size_t)b*CI + o)*PP + p] = acc[16 + o] + bs[16 + o];
#pragma unroll
        for (int c2 = 0; c2 < 16; c2++) g_v[((size_t)b*CC + c2)*PP + p] = acc[32 + c2] + bs[32 + c2];
    } else {
        for (int c = 0; c < 64; c++) {
            float xc = x[(size_t)c*PP];
#pragma unroll
            for (int i = 0; i < 48; i++) acc[i] += ws[(48 + i)*64 + c] * xc;
        }
#pragma unroll
        for (int i = 0; i < 48; i++) g_v[((size_t)b*CC + 16 + i)*PP + p] = acc[i] + bs[48 + i];
    }
}

// ---------------- K2: flash attention on tensor cores (tf32) -----------------
#define QS 20     // Q_s row stride (floats)
#define VS 132    // V_s row stride
#define SS 72     // S_s row stride
#define KS 68     // K_s row stride

struct SmemA {
    unsigned kk[16*KS];       // K tile, tf32           (~4.3 KB)
    unsigned qq[128*QS];      // Q tile, tf32           (10.0 KB)
    float    vv[64*VS];       // V tile, raw fp32       (33.0 KB)
    float    ss[128*SS];      // scores -> E (tf32 bits)(36.0 KB)
    float red_m[4][64];
    float red_l[4][64];
    float scale_s[64];
    float l_s[64];
};

extern __shared__ char smem_raw[];

// grid (PP/NCOL, BB), 256 threads (8 warps)
__global__ void __launch_bounds__(256, 2)
attn_kernel(const float* __restrict__ ftr, const float* __restrict__ delta)
{
    SmemA& sm = *reinterpret_cast<SmemA*>(smem_raw);
    int tid  = threadIdx.x;
    int w    = tid >> 5;
    int lane = tid & 31;
    int r    = lane >> 2;   // fragment row group
    int q4   = lane & 3;    // fragment col group
    int b    = blockIdx.y;
    int col0 = blockIdx.x * NCOL;

    // ---- stage K tile (once), tf32 ----
    for (int i = tid; i < 16*64; i += 256) {
        int o = i >> 6, j = i & 63;
        sm.kk[o*KS + j] = tf32cvt(g_k[((size_t)(b*CI + o))*PP + col0 + j]);
    }
    __syncthreads();

    // ---- resident K B-fragments: kb[n][kstep][reg] ----
    unsigned kb[8][2][2];
#pragma unroll
    for (int n = 0; n < 8; n++)
#pragma unroll
        for (int ks = 0; ks < 2; ks++) {
            kb[n][ks][0] = sm.kk[(ks*8 + q4    )*KS + n*8 + r];
            kb[n][ks][1] = sm.kk[(ks*8 + q4 + 4)*KS + n*8 + r];
        }

    // per-thread softmax state for column j (replicated across g groups)
    int j = tid & 63;
    int g = tid >> 6;
    float m = -INFINITY, l = 0.0f;

    // MMA2 accumulator: warp covers channels [m0,m0+16) x cols [nh*32, nh*32+32)
    int mb = w & 3, nh = w >> 2, m0 = mb*16;
    float cacc[4][4];
#pragma unroll
    for (int i = 0; i < 4; i++)
#pragma unroll
        for (int k2 = 0; k2 < 4; k2++) cacc[i][k2] = 0.0f;

    const float4* qsrc_all = reinterpret_cast<const float4*>(g_q + (size_t)b*PP*CI);
    const float*  vbase    = g_v + (size_t)b*CC*PP;

    for (int t = 0; t < PP/TP; t++) {
        int p0 = t * TP;

        // ---- stage Q tile (tf32) ----
#pragma unroll
        for (int u = 0; u < 2; u++) {
            int fidx = tid + u*256;                    // float4 idx within tile (512 total)
            float4 qv = qsrc_all[p0*4 + fidx];         // p0*16/4 floats4 offset
            int row = fidx >> 2, c4 = (fidx & 3) * 4;
            uint4 qt = { tf32cvt(qv.x), tf32cvt(qv.y), tf32cvt(qv.z), tf32cvt(qv.w) };
            *reinterpret_cast<uint4*>(&sm.qq[row*QS + c4]) = qt;
        }
        // ---- stage V tile (raw fp32, used as tf32 by truncation) ----
#pragma unroll
        for (int rr = 0; rr < 8; rr++) {
            int fidx = rr*256 + tid;                   // 2048 float4s
            int row = fidx >> 5, c4i = fidx & 31;
            *reinterpret_cast<float4*>(&sm.vv[row*VS + c4i*4]) =
                reinterpret_cast<const float4*>(vbase + (size_t)row*PP + p0)[c4i];
        }
        __syncthreads();

        // ---- MMA1: S[128x64], warp w does rows [w*16, w*16+16) ----
        {
            int pb = w * 16;
            unsigned a[2][4];
#pragma unroll
            for (int ks = 0; ks < 2; ks++) {
                int cbase = ks*8 + q4;
                a[ks][0] = sm.qq[(pb + r    )*QS + cbase];
                a[ks][1] = sm.qq[(pb + r + 8)*QS + cbase];
                a[ks][2] = sm.qq[(pb + r    )*QS + cbase + 4];
                a[ks][3] = sm.qq[(pb + r + 8)*QS + cbase + 4];
            }
#pragma unroll
            for (int n = 0; n < 8; n++) {
                float c[4] = {0.f, 0.f, 0.f, 0.f};
                mma8(c, a[0][0], a[0][1], a[0][2], a[0][3], kb[n][0][0], kb[n][0][1]);
                mma8(c, a[1][0], a[1][1], a[1][2], a[1][3], kb[n][1][0], kb[n][1][1]);
                *reinterpret_cast<float2*>(&sm.ss[(pb + r    )*SS + n*8 + q4*2]) = make_float2(c[0], c[1]);
                *reinterpret_cast<float2*>(&sm.ss[(pb + r + 8)*SS + n*8 + q4*2]) = make_float2(c[2], c[3]);
            }
        }
        __syncthreads();

        // ---- softmax (online, over p) ----
        float lmax = -INFINITY;
#pragma unroll
        for (int i = 0; i < 32; i++)
            lmax = fmaxf(lmax, sm.ss[(g*32 + i)*SS + j]);
        sm.red_m[g][j] = lmax;
        __syncthreads();

        float mt = fmaxf(fmaxf(sm.red_m[0][j], sm.red_m[1][j]),
                         fmaxf(sm.red_m[2][j], sm.red_m[3][j]));
        float mnew  = fmaxf(m, mt);
        float scale = __expf(m - mnew);     // first tile: exp(-inf)=0
        if (tid < 64) sm.scale_s[tid] = scale;

        float lp = 0.0f;
#pragma unroll
        for (int i = 0; i < 32; i++) {
            int idx = (g*32 + i)*SS + j;
            float e = __expf(sm.ss[idx] - mnew);
            lp += e;
            sm.ss[idx] = __uint_as_float(tf32cvt(e));
        }
        sm.red_l[g][j] = lp;
        __syncthreads();

        l = l*scale + (sm.red_l[0][j] + sm.red_l[1][j] + sm.red_l[2][j] + sm.red_l[3][j]);
        m = mnew;

        // ---- MMA2: G += V * E ----
#pragma unroll
        for (int nb = 0; nb < 4; nb++) {
            int cb = nh*32 + nb*8 + q4*2;
            float s0 = sm.scale_s[cb], s1 = sm.scale_s[cb + 1];
            cacc[nb][0] *= s0; cacc[nb][1] *= s1;
            cacc[nb][2] *= s0; cacc[nb][3] *= s1;
        }
#pragma unroll 4
        for (int k0 = 0; k0 < 16; k0++) {
            int p = k0 * 8;
            unsigned va0 = __float_as_uint(sm.vv[(m0 + r    )*VS + p + q4]);
            unsigned va1 = __float_as_uint(sm.vv[(m0 + r + 8)*VS + p + q4]);
            unsigned va2 = __float_as_uint(sm.vv[(m0 + r    )*VS + p + q4 + 4]);
            unsigned va3 = __float_as_uint(sm.vv[(m0 + r + 8)*VS + p + q4 + 4]);
#pragma unroll
            for (int nb = 0; nb < 4; nb++) {
                int n0 = nh*32 + nb*8;
                unsigned eb0 = __float_as_uint(sm.ss[(p + q4    )*SS + n0 + r]);
                unsigned eb1 = __float_as_uint(sm.ss[(p + q4 + 4)*SS + n0 + r]);
                mma8(cacc[nb], va0, va1, va2, va3, eb0, eb1);
            }
        }
        __syncthreads();
    }

    // ---- epilogue: out = delta*G/l + ftr ----
    if (tid < 64) sm.l_s[tid] = l;
    __syncthreads();
    float dlt = delta[0];
#pragma unroll
    for (int nb = 0; nb < 4; nb++) {
        int cl = nh*32 + nb*8 + q4*2;
        float inv0 = 1.0f / sm.l_s[cl];
        float inv1 = 1.0f / sm.l_s[cl + 1];
        size_t base0 = ((size_t)b*CC + m0 + r)*PP + col0 + cl;
        float2 f0 = *reinterpret_cast<const float2*>(&ftr[base0]);
        float2 o0 = make_float2(dlt*cacc[nb][0]*inv0 + f0.x,
                                dlt*cacc[nb][1]*inv1 + f0.y);
        *reinterpret_cast<float2*>(&g_out[base0]) = o0;
        size_t base1 = base0 + (size_t)8*PP;
        float2 f1 = *reinterpret_cast<const float2*>(&ftr[base1]);
        float2 o1 = make_float2(dlt*cacc[nb][2]*inv0 + f1.x,
                                dlt*cacc[nb][3]*inv1 + f1.y);
        *reinterpret_cast<float2*>(&g_out[base1]) = o1;
    }
}

// ---------------- K3: SE pooling (sum + max per (b,c)) -----------------------
__global__ void pool_kernel()
{
    int bc = blockIdx.x;                    // 0..255
    const float4* row = reinterpret_cast<const float4*>(g_out + (size_t)bc*PP);
    int tid = threadIdx.x;                  // 128
    float s = 0.0f, mx = -INFINITY;
#pragma unroll
    for (int i = 0; i < 8; i++) {
        float4 v = row[tid + i*128];
        s += (v.x + v.y) + (v.z + v.w);
        mx = fmaxf(mx, fmaxf(fmaxf(v.x, v.y), fmaxf(v.z, v.w)));
    }
#pragma unroll
    for (int off = 16; off; off >>= 1) {
        s  += __shfl_xor_sync(0xffffffffu, s, off);
        mx  = fmaxf(mx, __shfl_xor_sync(0xffffffffu, mx, off));
    }
    __shared__ float ssum[4], smax[4];
    if ((tid & 31) == 0) { ssum[tid >> 5] = s; smax[tid >> 5] = mx; }
    __syncthreads();
    if (tid == 0) {
        g_sum[bc]  = ssum[0] + ssum[1] + ssum[2] + ssum[3];
        g_fmax[bc] = fmaxf(fmaxf(smax[0], smax[1]), fmaxf(smax[2], smax[3]));
    }
}

// ---------------- K4: SE gate -------------------------------------------------
__global__ void gate_kernel(const float* __restrict__ w_avg1, const float* __restrict__ w_avg2,
                            const float* __restrict__ w_max1, const float* __restrict__ w_max2)
{
    __shared__ float h_avg[BB][CI], h_max[BB][CI];
    __shared__ float favg[BB][CC], fmaxv[BB][CC];
    int tid = threadIdx.x;   // 256
    int b = tid >> 6, c = tid & 63;
    favg[b][c]  = g_sum[tid] * (1.0f / (float)PP);
    fmaxv[b][c] = g_fmax[tid];
    __syncthreads();
    if (tid < 128) {
        int bb = tid >> 5;
        int rest = tid & 31;
        int branch = rest >> 4;
        int o = rest & 15;
        const float* w1 = branch ? w_max1 : w_avg1;
        const float* f = branch ? &fmaxv[bb][0] : &favg[bb][0];
        float h = 0.0f;
        for (int cc2 = 0; cc2 < 64; cc2++) h += w1[o*64 + cc2] * f[cc2];
        h = fmaxf(h, 0.0f);
        if (branch) h_max[bb][o] = h; else h_avg[bb][o] = h;
    }
    __syncthreads();
    float a = 0.0f, mm = 0.0f;
#pragma unroll
    for (int o = 0; o < 16; o++) {
        a  += w_avg2[c*16 + o] * h_avg[b][o];
        mm += w_max2[c*16 + o] * h_max[b][o];
    }
    g_gate[tid] = 1.0f / (1.0f + __expf(-(a + mm)));
}

// ---------------- K5: apply gate ---------------------------------------------
__global__ void final_kernel(float* __restrict__ out)
{
    int base = blockIdx.x * 512 + threadIdx.x;
    float4 v0 = reinterpret_cast<const float4*>(g_out)[base];
    float4 v1 = reinterpret_cast<const float4*>(g_out)[base + 256];
    float gv0 = g_gate[base >> 10];
    float gv1 = g_gate[(base + 256) >> 10];
    v0.x *= gv0; v0.y *= gv0; v0.z *= gv0; v0.w *= gv0;
    v1.x *= gv1; v1.y *= gv1; v1.z *= gv1; v1.w *= gv1;
    reinterpret_cast<float4*>(out)[base] = v0;
    reinterpret_cast<float4*>(out)[base + 256] = v1;
}

// ---------------- launch ------------------------------------------------------
extern "C" void kernel_launch(void* const* d_in, const int* in_sizes, int n_in,
                              void* d_out, int out_size)
{
    const float* ftr    = (const float*)d_in[0];
    const float* wq     = (const float*)d_in[1];
    const float* bq     = (const float*)d_in[2];
    const float* wk     = (const float*)d_in[3];
    const float* bk     = (const float*)d_in[4];
    const float* wv     = (const float*)d_in[5];
    const float* bv     = (const float*)d_in[6];
    const float* delta  = (const float*)d_in[7];
    const float* w_avg1 = (const float*)d_in[8];
    const float* w_avg2 = (const float*)d_in[9];
    const float* w_max1 = (const float*)d_in[10];
    const float* w_max2 = (const float*)d_in[11];
    float* out = (float*)d_out;

    cudaFuncSetAttribute(attn_kernel, cudaFuncAttributeMaxDynamicSharedMemorySize,
                         (int)sizeof(SmemA));

    qkv_kernel<<<dim3(PP/128, BB), 256>>>(ftr, wq, bq, wk, bk, wv, bv);
    attn_kernel<<<dim3(PP/NCOL, BB), 256, sizeof(SmemA)>>>(ftr, delta);
    pool_kernel<<<BB*CC, 128>>>();
    gate_kernel<<<1, 256>>>(w_avg1, w_avg2, w_max1, w_max2);
    final_kernel<<<512, 256>>>(out);
}

// round 5
// speedup vs baseline: 2.9086x; 1.1849x over previous
#include <cuda_runtime.h>
#include <math.h>

#define BB 4
#define CC 64
#define CI 16
#define PP 4096
#define NCOL 64
#define TP 128

// ---------------- scratch (device globals; no allocations allowed) ----------
__device__ float g_q[BB*PP*CI];      // [b][p][o]
__device__ float g_k[BB*CI*PP];      // [b][o][p]
__device__ float g_v[BB*CC*PP];      // [b][c][p]
__device__ float g_out[BB*CC*PP];    // pre-gate output
__device__ float g_sum[BB*CC];       // per (b,c) spatial sum
__device__ unsigned g_maxk[BB*CC];   // per (b,c) spatial max (ordered-uint key)

// monotone float<->uint key for atomicMax on floats (any sign)
__device__ __forceinline__ unsigned fkey(float f) {
    unsigned u = __float_as_uint(f);
    return (u & 0x80000000u) ? ~u : (u | 0x80000000u);
}
__device__ __forceinline__ float funkey(unsigned k) {
    unsigned u = (k & 0x80000000u) ? (k & 0x7FFFFFFFu) : ~k;
    return __uint_as_float(u);
}

// ---------------- tf32 / mma helpers -----------------------------------------
__device__ __forceinline__ unsigned tf32cvt(float f) {
    unsigned r;
    asm("cvt.rna.tf32.f32 %0, %1;" : "=r"(r) : "f"(f));
    return r;
}
__device__ __forceinline__ void mma8(float c[4],
                                     unsigned a0, unsigned a1, unsigned a2, unsigned a3,
                                     unsigned b0, unsigned b1)
{
    asm volatile(
        "mma.sync.aligned.m16n8k8.row.col.f32.tf32.tf32.f32 "
        "{%0,%1,%2,%3},{%4,%5,%6,%7},{%8,%9},{%0,%1,%2,%3};"
        : "+f"(c[0]), "+f"(c[1]), "+f"(c[2]), "+f"(c[3])
        : "r"(a0), "r"(a1), "r"(a2), "r"(a3), "r"(b0), "r"(b1));
}

// ---------------- K1: q/k/v projections -------------------------------------
__global__ void qkv_kernel(const float* __restrict__ ftr,
                           const float* __restrict__ wq, const float* __restrict__ bq,
                           const float* __restrict__ wk, const float* __restrict__ bk,
                           const float* __restrict__ wv, const float* __restrict__ bv)
{
    __shared__ float ws[96*64];   // rows: 0-15 wq, 16-31 wk, 32-95 wv
    __shared__ float bs[96];
    int tid = threadIdx.x;
    for (int i = tid; i < 16*64; i += 256) ws[i] = wq[i];
    for (int i = tid; i < 16*64; i += 256) ws[16*64 + i] = wk[i];
    for (int i = tid; i < 64*64; i += 256) ws[32*64 + i] = wv[i];
    if (tid < 16) bs[tid] = bq[tid];
    else if (tid < 32) bs[tid] = bk[tid - 16];
    else if (tid < 96) bs[tid] = bv[tid - 32];
    if (blockIdx.x == 0 && blockIdx.y == 0 && tid < BB*CC) {
        g_sum[tid] = 0.0f;
        g_maxk[tid] = 0u;   // below fkey of any real float
    }
    __syncthreads();

    int b = blockIdx.y;
    int p = blockIdx.x * 128 + (tid & 127);
    int half = tid >> 7;
    const float* x = ftr + (size_t)b*CC*PP + p;

    float acc[48];
#pragma unroll
    for (int i = 0; i < 48; i++) acc[i] = 0.0f;

    if (half == 0) {
        for (int c = 0; c < 64; c++) {
            float xc = x[(size_t)c*PP];
#pragma unroll
            for (int i = 0; i < 48; i++) acc[i] += ws[i*64 + c] * xc;
        }
        float* qp = g_q + ((size_t)b*PP + p)*CI;
#pragma unroll
        for (int o = 0; o < 16; o++) qp[o] = acc[o] + bs[o];
#pragma unroll
        for (int o = 0; o < 16; o++) g_k[((size_t)b*CI + o)*PP + p] = acc[16 + o] + bs[16 + o];
#pragma unroll
        for (int c2 = 0; c2 < 16; c2++) g_v[((size_t)b*CC + c2)*PP + p] = acc[32 + c2] + bs[32 + c2];
    } else {
        for (int c = 0; c < 64; c++) {
            float xc = x[(size_t)c*PP];
#pragma unroll
            for (int i = 0; i < 48; i++) acc[i] += ws[(48 + i)*64 + c] * xc;
        }
#pragma unroll
        for (int i = 0; i < 48; i++) g_v[((size_t)b*CC + 16 + i)*PP + p] = acc[i] + bs[48 + i];
    }
}

// ---------------- K2: flash attention on tensor cores (tf32) -----------------
#define QS 20     // Q_s row stride (floats)
#define VS 132    // V_s row stride
#define SS 72     // S_s row stride
#define KS 68     // K_s row stride

struct SmemA {
    unsigned kk[16*KS];       // K tile, tf32
    unsigned qq[128*QS];      // Q tile, tf32
    float    vv[64*VS];       // V tile, raw fp32 (tf32 by truncation)
    float    ss[128*SS];      // scores -> E (tf32 bits); reused for k-merge
    float red_m[4][64];
    float red_l[4][64];
    float scale_s[64];
    float l_s[64];
    float psum[64][2];
    float pmax[64][2];
};

extern __shared__ char smem_raw[];

// grid (PP/NCOL, BB), 256 threads (8 warps)
__global__ void __launch_bounds__(256, 2)
attn_kernel(const float* __restrict__ ftr, const float* __restrict__ delta)
{
    SmemA& sm = *reinterpret_cast<SmemA*>(smem_raw);
    int tid  = threadIdx.x;
    int w    = tid >> 5;
    int lane = tid & 31;
    int r    = lane >> 2;   // fragment row group
    int q4   = lane & 3;    // fragment col group
    int b    = blockIdx.y;
    int col0 = blockIdx.x * NCOL;

    // k-split warp tiling for MMA2: warp = (k-half, warp-tile)
    int ws_k = w & 1;            // k-half: p in [ws_k*64, ws_k*64+64)
    int wt   = w >> 1;           // 0..3
    int m0   = (wt & 1) * 32;    // channel block
    int n0   = (wt >> 1) * 32;   // column block

    // ---- stage K tile (once), tf32 ----
    for (int i = tid; i < 16*64; i += 256) {
        int o = i >> 6, jj = i & 63;
        sm.kk[o*KS + jj] = tf32cvt(g_k[((size_t)(b*CI + o))*PP + col0 + jj]);
    }
    __syncthreads();

    // ---- resident K B-fragments for MMA1: kb[n][kstep][reg] ----
    unsigned kb[8][2][2];
#pragma unroll
    for (int n = 0; n < 8; n++)
#pragma unroll
        for (int ks = 0; ks < 2; ks++) {
            kb[n][ks][0] = sm.kk[(ks*8 + q4    )*KS + n*8 + r];
            kb[n][ks][1] = sm.kk[(ks*8 + q4 + 4)*KS + n*8 + r];
        }

    // per-thread softmax state for column j (replicated across g groups)
    int j = tid & 63;
    int g = tid >> 6;
    float m = -INFINITY, l = 0.0f;

    // MMA2 accumulator: m32 x n32 x k64 per warp -> [mb2][nb][4]
    float cacc[2][4][4];
#pragma unroll
    for (int a = 0; a < 2; a++)
#pragma unroll
        for (int bq_ = 0; bq_ < 4; bq_++)
#pragma unroll
            for (int k2 = 0; k2 < 4; k2++) cacc[a][bq_][k2] = 0.0f;

    const float4* qsrc_all = reinterpret_cast<const float4*>(g_q + (size_t)b*PP*CI);
    const float*  vbase    = g_v + (size_t)b*CC*PP;

    for (int t = 0; t < PP/TP; t++) {
        int p0 = t * TP;

        // ---- stage Q tile (tf32) ----
#pragma unroll
        for (int u = 0; u < 2; u++) {
            int fidx = tid + u*256;
            float4 qv = qsrc_all[p0*4 + fidx];
            int row = fidx >> 2, c4 = (fidx & 3) * 4;
            uint4 qt = { tf32cvt(qv.x), tf32cvt(qv.y), tf32cvt(qv.z), tf32cvt(qv.w) };
            *reinterpret_cast<uint4*>(&sm.qq[row*QS + c4]) = qt;
        }
        // ---- stage V tile ----
#pragma unroll
        for (int rr = 0; rr < 8; rr++) {
            int fidx = rr*256 + tid;
            int row = fidx >> 5, c4i = fidx & 31;
            *reinterpret_cast<float4*>(&sm.vv[row*VS + c4i*4]) =
                reinterpret_cast<const float4*>(vbase + (size_t)row*PP + p0)[c4i];
        }
        __syncthreads();

        // ---- MMA1: S[128x64], warp w does rows [w*16, w*16+16) ----
        {
            int pb = w * 16;
            unsigned a[2][4];
#pragma unroll
            for (int ks = 0; ks < 2; ks++) {
                int cbase = ks*8 + q4;
                a[ks][0] = sm.qq[(pb + r    )*QS + cbase];
                a[ks][1] = sm.qq[(pb + r + 8)*QS + cbase];
                a[ks][2] = sm.qq[(pb + r    )*QS + cbase + 4];
                a[ks][3] = sm.qq[(pb + r + 8)*QS + cbase + 4];
            }
#pragma unroll
            for (int n = 0; n < 8; n++) {
                float c[4] = {0.f, 0.f, 0.f, 0.f};
                mma8(c, a[0][0], a[0][1], a[0][2], a[0][3], kb[n][0][0], kb[n][0][1]);
                mma8(c, a[1][0], a[1][1], a[1][2], a[1][3], kb[n][1][0], kb[n][1][1]);
                *reinterpret_cast<float2*>(&sm.ss[(pb + r    )*SS + n*8 + q4*2]) = make_float2(c[0], c[1]);
                *reinterpret_cast<float2*>(&sm.ss[(pb + r + 8)*SS + n*8 + q4*2]) = make_float2(c[2], c[3]);
            }
        }
        __syncthreads();

        // ---- softmax (online, over p); cache scores in regs ----
        float sreg[32];
        float lmax = -INFINITY;
#pragma unroll
        for (int i = 0; i < 32; i++) {
            sreg[i] = sm.ss[(g*32 + i)*SS + j];
            lmax = fmaxf(lmax, sreg[i]);
        }
        sm.red_m[g][j] = lmax;
        __syncthreads();

        float mt = fmaxf(fmaxf(sm.red_m[0][j], sm.red_m[1][j]),
                         fmaxf(sm.red_m[2][j], sm.red_m[3][j]));
        float mnew  = fmaxf(m, mt);
        float scale = __expf(m - mnew);     // first tile: exp(-inf)=0
        if (tid < 64) sm.scale_s[tid] = scale;

        float lp = 0.0f;
#pragma unroll
        for (int i = 0; i < 32; i++) {
            float e = __expf(sreg[i] - mnew);
            lp += e;
            sm.ss[(g*32 + i)*SS + j] = __uint_as_float(tf32cvt(e));
        }
        sm.red_l[g][j] = lp;
        __syncthreads();

        l = l*scale + (sm.red_l[0][j] + sm.red_l[1][j] + sm.red_l[2][j] + sm.red_l[3][j]);
        m = mnew;

        // ---- MMA2 (k-split): G[m32,n32] += V[m32,k64] * E[k64,n32] ----
#pragma unroll
        for (int mb2 = 0; mb2 < 2; mb2++)
#pragma unroll
            for (int nb = 0; nb < 4; nb++) {
                int cb = n0 + nb*8 + q4*2;
                float s0 = sm.scale_s[cb], s1 = sm.scale_s[cb + 1];
                cacc[mb2][nb][0] *= s0; cacc[mb2][nb][1] *= s1;
                cacc[mb2][nb][2] *= s0; cacc[mb2][nb][3] *= s1;
            }
#pragma unroll 2
        for (int k0 = 0; k0 < 8; k0++) {
            int p = ws_k*64 + k0*8;
            unsigned va[2][4];
#pragma unroll
            for (int mb2 = 0; mb2 < 2; mb2++) {
                int row = m0 + mb2*16;
                va[mb2][0] = __float_as_uint(sm.vv[(row + r    )*VS + p + q4]);
                va[mb2][1] = __float_as_uint(sm.vv[(row + r + 8)*VS + p + q4]);
                va[mb2][2] = __float_as_uint(sm.vv[(row + r    )*VS + p + q4 + 4]);
                va[mb2][3] = __float_as_uint(sm.vv[(row + r + 8)*VS + p + q4 + 4]);
            }
#pragma unroll
            for (int nb = 0; nb < 4; nb++) {
                int nn = n0 + nb*8;
                unsigned eb0 = __float_as_uint(sm.ss[(p + q4    )*SS + nn + r]);
                unsigned eb1 = __float_as_uint(sm.ss[(p + q4 + 4)*SS + nn + r]);
                mma8(cacc[0][nb], va[0][0], va[0][1], va[0][2], va[0][3], eb0, eb1);
                mma8(cacc[1][nb], va[1][0], va[1][1], va[1][2], va[1][3], eb0, eb1);
            }
        }
        __syncthreads();
    }

    // ---- publish l, merge k-split halves ----
    if (tid < 64) sm.l_s[tid] = l;
    if (ws_k == 1) {
        float* mg = &sm.ss[wt * 1024];
#pragma unroll
        for (int mb2 = 0; mb2 < 2; mb2++)
#pragma unroll
            for (int nb = 0; nb < 4; nb++)
#pragma unroll
                for (int k2 = 0; k2 < 4; k2++)
                    mg[(mb2*16 + nb*4 + k2)*32 + lane] = cacc[mb2][nb][k2];
    }
    __syncthreads();

    if (ws_k == 0) {
        const float* mg = &sm.ss[wt * 1024];
#pragma unroll
        for (int mb2 = 0; mb2 < 2; mb2++)
#pragma unroll
            for (int nb = 0; nb < 4; nb++)
#pragma unroll
                for (int k2 = 0; k2 < 4; k2++)
                    cacc[mb2][nb][k2] += mg[(mb2*16 + nb*4 + k2)*32 + lane];

        // ---- epilogue: out = delta*G/l + ftr, plus per-row pooling partials ----
        float dlt = delta[0];
        float psum_[2][2], pmax_[2][2];
#pragma unroll
        for (int mb2 = 0; mb2 < 2; mb2++)
#pragma unroll
            for (int hh = 0; hh < 2; hh++) { psum_[mb2][hh] = 0.0f; pmax_[mb2][hh] = -INFINITY; }

#pragma unroll
        for (int mb2 = 0; mb2 < 2; mb2++)
#pragma unroll
            for (int nb = 0; nb < 4; nb++) {
                int cl = n0 + nb*8 + q4*2;
                float inv0 = 1.0f / sm.l_s[cl];
                float inv1 = 1.0f / sm.l_s[cl + 1];
                int row = m0 + mb2*16 + r;
                size_t base0 = ((size_t)b*CC + row)*PP + col0 + cl;
                float2 f0 = *reinterpret_cast<const float2*>(&ftr[base0]);
                float2 o0 = make_float2(dlt*cacc[mb2][nb][0]*inv0 + f0.x,
                                        dlt*cacc[mb2][nb][1]*inv1 + f0.y);
                *reinterpret_cast<float2*>(&g_out[base0]) = o0;
                psum_[mb2][0] += o0.x + o0.y;
                pmax_[mb2][0] = fmaxf(pmax_[mb2][0], fmaxf(o0.x, o0.y));

                size_t base1 = base0 + (size_t)8*PP;
                float2 f1 = *reinterpret_cast<const float2*>(&ftr[base1]);
                float2 o1 = make_float2(dlt*cacc[mb2][nb][2]*inv0 + f1.x,
                                        dlt*cacc[mb2][nb][3]*inv1 + f1.y);
                *reinterpret_cast<float2*>(&g_out[base1]) = o1;
                psum_[mb2][1] += o1.x + o1.y;
                pmax_[mb2][1] = fmaxf(pmax_[mb2][1], fmaxf(o1.x, o1.y));
            }

        // reduce over q4 lanes (xor 1, 2)
#pragma unroll
        for (int mb2 = 0; mb2 < 2; mb2++)
#pragma unroll
            for (int hh = 0; hh < 2; hh++) {
#pragma unroll
                for (int off = 1; off <= 2; off <<= 1) {
                    psum_[mb2][hh] += __shfl_xor_sync(0xffffffffu, psum_[mb2][hh], off);
                    pmax_[mb2][hh] = fmaxf(pmax_[mb2][hh],
                                           __shfl_xor_sync(0xffffffffu, pmax_[mb2][hh], off));
                }
                if (q4 == 0) {
                    int row = m0 + mb2*16 + r + hh*8;
                    int nhalf = wt >> 1;
                    sm.psum[row][nhalf] = psum_[mb2][hh];
                    sm.pmax[row][nhalf] = pmax_[mb2][hh];
                }
            }
    }
    __syncthreads();

    if (tid < 64) {
        float s  = sm.psum[tid][0] + sm.psum[tid][1];
        float mx = fmaxf(sm.pmax[tid][0], sm.pmax[tid][1]);
        atomicAdd(&g_sum[b*CC + tid], s);
        atomicMax(&g_maxk[b*CC + tid], fkey(mx));
    }
}

// ---------------- K3: apply gate (gate computed per-block, redundantly) ------
__global__ void final_kernel(float* __restrict__ out,
                             const float* __restrict__ w_avg1, const float* __restrict__ w_avg2,
                             const float* __restrict__ w_max1, const float* __restrict__ w_max2)
{
    __shared__ float hh[32];
    __shared__ float gate_s;
    int t = threadIdx.x;
    int blk = blockIdx.x;          // 0..511; block = half a channel (2048 floats)
    int b = blk >> 7;
    int c = (blk >> 1) & 63;

    // hidden layer: 32 dots of length 64, 8 threads each
    {
        int d = t >> 3, part = t & 7;
        int branch = d >> 4, o = d & 15;
        const float* w1 = branch ? w_max1 : w_avg1;
        float acc = 0.0f;
#pragma unroll
        for (int i = 0; i < 8; i++) {
            int idx = part*8 + i;
            float f = branch ? funkey(g_maxk[b*CC + idx])
                             : g_sum[b*CC + idx] * (1.0f/(float)PP);
            acc += w1[o*64 + idx] * f;
        }
#pragma unroll
        for (int off = 1; off <= 4; off <<= 1)
            acc += __shfl_xor_sync(0xffffffffu, acc, off);
        if (part == 0) hh[d] = fmaxf(acc, 0.0f);
    }
    __syncthreads();
    if (t == 0) {
        float a = 0.0f, mm = 0.0f;
#pragma unroll
        for (int o = 0; o < 16; o++) {
            a  += w_avg2[c*16 + o] * hh[o];
            mm += w_max2[c*16 + o] * hh[16 + o];
        }
        gate_s = 1.0f / (1.0f + __expf(-(a + mm)));
    }
    __syncthreads();

    float gv = gate_s;
    int base = blk * 512 + t;      // float4 units
    float4 v0 = reinterpret_cast<const float4*>(g_out)[base];
    float4 v1 = reinterpret_cast<const float4*>(g_out)[base + 256];
    v0.x *= gv; v0.y *= gv; v0.z *= gv; v0.w *= gv;
    v1.x *= gv; v1.y *= gv; v1.z *= gv; v1.w *= gv;
    reinterpret_cast<float4*>(out)[base] = v0;
    reinterpret_cast<float4*>(out)[base + 256] = v1;
}

// ---------------- launch ------------------------------------------------------
extern "C" void kernel_launch(void* const* d_in, const int* in_sizes, int n_in,
                              void* d_out, int out_size)
{
    const float* ftr    = (const float*)d_in[0];
    const float* wq     = (const float*)d_in[1];
    const float* bq     = (const float*)d_in[2];
    const float* wk     = (const float*)d_in[3];
    const float* bk     = (const float*)d_in[4];
    const float* wv     = (const float*)d_in[5];
    const float* bv     = (const float*)d_in[6];
    const float* delta  = (const float*)d_in[7];
    const float* w_avg1 = (const float*)d_in[8];
    const float* w_avg2 = (const float*)d_in[9];
    const float* w_max1 = (const float*)d_in[10];
    const float* w_max2 = (const float*)d_in[11];
    float* out = (float*)d_out;

    cudaFuncSetAttribute(attn_kernel, cudaFuncAttributeMaxDynamicSharedMemorySize,
                         (int)sizeof(SmemA));

    qkv_kernel<<<dim3(PP/128, BB), 256>>>(ftr, wq, bq, wk, bk, wv, bv);
    attn_kernel<<<dim3(PP/NCOL, BB), 256, sizeof(SmemA)>>>(ftr, delta);
    final_kernel<<<512, 256>>>(out, w_avg1, w_avg2, w_max1, w_max2);
}

// round 6
// speedup vs baseline: 2.9442x; 1.0122x over previous
#include <cuda_runtime.h>
#include <math.h>

#define BB 4
#define CC 64
#define CI 16
#define PP 4096
#define NCOL 64
#define TP 128

// ---------------- scratch (device globals; no allocations allowed) ----------
__device__ float g_q[BB*PP*CI];      // [b][p][o]
__device__ float g_k[BB*CI*PP];      // [b][o][p]
__device__ float g_v[BB*CC*PP];      // [b][c][p]
__device__ float g_out[BB*CC*PP];    // pre-gate output
__device__ float g_sum[BB*CC];       // per (b,c) spatial sum
__device__ unsigned g_maxk[BB*CC];   // per (b,c) spatial max (ordered-uint key)

// monotone float<->uint key for atomicMax on floats (any sign)
__device__ __forceinline__ unsigned fkey(float f) {
    unsigned u = __float_as_uint(f);
    return (u & 0x80000000u) ? ~u : (u | 0x80000000u);
}
__device__ __forceinline__ float funkey(unsigned k) {
    unsigned u = (k & 0x80000000u) ? (k & 0x7FFFFFFFu) : ~k;
    return __uint_as_float(u);
}

// ---------------- tf32 / mma helpers -----------------------------------------
__device__ __forceinline__ unsigned tf32cvt(float f) {
    unsigned r;
    asm("cvt.rna.tf32.f32 %0, %1;" : "=r"(r) : "f"(f));
    return r;
}
__device__ __forceinline__ void mma8(float c[4],
                                     unsigned a0, unsigned a1, unsigned a2, unsigned a3,
                                     unsigned b0, unsigned b1)
{
    asm volatile(
        "mma.sync.aligned.m16n8k8.row.col.f32.tf32.tf32.f32 "
        "{%0,%1,%2,%3},{%4,%5,%6,%7},{%8,%9},{%0,%1,%2,%3};"
        : "+f"(c[0]), "+f"(c[1]), "+f"(c[2]), "+f"(c[3])
        : "r"(a0), "r"(a1), "r"(a2), "r"(a3), "r"(b0), "r"(b1));
}

// ---------------- K1: q/k/v projections (tiled smem GEMM) --------------------
// grid (PP/32, BB), 256 threads: p-lane = tid&31, output-group = tid>>5 (12 outs each)
__global__ void __launch_bounds__(256)
qkv_kernel(const float* __restrict__ ftr,
           const float* __restrict__ wq, const float* __restrict__ bq,
           const float* __restrict__ wk, const float* __restrict__ bk,
           const float* __restrict__ wv, const float* __restrict__ bv)
{
    __shared__ float wt[64][96];   // transposed weights: [c][o]  (o: 0-15 q, 16-31 k, 32-95 v)
    __shared__ float bs[96];
    __shared__ float xs[64][32];   // x tile [c][p_local]

    int tid = threadIdx.x;
    for (int i = tid; i < 16*64; i += 256) { int o = i >> 6, c = i & 63; wt[c][o]      = wq[i]; }
    for (int i = tid; i < 16*64; i += 256) { int o = i >> 6, c = i & 63; wt[c][16 + o] = wk[i]; }
    for (int i = tid; i < 64*64; i += 256) { int o = i >> 6, c = i & 63; wt[c][32 + o] = wv[i]; }
    if (tid < 16) bs[tid] = bq[tid];
    else if (tid < 32) bs[tid] = bk[tid - 16];
    else if (tid < 96) bs[tid] = bv[tid - 32];
    if (blockIdx.x == 0 && blockIdx.y == 0 && tid < BB*CC) {
        g_sum[tid] = 0.0f;
        g_maxk[tid] = 0u;   // below fkey of any real float
    }

    int b  = blockIdx.y;
    int p0 = blockIdx.x * 32;
    // stage x tile: 64 rows x 32 floats = 512 float4s, 2 per thread
#pragma unroll
    for (int u = 0; u < 2; u++) {
        int f = tid + u*256;
        int c = f >> 3, s = f & 7;
        *reinterpret_cast<float4*>(&xs[c][s*4]) =
            *reinterpret_cast<const float4*>(ftr + ((size_t)b*CC + c)*PP + p0 + s*4);
    }
    __syncthreads();

    int pl  = tid & 31;
    int grp = tid >> 5;
    float acc[12];
#pragma unroll
    for (int i = 0; i < 12; i++) acc[i] = 0.0f;

#pragma unroll 8
    for (int c = 0; c < 64; c++) {
        float xv = xs[c][pl];
        float4 w0 = *reinterpret_cast<const float4*>(&wt[c][grp*12]);
        float4 w1 = *reinterpret_cast<const float4*>(&wt[c][grp*12 + 4]);
        float4 w2 = *reinterpret_cast<const float4*>(&wt[c][grp*12 + 8]);
        acc[0]  = fmaf(w0.x, xv, acc[0]);
        acc[1]  = fmaf(w0.y, xv, acc[1]);
        acc[2]  = fmaf(w0.z, xv, acc[2]);
        acc[3]  = fmaf(w0.w, xv, acc[3]);
        acc[4]  = fmaf(w1.x, xv, acc[4]);
        acc[5]  = fmaf(w1.y, xv, acc[5]);
        acc[6]  = fmaf(w1.z, xv, acc[6]);
        acc[7]  = fmaf(w1.w, xv, acc[7]);
        acc[8]  = fmaf(w2.x, xv, acc[8]);
        acc[9]  = fmaf(w2.y, xv, acc[9]);
        acc[10] = fmaf(w2.z, xv, acc[10]);
        acc[11] = fmaf(w2.w, xv, acc[11]);
    }

    int p = p0 + pl;
#pragma unroll
    for (int o = 0; o < 12; o++) {
        int go = grp*12 + o;
        float val = acc[o] + bs[go];
        if (go < 16)
            g_q[(((size_t)b*PP + p) << 4) + go] = val;
        else if (go < 32)
            g_k[((size_t)b*CI + (go - 16))*PP + p] = val;
        else
            g_v[((size_t)b*CC + (go - 32))*PP + p] = val;
    }
}

// ---------------- K2: flash attention on tensor cores (tf32) -----------------
#define QS 20     // Q_s row stride (floats)
#define VS 132    // V_s row stride
#define SS 72     // S_s row stride
#define KS 68     // K_s row stride

struct SmemA {
    unsigned kk[16*KS];       // K tile, tf32
    unsigned qq[128*QS];      // Q tile, tf32
    float    vv[64*VS];       // V tile, raw fp32 (tf32 by truncation)
    float    ss[128*SS];      // scores -> E (tf32 bits); reused for k-merge
    float red_m[4][64];
    float red_l[4][64];
    float scale_s[64];
    float l_s[64];
    float psum[64][2];
    float pmax[64][2];
};

extern __shared__ char smem_raw[];

// grid (PP/NCOL, BB), 256 threads (8 warps)
__global__ void __launch_bounds__(256, 2)
attn_kernel(const float* __restrict__ ftr, const float* __restrict__ delta)
{
    SmemA& sm = *reinterpret_cast<SmemA*>(smem_raw);
    int tid  = threadIdx.x;
    int w    = tid >> 5;
    int lane = tid & 31;
    int r    = lane >> 2;   // fragment row group
    int q4   = lane & 3;    // fragment col group
    int b    = blockIdx.y;
    int col0 = blockIdx.x * NCOL;

    // k-split warp tiling for MMA2: warp = (k-half, warp-tile)
    int ws_k = w & 1;            // k-half: p in [ws_k*64, ws_k*64+64)
    int wt   = w >> 1;           // 0..3
    int m0   = (wt & 1) * 32;    // channel block
    int n0   = (wt >> 1) * 32;   // column block

    // ---- stage K tile (once), tf32 ----
    for (int i = tid; i < 16*64; i += 256) {
        int o = i >> 6, jj = i & 63;
        sm.kk[o*KS + jj] = tf32cvt(g_k[((size_t)(b*CI + o))*PP + col0 + jj]);
    }
    __syncthreads();

    // ---- resident K B-fragments for MMA1: kb[n][kstep][reg] ----
    unsigned kb[8][2][2];
#pragma unroll
    for (int n = 0; n < 8; n++)
#pragma unroll
        for (int ks = 0; ks < 2; ks++) {
            kb[n][ks][0] = sm.kk[(ks*8 + q4    )*KS + n*8 + r];
            kb[n][ks][1] = sm.kk[(ks*8 + q4 + 4)*KS + n*8 + r];
        }

    // per-thread softmax state for column j (replicated across g groups)
    int j = tid & 63;
    int g = tid >> 6;
    float m = -INFINITY, l = 0.0f;

    // MMA2 accumulator: m32 x n32 x k64 per warp -> [mb2][nb][4]
    float cacc[2][4][4];
#pragma unroll
    for (int a = 0; a < 2; a++)
#pragma unroll
        for (int bq_ = 0; bq_ < 4; bq_++)
#pragma unroll
            for (int k2 = 0; k2 < 4; k2++) cacc[a][bq_][k2] = 0.0f;

    const float4* qsrc_all = reinterpret_cast<const float4*>(g_q + (size_t)b*PP*CI);
    const float*  vbase    = g_v + (size_t)b*CC*PP;

    for (int t = 0; t < PP/TP; t++) {
        int p0 = t * TP;

        // ---- stage Q tile (tf32) ----
#pragma unroll
        for (int u = 0; u < 2; u++) {
            int fidx = tid + u*256;
            float4 qv = qsrc_all[p0*4 + fidx];
            int row = fidx >> 2, c4 = (fidx & 3) * 4;
            uint4 qt = { tf32cvt(qv.x), tf32cvt(qv.y), tf32cvt(qv.z), tf32cvt(qv.w) };
            *reinterpret_cast<uint4*>(&sm.qq[row*QS + c4]) = qt;
        }
        // ---- stage V tile ----
#pragma unroll
        for (int rr = 0; rr < 8; rr++) {
            int fidx = rr*256 + tid;
            int row = fidx >> 5, c4i = fidx & 31;
            *reinterpret_cast<float4*>(&sm.vv[row*VS + c4i*4]) =
                reinterpret_cast<const float4*>(vbase + (size_t)row*PP + p0)[c4i];
        }
        __syncthreads();

        // ---- MMA1: S[128x64], warp w does rows [w*16, w*16+16) ----
        {
            int pb = w * 16;
            unsigned a[2][4];
#pragma unroll
            for (int ks = 0; ks < 2; ks++) {
                int cbase = ks*8 + q4;
                a[ks][0] = sm.qq[(pb + r    )*QS + cbase];
                a[ks][1] = sm.qq[(pb + r + 8)*QS + cbase];
                a[ks][2] = sm.qq[(pb + r    )*QS + cbase + 4];
                a[ks][3] = sm.qq[(pb + r + 8)*QS + cbase + 4];
            }
#pragma unroll
            for (int n = 0; n < 8; n++) {
                float c[4] = {0.f, 0.f, 0.f, 0.f};
                mma8(c, a[0][0], a[0][1], a[0][2], a[0][3], kb[n][0][0], kb[n][0][1]);
                mma8(c, a[1][0], a[1][1], a[1][2], a[1][3], kb[n][1][0], kb[n][1][1]);
                *reinterpret_cast<float2*>(&sm.ss[(pb + r    )*SS + n*8 + q4*2]) = make_float2(c[0], c[1]);
                *reinterpret_cast<float2*>(&sm.ss[(pb + r + 8)*SS + n*8 + q4*2]) = make_float2(c[2], c[3]);
            }
        }
        __syncthreads();

        // ---- softmax (online, over p); cache scores in regs ----
        float sreg[32];
        float lmax = -INFINITY;
#pragma unroll
        for (int i = 0; i < 32; i++) {
            sreg[i] = sm.ss[(g*32 + i)*SS + j];
            lmax = fmaxf(lmax, sreg[i]);
        }
        sm.red_m[g][j] = lmax;
        __syncthreads();

        float mt = fmaxf(fmaxf(sm.red_m[0][j], sm.red_m[1][j]),
                         fmaxf(sm.red_m[2][j], sm.red_m[3][j]));
        float mnew  = fmaxf(m, mt);
        float scale = __expf(m - mnew);     // first tile: exp(-inf)=0
        if (tid < 64) sm.scale_s[tid] = scale;

        float lp = 0.0f;
#pragma unroll
        for (int i = 0; i < 32; i++) {
            float e = __expf(sreg[i] - mnew);
            lp += e;
            sm.ss[(g*32 + i)*SS + j] = __uint_as_float(tf32cvt(e));
        }
        sm.red_l[g][j] = lp;
        __syncthreads();

        l = l*scale + (sm.red_l[0][j] + sm.red_l[1][j] + sm.red_l[2][j] + sm.red_l[3][j]);
        m = mnew;

        // ---- MMA2 (k-split): G[m32,n32] += V[m32,k64] * E[k64,n32] ----
#pragma unroll
        for (int mb2 = 0; mb2 < 2; mb2++)
#pragma unroll
            for (int nb = 0; nb < 4; nb++) {
                int cb = n0 + nb*8 + q4*2;
                float s0 = sm.scale_s[cb], s1 = sm.scale_s[cb + 1];
                cacc[mb2][nb][0] *= s0; cacc[mb2][nb][1] *= s1;
                cacc[mb2][nb][2] *= s0; cacc[mb2][nb][3] *= s1;
            }
#pragma unroll 2
        for (int k0 = 0; k0 < 8; k0++) {
            int p = ws_k*64 + k0*8;
            unsigned va[2][4];
#pragma unroll
            for (int mb2 = 0; mb2 < 2; mb2++) {
                int row = m0 + mb2*16;
                va[mb2][0] = __float_as_uint(sm.vv[(row + r    )*VS + p + q4]);
                va[mb2][1] = __float_as_uint(sm.vv[(row + r + 8)*VS + p + q4]);
                va[mb2][2] = __float_as_uint(sm.vv[(row + r    )*VS + p + q4 + 4]);
                va[mb2][3] = __float_as_uint(sm.vv[(row + r + 8)*VS + p + q4 + 4]);
            }
#pragma unroll
            for (int nb = 0; nb < 4; nb++) {
                int nn = n0 + nb*8;
                unsigned eb0 = __float_as_uint(sm.ss[(p + q4    )*SS + nn + r]);
                unsigned eb1 = __float_as_uint(sm.ss[(p + q4 + 4)*SS + nn + r]);
                mma8(cacc[0][nb], va[0][0], va[0][1], va[0][2], va[0][3], eb0, eb1);
                mma8(cacc[1][nb], va[1][0], va[1][1], va[1][2], va[1][3], eb0, eb1);
            }
        }
        __syncthreads();
    }

    // ---- publish l, merge k-split halves ----
    if (tid < 64) sm.l_s[tid] = l;
    if (ws_k == 1) {
        float* mg = &sm.ss[wt * 1024];
#pragma unroll
        for (int mb2 = 0; mb2 < 2; mb2++)
#pragma unroll
            for (int nb = 0; nb < 4; nb++)
#pragma unroll
                for (int k2 = 0; k2 < 4; k2++)
                    mg[(mb2*16 + nb*4 + k2)*32 + lane] = cacc[mb2][nb][k2];
    }
    __syncthreads();

    if (ws_k == 0) {
        const float* mg = &sm.ss[wt * 1024];
#pragma unroll
        for (int mb2 = 0; mb2 < 2; mb2++)
#pragma unroll
            for (int nb = 0; nb < 4; nb++)
#pragma unroll
                for (int k2 = 0; k2 < 4; k2++)
                    cacc[mb2][nb][k2] += mg[(mb2*16 + nb*4 + k2)*32 + lane];

        // ---- epilogue: out = delta*G/l + ftr, plus per-row pooling partials ----
        float dlt = delta[0];
        float psum_[2][2], pmax_[2][2];
#pragma unroll
        for (int mb2 = 0; mb2 < 2; mb2++)
#pragma unroll
            for (int hh = 0; hh < 2; hh++) { psum_[mb2][hh] = 0.0f; pmax_[mb2][hh] = -INFINITY; }

#pragma unroll
        for (int mb2 = 0; mb2 < 2; mb2++)
#pragma unroll
            for (int nb = 0; nb < 4; nb++) {
                int cl = n0 + nb*8 + q4*2;
                float inv0 = 1.0f / sm.l_s[cl];
                float inv1 = 1.0f / sm.l_s[cl + 1];
                int row = m0 + mb2*16 + r;
                size_t base0 = ((size_t)b*CC + row)*PP + col0 + cl;
                float2 f0 = *reinterpret_cast<const float2*>(&ftr[base0]);
                float2 o0 = make_float2(dlt*cacc[mb2][nb][0]*inv0 + f0.x,
                                        dlt*cacc[mb2][nb][1]*inv1 + f0.y);
                *reinterpret_cast<float2*>(&g_out[base0]) = o0;
                psum_[mb2][0] += o0.x + o0.y;
                pmax_[mb2][0] = fmaxf(pmax_[mb2][0], fmaxf(o0.x, o0.y));

                size_t base1 = base0 + (size_t)8*PP;
                float2 f1 = *reinterpret_cast<const float2*>(&ftr[base1]);
                float2 o1 = make_float2(dlt*cacc[mb2][nb][2]*inv0 + f1.x,
                                        dlt*cacc[mb2][nb][3]*inv1 + f1.y);
                *reinterpret_cast<float2*>(&g_out[base1]) = o1;
                psum_[mb2][1] += o1.x + o1.y;
                pmax_[mb2][1] = fmaxf(pmax_[mb2][1], fmaxf(o1.x, o1.y));
            }

        // reduce over q4 lanes (xor 1, 2)
#pragma unroll
        for (int mb2 = 0; mb2 < 2; mb2++)
#pragma unroll
            for (int hh = 0; hh < 2; hh++) {
#pragma unroll
                for (int off = 1; off <= 2; off <<= 1) {
                    psum_[mb2][hh] += __shfl_xor_sync(0xffffffffu, psum_[mb2][hh], off);
                    pmax_[mb2][hh] = fmaxf(pmax_[mb2][hh],
                                           __shfl_xor_sync(0xffffffffu, pmax_[mb2][hh], off));
                }
                if (q4 == 0) {
                    int row = m0 + mb2*16 + r + hh*8;
                    int nhalf = wt >> 1;
                    sm.psum[row][nhalf] = psum_[mb2][hh];
                    sm.pmax[row][nhalf] = pmax_[mb2][hh];
                }
            }
    }
    __syncthreads();

    if (tid < 64) {
        float s  = sm.psum[tid][0] + sm.psum[tid][1];
        float mx = fmaxf(sm.pmax[tid][0], sm.pmax[tid][1]);
        atomicAdd(&g_sum[b*CC + tid], s);
        atomicMax(&g_maxk[b*CC + tid], fkey(mx));
    }
}

// ---------------- K3: apply gate (gate computed per-block, redundantly) ------
__global__ void final_kernel(float* __restrict__ out,
                             const float* __restrict__ w_avg1, const float* __restrict__ w_avg2,
                             const float* __restrict__ w_max1, const float* __restrict__ w_max2)
{
    __shared__ float hh[32];
    __shared__ float gate_s;
    int t = threadIdx.x;
    int blk = blockIdx.x;          // 0..511; block = half a channel (2048 floats)
    int b = blk >> 7;
    int c = (blk >> 1) & 63;

    // hidden layer: 32 dots of length 64, 8 threads each
    {
        int d = t >> 3, part = t & 7;
        int branch = d >> 4, o = d & 15;
        const float* w1 = branch ? w_max1 : w_avg1;
        float acc = 0.0f;
#pragma unroll
        for (int i = 0; i < 8; i++) {
            int idx = part*8 + i;
            float f = branch ? funkey(g_maxk[b*CC + idx])
                             : g_sum[b*CC + idx] * (1.0f/(float)PP);
            acc += w1[o*64 + idx] * f;
        }
#pragma unroll
        for (int off = 1; off <= 4; off <<= 1)
            acc += __shfl_xor_sync(0xffffffffu, acc, off);
        if (part == 0) hh[d] = fmaxf(acc, 0.0f);
    }
    __syncthreads();
    if (t == 0) {
        float a = 0.0f, mm = 0.0f;
#pragma unroll
        for (int o = 0; o < 16; o++) {
            a  += w_avg2[c*16 + o] * hh[o];
            mm += w_max2[c*16 + o] * hh[16 + o];
        }
        gate_s = 1.0f / (1.0f + __expf(-(a + mm)));
    }
    __syncthreads();

    float gv = gate_s;
    int base = blk * 512 + t;      // float4 units
    float4 v0 = reinterpret_cast<const float4*>(g_out)[base];
    float4 v1 = reinterpret_cast<const float4*>(g_out)[base + 256];
    v0.x *= gv; v0.y *= gv; v0.z *= gv; v0.w *= gv;
    v1.x *= gv; v1.y *= gv; v1.z *= gv; v1.w *= gv;
    reinterpret_cast<float4*>(out)[base] = v0;
    reinterpret_cast<float4*>(out)[base + 256] = v1;
}

// ---------------- launch ------------------------------------------------------
extern "C" void kernel_launch(void* const* d_in, const int* in_sizes, int n_in,
                              void* d_out, int out_size)
{
    const float* ftr    = (const float*)d_in[0];
    const float* wq     = (const float*)d_in[1];
    const float* bq     = (const float*)d_in[2];
    const float* wk     = (const float*)d_in[3];
    const float* bk     = (const float*)d_in[4];
    const float* wv     = (const float*)d_in[5];
    const float* bv     = (const float*)d_in[6];
    const float* delta  = (const float*)d_in[7];
    const float* w_avg1 = (const float*)d_in[8];
    const float* w_avg2 = (const float*)d_in[9];
    const float* w_max1 = (const float*)d_in[10];
    const float* w_max2 = (const float*)d_in[11];
    float* out = (float*)d_out;

    cudaFuncSetAttribute(attn_kernel, cudaFuncAttributeMaxDynamicSharedMemorySize,
                         (int)sizeof(SmemA));

    qkv_kernel<<<dim3(PP/32, BB), 256>>>(ftr, wq, bq, wk, bk, wv, bv);
    attn_kernel<<<dim3(PP/NCOL, BB), 256, sizeof(SmemA)>>>(ftr, delta);
    final_kernel<<<512, 256>>>(out, w_avg1, w_avg2, w_max1, w_max2);
}

// round 7
// speedup vs baseline: 2.9605x; 1.0056x over previous
#include <cuda_runtime.h>
#include <math.h>

#define BB 4
#define CC 64
#define CI 16
#define PP 4096
#define NCOL 64
#define TP 128

// ---------------- scratch (device globals; no allocations allowed) ----------
__device__ float g_q[BB*PP*CI];      // [b][p][o]
__device__ float g_k[BB*CI*PP];      // [b][o][p]
__device__ float g_v[BB*CC*PP];      // [b][c][p]
__device__ float g_out[BB*CC*PP];    // pre-gate output
__device__ float g_sum[BB*CC];       // per (b,c) spatial sum
__device__ unsigned g_maxk[BB*CC];   // per (b,c) spatial max (ordered-uint key)

// monotone float<->uint key for atomicMax on floats (any sign)
__device__ __forceinline__ unsigned fkey(float f) {
    unsigned u = __float_as_uint(f);
    return (u & 0x80000000u) ? ~u : (u | 0x80000000u);
}
__device__ __forceinline__ float funkey(unsigned k) {
    unsigned u = (k & 0x80000000u) ? (k & 0x7FFFFFFFu) : ~k;
    return __uint_as_float(u);
}

// ---------------- tf32 / mma helpers -----------------------------------------
__device__ __forceinline__ unsigned tf32cvt(float f) {
    unsigned r;
    asm("cvt.rna.tf32.f32 %0, %1;" : "=r"(r) : "f"(f));
    return r;
}
__device__ __forceinline__ void mma8(float c[4],
                                     unsigned a0, unsigned a1, unsigned a2, unsigned a3,
                                     unsigned b0, unsigned b1)
{
    asm volatile(
        "mma.sync.aligned.m16n8k8.row.col.f32.tf32.tf32.f32 "
        "{%0,%1,%2,%3},{%4,%5,%6,%7},{%8,%9},{%0,%1,%2,%3};"
        : "+f"(c[0]), "+f"(c[1]), "+f"(c[2]), "+f"(c[3])
        : "r"(a0), "r"(a1), "r"(a2), "r"(a3), "r"(b0), "r"(b1));
}

// ---------------- K1: q/k/v projections (tiled smem GEMM) --------------------
// grid (PP/32, BB), 256 threads: p-lane = tid&31, output-group = tid>>5 (12 outs each)
__global__ void __launch_bounds__(256)
qkv_kernel(const float* __restrict__ ftr,
           const float* __restrict__ wq, const float* __restrict__ bq,
           const float* __restrict__ wk, const float* __restrict__ bk,
           const float* __restrict__ wv, const float* __restrict__ bv)
{
    __shared__ float wt[64][96];   // transposed weights: [c][o]  (o: 0-15 q, 16-31 k, 32-95 v)
    __shared__ float bs[96];
    __shared__ float xs[64][32];   // x tile [c][p_local]

    int tid = threadIdx.x;
    for (int i = tid; i < 16*64; i += 256) { int o = i >> 6, c = i & 63; wt[c][o]      = wq[i]; }
    for (int i = tid; i < 16*64; i += 256) { int o = i >> 6, c = i & 63; wt[c][16 + o] = wk[i]; }
    for (int i = tid; i < 64*64; i += 256) { int o = i >> 6, c = i & 63; wt[c][32 + o] = wv[i]; }
    if (tid < 16) bs[tid] = bq[tid];
    else if (tid < 32) bs[tid] = bk[tid - 16];
    else if (tid < 96) bs[tid] = bv[tid - 32];
    if (blockIdx.x == 0 && blockIdx.y == 0 && tid < BB*CC) {
        g_sum[tid] = 0.0f;
        g_maxk[tid] = 0u;   // below fkey of any real float
    }

    int b  = blockIdx.y;
    int p0 = blockIdx.x * 32;
    // stage x tile: 64 rows x 32 floats = 512 float4s, 2 per thread
#pragma unroll
    for (int u = 0; u < 2; u++) {
        int f = tid + u*256;
        int c = f >> 3, s = f & 7;
        *reinterpret_cast<float4*>(&xs[c][s*4]) =
            *reinterpret_cast<const float4*>(ftr + ((size_t)b*CC + c)*PP + p0 + s*4);
    }
    __syncthreads();

    int pl  = tid & 31;
    int grp = tid >> 5;
    float acc[12];
#pragma unroll
    for (int i = 0; i < 12; i++) acc[i] = 0.0f;

#pragma unroll 8
    for (int c = 0; c < 64; c++) {
        float xv = xs[c][pl];
        float4 w0 = *reinterpret_cast<const float4*>(&wt[c][grp*12]);
        float4 w1 = *reinterpret_cast<const float4*>(&wt[c][grp*12 + 4]);
        float4 w2 = *reinterpret_cast<const float4*>(&wt[c][grp*12 + 8]);
        acc[0]  = fmaf(w0.x, xv, acc[0]);
        acc[1]  = fmaf(w0.y, xv, acc[1]);
        acc[2]  = fmaf(w0.z, xv, acc[2]);
        acc[3]  = fmaf(w0.w, xv, acc[3]);
        acc[4]  = fmaf(w1.x, xv, acc[4]);
        acc[5]  = fmaf(w1.y, xv, acc[5]);
        acc[6]  = fmaf(w1.z, xv, acc[6]);
        acc[7]  = fmaf(w1.w, xv, acc[7]);
        acc[8]  = fmaf(w2.x, xv, acc[8]);
        acc[9]  = fmaf(w2.y, xv, acc[9]);
        acc[10] = fmaf(w2.z, xv, acc[10]);
        acc[11] = fmaf(w2.w, xv, acc[11]);
    }

    int p = p0 + pl;
#pragma unroll
    for (int o = 0; o < 12; o++) {
        int go = grp*12 + o;
        float val = acc[o] + bs[go];
        if (go < 16)
            g_q[(((size_t)b*PP + p) << 4) + go] = val;
        else if (go < 32)
            g_k[((size_t)b*CI + (go - 16))*PP + p] = val;
        else
            g_v[((size_t)b*CC + (go - 32))*PP + p] = val;
    }
}

// ---------------- K2: flash attention on tensor cores (tf32) -----------------
#define QS 20     // Q_s row stride (floats)
#define VS 132    // V_s row stride
#define SS 72     // S_s row stride
#define KS 68     // K_s row stride

struct SmemA {
    unsigned kk[16*KS];       // K tile, tf32
    unsigned qq[128*QS];      // Q tile, tf32
    float    vv[64*VS];       // V tile, raw fp32 (tf32 by truncation)
    float    ss[128*SS];      // scores -> E (tf32 bits); reused for k-merge
    float red_m[4][64];
    float red_l[4][64];
    float scale_s[64];
    float l_s[64];
    float psum[64][2];
    float pmax[64][2];
};

extern __shared__ char smem_raw[];

// grid (PP/NCOL, BB), 256 threads (8 warps)
__global__ void __launch_bounds__(256, 2)
attn_kernel(const float* __restrict__ ftr, const float* __restrict__ delta)
{
    SmemA& sm = *reinterpret_cast<SmemA*>(smem_raw);
    int tid  = threadIdx.x;
    int w    = tid >> 5;
    int lane = tid & 31;
    int r    = lane >> 2;   // fragment row group
    int q4   = lane & 3;    // fragment col group
    int b    = blockIdx.y;
    int col0 = blockIdx.x * NCOL;

    // k-split warp tiling for MMA2: warp = (k-half, warp-tile)
    int ws_k = w & 1;            // k-half: p in [ws_k*64, ws_k*64+64)
    int wt   = w >> 1;           // 0..3
    int m0   = (wt & 1) * 32;    // channel block
    int n0   = (wt >> 1) * 32;   // column block

    // ---- stage K tile (once), tf32 ----
    for (int i = tid; i < 16*64; i += 256) {
        int o = i >> 6, jj = i & 63;
        sm.kk[o*KS + jj] = tf32cvt(g_k[((size_t)(b*CI + o))*PP + col0 + jj]);
    }
    __syncthreads();

    // ---- resident K B-fragments for MMA1: kb[n][kstep][reg] ----
    unsigned kb[8][2][2];
#pragma unroll
    for (int n = 0; n < 8; n++)
#pragma unroll
        for (int ks = 0; ks < 2; ks++) {
            kb[n][ks][0] = sm.kk[(ks*8 + q4    )*KS + n*8 + r];
            kb[n][ks][1] = sm.kk[(ks*8 + q4 + 4)*KS + n*8 + r];
        }

    // per-thread softmax state for column j (replicated across g groups)
    int j = tid & 63;
    int g = tid >> 6;
    float m = -INFINITY, l = 0.0f;

    // MMA2 accumulator: m32 x n32 x k64 per warp -> [mb2][nb][4]
    float cacc[2][4][4];
#pragma unroll
    for (int a = 0; a < 2; a++)
#pragma unroll
        for (int bq_ = 0; bq_ < 4; bq_++)
#pragma unroll
            for (int k2 = 0; k2 < 4; k2++) cacc[a][bq_][k2] = 0.0f;

    const float4* qsrc_all = reinterpret_cast<const float4*>(g_q + (size_t)b*PP*CI);
    const float*  vbase    = g_v + (size_t)b*CC*PP;

    for (int t = 0; t < PP/TP; t++) {
        int p0 = t * TP;

        // ---- stage Q tile (tf32) ----
#pragma unroll
        for (int u = 0; u < 2; u++) {
            int fidx = tid + u*256;
            float4 qv = qsrc_all[p0*4 + fidx];
            int row = fidx >> 2, c4 = (fidx & 3) * 4;
            uint4 qt = { tf32cvt(qv.x), tf32cvt(qv.y), tf32cvt(qv.z), tf32cvt(qv.w) };
            *reinterpret_cast<uint4*>(&sm.qq[row*QS + c4]) = qt;
        }
        // ---- stage V tile ----
#pragma unroll
        for (int rr = 0; rr < 8; rr++) {
            int fidx = rr*256 + tid;
            int row = fidx >> 5, c4i = fidx & 31;
            *reinterpret_cast<float4*>(&sm.vv[row*VS + c4i*4]) =
                reinterpret_cast<const float4*>(vbase + (size_t)row*PP + p0)[c4i];
        }
        __syncthreads();

        // ---- MMA1: S[128x64], warp w does rows [w*16, w*16+16) ----
        {
            int pb = w * 16;
            unsigned a[2][4];
#pragma unroll
            for (int ks = 0; ks < 2; ks++) {
                int cbase = ks*8 + q4;
                a[ks][0] = sm.qq[(pb + r    )*QS + cbase];
                a[ks][1] = sm.qq[(pb + r + 8)*QS + cbase];
                a[ks][2] = sm.qq[(pb + r    )*QS + cbase + 4];
                a[ks][3] = sm.qq[(pb + r + 8)*QS + cbase + 4];
            }
#pragma unroll
            for (int n = 0; n < 8; n++) {
                float c[4] = {0.f, 0.f, 0.f, 0.f};
                mma8(c, a[0][0], a[0][1], a[0][2], a[0][3], kb[n][0][0], kb[n][0][1]);
                mma8(c, a[1][0], a[1][1], a[1][2], a[1][3], kb[n][1][0], kb[n][1][1]);
                *reinterpret_cast<float2*>(&sm.ss[(pb + r    )*SS + n*8 + q4*2]) = make_float2(c[0], c[1]);
                *reinterpret_cast<float2*>(&sm.ss[(pb + r + 8)*SS + n*8 + q4*2]) = make_float2(c[2], c[3]);
            }
        }
        __syncthreads();

        // ---- softmax (online, over p); cache scores in regs ----
        float sreg[32];
        float lmax = -INFINITY;
#pragma unroll
        for (int i = 0; i < 32; i++) {
            sreg[i] = sm.ss[(g*32 + i)*SS + j];
            lmax = fmaxf(lmax, sreg[i]);
        }
        sm.red_m[g][j] = lmax;
        __syncthreads();

        float mt = fmaxf(fmaxf(sm.red_m[0][j], sm.red_m[1][j]),
                         fmaxf(sm.red_m[2][j], sm.red_m[3][j]));
        float mnew  = fmaxf(m, mt);
        float scale = __expf(m - mnew);     // first tile: exp(-inf)=0
        if (tid < 64) sm.scale_s[tid] = scale;

        float lp = 0.0f;
#pragma unroll
        for (int i = 0; i < 32; i++) {
            float e = __expf(sreg[i] - mnew);
            lp += e;
            sm.ss[(g*32 + i)*SS + j] = __uint_as_float(tf32cvt(e));
        }
        sm.red_l[g][j] = lp;
        __syncthreads();

        l = l*scale + (sm.red_l[0][j] + sm.red_l[1][j] + sm.red_l[2][j] + sm.red_l[3][j]);
        m = mnew;

        // ---- MMA2 (k-split): G[m32,n32] += V[m32,k64] * E[k64,n32] ----
#pragma unroll
        for (int mb2 = 0; mb2 < 2; mb2++)
#pragma unroll
            for (int nb = 0; nb < 4; nb++) {
                int cb = n0 + nb*8 + q4*2;
                float s0 = sm.scale_s[cb], s1 = sm.scale_s[cb + 1];
                cacc[mb2][nb][0] *= s0; cacc[mb2][nb][1] *= s1;
                cacc[mb2][nb][2] *= s0; cacc[mb2][nb][3] *= s1;
            }
#pragma unroll 2
        for (int k0 = 0; k0 < 8; k0++) {
            int p = ws_k*64 + k0*8;
            unsigned va[2][4];
#pragma unroll
            for (int mb2 = 0; mb2 < 2; mb2++) {
                int row = m0 + mb2*16;
                va[mb2][0] = __float_as_uint(sm.vv[(row + r    )*VS + p + q4]);
                va[mb2][1] = __float_as_uint(sm.vv[(row + r + 8)*VS + p + q4]);
                va[mb2][2] = __float_as_uint(sm.vv[(row + r    )*VS + p + q4 + 4]);
                va[mb2][3] = __float_as_uint(sm.vv[(row + r + 8)*VS + p + q4 + 4]);
            }
#pragma unroll
            for (int nb = 0; nb < 4; nb++) {
                int nn = n0 + nb*8;
                unsigned eb0 = __float_as_uint(sm.ss[(p + q4    )*SS + nn + r]);
                unsigned eb1 = __float_as_uint(sm.ss[(p + q4 + 4)*SS + nn + r]);
                mma8(cacc[0][nb], va[0][0], va[0][1], va[0][2], va[0][3], eb0, eb1);
                mma8(cacc[1][nb], va[1][0], va[1][1], va[1][2], va[1][3], eb0, eb1);
            }
        }
        __syncthreads();
    }

    // ---- publish l, merge k-split halves ----
    if (tid < 64) sm.l_s[tid] = l;
    if (ws_k == 1) {
        float* mg = &sm.ss[wt * 1024];
#pragma unroll
        for (int mb2 = 0; mb2 < 2; mb2++)
#pragma unroll
            for (int nb = 0; nb < 4; nb++)
#pragma unroll
                for (int k2 = 0; k2 < 4; k2++)
                    mg[(mb2*16 + nb*4 + k2)*32 + lane] = cacc[mb2][nb][k2];
    }
    __syncthreads();

    if (ws_k == 0) {
        const float* mg = &sm.ss[wt * 1024];
#pragma unroll
        for (int mb2 = 0; mb2 < 2; mb2++)
#pragma unroll
            for (int nb = 0; nb < 4; nb++)
#pragma unroll
                for (int k2 = 0; k2 < 4; k2++)
                    cacc[mb2][nb][k2] += mg[(mb2*16 + nb*4 + k2)*32 + lane];

        // ---- epilogue: out = delta*G/l + ftr, plus per-row pooling partials ----
        float dlt = delta[0];
        float psum_[2][2], pmax_[2][2];
#pragma unroll
        for (int mb2 = 0; mb2 < 2; mb2++)
#pragma unroll
            for (int hh = 0; hh < 2; hh++) { psum_[mb2][hh] = 0.0f; pmax_[mb2][hh] = -INFINITY; }

#pragma unroll
        for (int mb2 = 0; mb2 < 2; mb2++)
#pragma unroll
            for (int nb = 0; nb < 4; nb++) {
                int cl = n0 + nb*8 + q4*2;
                float inv0 = 1.0f / sm.l_s[cl];
                float inv1 = 1.0f / sm.l_s[cl + 1];
                int row = m0 + mb2*16 + r;
                size_t base0 = ((size_t)b*CC + row)*PP + col0 + cl;
                float2 f0 = *reinterpret_cast<const float2*>(&ftr[base0]);
                float2 o0 = make_float2(dlt*cacc[mb2][nb][0]*inv0 + f0.x,
                                        dlt*cacc[mb2][nb][1]*inv1 + f0.y);
                *reinterpret_cast<float2*>(&g_out[base0]) = o0;
                psum_[mb2][0] += o0.x + o0.y;
                pmax_[mb2][0] = fmaxf(pmax_[mb2][0], fmaxf(o0.x, o0.y));

                size_t base1 = base0 + (size_t)8*PP;
                float2 f1 = *reinterpret_cast<const float2*>(&ftr[base1]);
                float2 o1 = make_float2(dlt*cacc[mb2][nb][2]*inv0 + f1.x,
                                        dlt*cacc[mb2][nb][3]*inv1 + f1.y);
                *reinterpret_cast<float2*>(&g_out[base1]) = o1;
                psum_[mb2][1] += o1.x + o1.y;
                pmax_[mb2][1] = fmaxf(pmax_[mb2][1], fmaxf(o1.x, o1.y));
            }

        // reduce over q4 lanes (xor 1, 2)
#pragma unroll
        for (int mb2 = 0; mb2 < 2; mb2++)
#pragma unroll
            for (int hh = 0; hh < 2; hh++) {
#pragma unroll
                for (int off = 1; off <= 2; off <<= 1) {
                    psum_[mb2][hh] += __shfl_xor_sync(0xffffffffu, psum_[mb2][hh], off);
                    pmax_[mb2][hh] = fmaxf(pmax_[mb2][hh],
                                           __shfl_xor_sync(0xffffffffu, pmax_[mb2][hh], off));
                }
                if (q4 == 0) {
                    int row = m0 + mb2*16 + r + hh*8;
                    int nhalf = wt >> 1;
                    sm.psum[row][nhalf] = psum_[mb2][hh];
                    sm.pmax[row][nhalf] = pmax_[mb2][hh];
                }
            }
    }
    __syncthreads();

    if (tid < 64) {
        float s  = sm.psum[tid][0] + sm.psum[tid][1];
        float mx = fmaxf(sm.pmax[tid][0], sm.pmax[tid][1]);
        atomicAdd(&g_sum[b*CC + tid], s);
        atomicMax(&g_maxk[b*CC + tid], fkey(mx));
    }
}

// ---------------- K3: apply gate (gate computed per-block, redundantly) ------
__global__ void final_kernel(float* __restrict__ out,
                             const float* __restrict__ w_avg1, const float* __restrict__ w_avg2,
                             const float* __restrict__ w_max1, const float* __restrict__ w_max2)
{
    __shared__ float hh[32];
    __shared__ float gate_s;
    int t = threadIdx.x;
    int blk = blockIdx.x;          // 0..511; block = half a channel (2048 floats)
    int b = blk >> 7;
    int c = (blk >> 1) & 63;

    // hidden layer: 32 dots of length 64, 8 threads each
    {
        int d = t >> 3, part = t & 7;
        int branch = d >> 4, o = d & 15;
        const float* w1 = branch ? w_max1 : w_avg1;
        float acc = 0.0f;
#pragma unroll
        for (int i = 0; i < 8; i++) {
            int idx = part*8 + i;
            float f = branch ? funkey(g_maxk[b*CC + idx])
                             : g_sum[b*CC + idx] * (1.0f/(float)PP);
            acc += w1[o*64 + idx] * f;
        }
#pragma unroll
        for (int off = 1; off <= 4; off <<= 1)
            acc += __shfl_xor_sync(0xffffffffu, acc, off);
        if (part == 0) hh[d] = fmaxf(acc, 0.0f);
    }
    __syncthreads();
    if (t == 0) {
        float a = 0.0f, mm = 0.0f;
#pragma unroll
        for (int o = 0; o < 16; o++) {
            a  += w_avg2[c*16 + o] * hh[o];
            mm += w_max2[c*16 + o] * hh[16 + o];
        }
        gate_s = 1.0f / (1.0f + __expf(-(a + mm)));
    }
    __syncthreads();

    float gv = gate_s;
    int base = blk * 512 + t;      // float4 units
    float4 v0 = reinterpret_cast<const float4*>(g_out)[base];
    float4 v1 = reinterpret_cast<const float4*>(g_out)[base + 256];
    v0.x *= gv; v0.y *= gv; v0.z *= gv; v0.w *= gv;
    v1.x *= gv; v1.y *= gv; v1.z *= gv; v1.w *= gv;
    reinterpret_cast<float4*>(out)[base] = v0;
    reinterpret_cast<float4*>(out)[base + 256] = v1;
}

// ---------------- launch ------------------------------------------------------
extern "C" void kernel_launch(void* const* d_in, const int* in_sizes, int n_in,
                              void* d_out, int out_size)
{
    const float* ftr    = (const float*)d_in[0];
    const float* wq     = (const float*)d_in[1];
    const float* bq     = (const float*)d_in[2];
    const float* wk     = (const float*)d_in[3];
    const float* bk     = (const float*)d_in[4];
    const float* wv     = (const float*)d_in[5];
    const float* bv     = (const float*)d_in[6];
    const float* delta  = (const float*)d_in[7];
    const float* w_avg1 = (const float*)d_in[8];
    const float* w_avg2 = (const float*)d_in[9];
    const float* w_max1 = (const float*)d_in[10];
    const float* w_max2 = (const float*)d_in[11];
    float* out = (float*)d_out;

    cudaFuncSetAttribute(attn_kernel, cudaFuncAttributeMaxDynamicSharedMemorySize,
                         (int)sizeof(SmemA));

    qkv_kernel<<<dim3(PP/32, BB), 256>>>(ftr, wq, bq, wk, bk, wv, bv);
    attn_kernel<<<dim3(PP/NCOL, BB), 256, sizeof(SmemA)>>>(ftr, delta);
    final_kernel<<<512, 256>>>(out, w_avg1, w_avg2, w_max1, w_max2);
}

// round 8
// speedup vs baseline: 4.2993x; 1.4522x over previous
#include <cuda_runtime.h>
#include <cuda_bf16.h>
#include <math.h>

#define BB 4
#define CC 64
#define CI 16
#define PP 4096
#define NCOL 64
#define TP 128

// ---------------- scratch (device globals; no allocations allowed) ----------
__device__ float    g_q[BB*PP*CI];       // [b][p][o]  fp32 (MMA1 is tf32)
__device__ float    g_k[BB*CI*PP];       // [b][o][p]  fp32
__device__ unsigned g_v32[BB*CC*PP/2];   // [b][c][p/2] packed bf16x2
__device__ float    g_out[BB*CC*PP];     // pre-gate output
__device__ float    g_sum[BB*CC];
__device__ unsigned g_maxk[BB*CC];

// monotone float<->uint key for atomicMax on floats (any sign)
__device__ __forceinline__ unsigned fkey(float f) {
    unsigned u = __float_as_uint(f);
    return (u & 0x80000000u) ? ~u : (u | 0x80000000u);
}
__device__ __forceinline__ float funkey(unsigned k) {
    unsigned u = (k & 0x80000000u) ? (k & 0x7FFFFFFFu) : ~k;
    return __uint_as_float(u);
}

// ---------------- cvt / mma helpers ------------------------------------------
__device__ __forceinline__ unsigned tf32cvt(float f) {
    unsigned r;
    asm("cvt.rna.tf32.f32 %0, %1;" : "=r"(r) : "f"(f));
    return r;
}
// d = {hi=cvt(hi), lo=cvt(lo)}
__device__ __forceinline__ unsigned bf16x2pack(float hi, float lo) {
    unsigned r;
    asm("cvt.rn.bf16x2.f32 %0, %1, %2;" : "=r"(r) : "f"(hi), "f"(lo));
    return r;
}
__device__ __forceinline__ void mma8(float c[4],
                                     unsigned a0, unsigned a1, unsigned a2, unsigned a3,
                                     unsigned b0, unsigned b1)
{
    asm volatile(
        "mma.sync.aligned.m16n8k8.row.col.f32.tf32.tf32.f32 "
        "{%0,%1,%2,%3},{%4,%5,%6,%7},{%8,%9},{%0,%1,%2,%3};"
        : "+f"(c[0]), "+f"(c[1]), "+f"(c[2]), "+f"(c[3])
        : "r"(a0), "r"(a1), "r"(a2), "r"(a3), "r"(b0), "r"(b1));
}
__device__ __forceinline__ void mma16(float c[4], const unsigned a[4],
                                      unsigned b0, unsigned b1)
{
    asm volatile(
        "mma.sync.aligned.m16n8k16.row.col.f32.bf16.bf16.f32 "
        "{%0,%1,%2,%3},{%4,%5,%6,%7},{%8,%9},{%0,%1,%2,%3};"
        : "+f"(c[0]), "+f"(c[1]), "+f"(c[2]), "+f"(c[3])
        : "r"(a[0]), "r"(a[1]), "r"(a[2]), "r"(a[3]), "r"(b0), "r"(b1));
}

// ---------------- K1: q/k/v projections (tiled smem GEMM, 2p/thread) --------
// grid (PP/64, BB), 256 threads: pl = tid&31 (2 p's), grp = tid>>5 (12 outs)
#define WTS 100
__global__ void __launch_bounds__(256)
qkv_kernel(const float* __restrict__ ftr,
           const float* __restrict__ wq, const float* __restrict__ bq,
           const float* __restrict__ wk, const float* __restrict__ bk,
           const float* __restrict__ wv, const float* __restrict__ bv)
{
    __shared__ float wt[64][WTS];  // transposed weights [c][o]  (0-15 q, 16-31 k, 32-95 v)
    __shared__ float bs[96];
    __shared__ float xs[64][64];   // x tile [c][p_local]

    int tid = threadIdx.x;
    for (int i = tid; i < 16*64; i += 256) { int o = i >> 6, c = i & 63; wt[c][o]      = wq[i]; }
    for (int i = tid; i < 16*64; i += 256) { int o = i >> 6, c = i & 63; wt[c][16 + o] = wk[i]; }
    for (int i = tid; i < 64*64; i += 256) { int o = i >> 6, c = i & 63; wt[c][32 + o] = wv[i]; }
    if (tid < 16) bs[tid] = bq[tid];
    else if (tid < 32) bs[tid] = bk[tid - 16];
    else if (tid < 96) bs[tid] = bv[tid - 32];
    if (blockIdx.x == 0 && blockIdx.y == 0 && tid < BB*CC) {
        g_sum[tid] = 0.0f;
        g_maxk[tid] = 0u;
    }

    int b  = blockIdx.y;
    int p0 = blockIdx.x * 64;
    // stage x tile: 64 rows x 64 floats = 1024 float4s, 4 per thread
#pragma unroll
    for (int u = 0; u < 4; u++) {
        int f = tid + u*256;
        int c = f >> 4, s = f & 15;
        *reinterpret_cast<float4*>(&xs[c][s*4]) =
            *reinterpret_cast<const float4*>(ftr + ((size_t)b*CC + c)*PP + p0 + s*4);
    }
    __syncthreads();

    int pl  = tid & 31;
    int grp = tid >> 5;
    float acc[12][2];
#pragma unroll
    for (int i = 0; i < 12; i++) acc[i][0] = acc[i][1] = 0.0f;

#pragma unroll 4
    for (int c = 0; c < 64; c++) {
        float2 xv = *reinterpret_cast<const float2*>(&xs[c][pl*2]);
        float4 w0 = *reinterpret_cast<const float4*>(&wt[c][grp*12]);
        float4 w1 = *reinterpret_cast<const float4*>(&wt[c][grp*12 + 4]);
        float4 w2 = *reinterpret_cast<const float4*>(&wt[c][grp*12 + 8]);
        acc[0][0]  = fmaf(w0.x, xv.x, acc[0][0]);   acc[0][1]  = fmaf(w0.x, xv.y, acc[0][1]);
        acc[1][0]  = fmaf(w0.y, xv.x, acc[1][0]);   acc[1][1]  = fmaf(w0.y, xv.y, acc[1][1]);
        acc[2][0]  = fmaf(w0.z, xv.x, acc[2][0]);   acc[2][1]  = fmaf(w0.z, xv.y, acc[2][1]);
        acc[3][0]  = fmaf(w0.w, xv.x, acc[3][0]);   acc[3][1]  = fmaf(w0.w, xv.y, acc[3][1]);
        acc[4][0]  = fmaf(w1.x, xv.x, acc[4][0]);   acc[4][1]  = fmaf(w1.x, xv.y, acc[4][1]);
        acc[5][0]  = fmaf(w1.y, xv.x, acc[5][0]);   acc[5][1]  = fmaf(w1.y, xv.y, acc[5][1]);
        acc[6][0]  = fmaf(w1.z, xv.x, acc[6][0]);   acc[6][1]  = fmaf(w1.z, xv.y, acc[6][1]);
        acc[7][0]  = fmaf(w1.w, xv.x, acc[7][0]);   acc[7][1]  = fmaf(w1.w, xv.y, acc[7][1]);
        acc[8][0]  = fmaf(w2.x, xv.x, acc[8][0]);   acc[8][1]  = fmaf(w2.x, xv.y, acc[8][1]);
        acc[9][0]  = fmaf(w2.y, xv.x, acc[9][0]);   acc[9][1]  = fmaf(w2.y, xv.y, acc[9][1]);
        acc[10][0] = fmaf(w2.z, xv.x, acc[10][0]);  acc[10][1] = fmaf(w2.z, xv.y, acc[10][1]);
        acc[11][0] = fmaf(w2.w, xv.x, acc[11][0]);  acc[11][1] = fmaf(w2.w, xv.y, acc[11][1]);
    }

    int p = p0 + pl*2;
#pragma unroll
    for (int o = 0; o < 12; o++) {
        int go = grp*12 + o;
        float bsv = bs[go];
        float v0 = acc[o][0] + bsv;
        float v1 = acc[o][1] + bsv;
        if (go < 16) {
            g_q[(((size_t)b*PP + p)     << 4) + go] = v0;
            g_q[(((size_t)b*PP + p + 1) << 4) + go] = v1;
        } else if (go < 32) {
            *reinterpret_cast<float2*>(&g_k[((size_t)b*CI + (go - 16))*PP + p]) =
                make_float2(v0, v1);
        } else {
            g_v32[(((size_t)b*CC + (go - 32))*PP + p) >> 1] = bf16x2pack(v1, v0);
        }
    }
}

// ---------------- K2: flash attention on tensor cores ------------------------
#define QS 20     // Q_s row stride (floats)
#define SS 72     // S_s row stride (floats)
#define KS 68     // K_s row stride (u32)
#define VSB 68    // V bf16x2 row stride (u32)
#define ESB 72    // E bf16x2 row stride (u32)

struct SmemA {
    unsigned kk[16*KS];       // K tile, tf32
    unsigned qq[128*QS];      // Q tile, tf32
    unsigned vvb[64*VSB];     // V tile, packed bf16x2 (k=p pairs)
    float    ss[128*SS];      // scores fp32; reused for k-merge
    unsigned eeb[64*ESB];     // E tile, packed bf16x2
    float red_m[4][64];
    float red_l[4][64];
    float scale_s[64];
    float l_s[64];
    float psum[64][2];
    float pmax[64][2];
};

extern __shared__ char smem_raw[];

// grid (PP/NCOL, BB), 256 threads (8 warps)
__global__ void __launch_bounds__(256, 2)
attn_kernel(const float* __restrict__ ftr, const float* __restrict__ delta)
{
    SmemA& sm = *reinterpret_cast<SmemA*>(smem_raw);
    int tid  = threadIdx.x;
    int w    = tid >> 5;
    int lane = tid & 31;
    int r    = lane >> 2;
    int q4   = lane & 3;
    int b    = blockIdx.y;
    int col0 = blockIdx.x * NCOL;

    // k-split warp tiling for MMA2
    int ws_k = w & 1;            // p-half: [ws_k*64, ws_k*64+64)
    int wt   = w >> 1;           // 0..3
    int m0   = (wt & 1) * 32;
    int n0   = (wt >> 1) * 32;

    // ---- stage K tile (once), tf32 ----
    for (int i = tid; i < 16*64; i += 256) {
        int o = i >> 6, jj = i & 63;
        sm.kk[o*KS + jj] = tf32cvt(g_k[((size_t)(b*CI + o))*PP + col0 + jj]);
    }
    __syncthreads();

    unsigned kb[8][2][2];
#pragma unroll
    for (int n = 0; n < 8; n++)
#pragma unroll
        for (int ks = 0; ks < 2; ks++) {
            kb[n][ks][0] = sm.kk[(ks*8 + q4    )*KS + n*8 + r];
            kb[n][ks][1] = sm.kk[(ks*8 + q4 + 4)*KS + n*8 + r];
        }

    int j = tid & 63;
    int g = tid >> 6;
    float m = -INFINITY, l = 0.0f;

    float cacc[2][4][4];
#pragma unroll
    for (int a = 0; a < 2; a++)
#pragma unroll
        for (int bq_ = 0; bq_ < 4; bq_++)
#pragma unroll
            for (int k2 = 0; k2 < 4; k2++) cacc[a][bq_][k2] = 0.0f;

    const float4* qsrc_all = reinterpret_cast<const float4*>(g_q + (size_t)b*PP*CI);
    const unsigned* vbase  = g_v32 + ((size_t)b*CC*PP >> 1);

    for (int t = 0; t < PP/TP; t++) {
        int p0 = t * TP;

        // ---- stage Q tile (tf32) ----
#pragma unroll
        for (int u = 0; u < 2; u++) {
            int fidx = tid + u*256;
            float4 qv = qsrc_all[p0*4 + fidx];
            int row = fidx >> 2, c4 = (fidx & 3) * 4;
            uint4 qt = { tf32cvt(qv.x), tf32cvt(qv.y), tf32cvt(qv.z), tf32cvt(qv.w) };
            *reinterpret_cast<uint4*>(&sm.qq[row*QS + c4]) = qt;
        }
        // ---- stage V tile (bf16x2): 64 rows x 64 u32 = 1024 uint4 ----
#pragma unroll
        for (int rr = 0; rr < 4; rr++) {
            int fidx = rr*256 + tid;
            int row = fidx >> 4, c4 = fidx & 15;
            *reinterpret_cast<uint4*>(&sm.vvb[row*VSB + c4*4]) =
                *reinterpret_cast<const uint4*>(vbase + (size_t)row*(PP/2) + (p0 >> 1) + c4*4);
        }
        __syncthreads();

        // ---- MMA1 (tf32): S[128x64], warp w does rows [w*16, w*16+16) ----
        {
            int pb = w * 16;
            unsigned a[2][4];
#pragma unroll
            for (int ks = 0; ks < 2; ks++) {
                int cbase = ks*8 + q4;
                a[ks][0] = sm.qq[(pb + r    )*QS + cbase];
                a[ks][1] = sm.qq[(pb + r + 8)*QS + cbase];
                a[ks][2] = sm.qq[(pb + r    )*QS + cbase + 4];
                a[ks][3] = sm.qq[(pb + r + 8)*QS + cbase + 4];
            }
#pragma unroll
            for (int n = 0; n < 8; n++) {
                float c[4] = {0.f, 0.f, 0.f, 0.f};
                mma8(c, a[0][0], a[0][1], a[0][2], a[0][3], kb[n][0][0], kb[n][0][1]);
                mma8(c, a[1][0], a[1][1], a[1][2], a[1][3], kb[n][1][0], kb[n][1][1]);
                *reinterpret_cast<float2*>(&sm.ss[(pb + r    )*SS + n*8 + q4*2]) = make_float2(c[0], c[1]);
                *reinterpret_cast<float2*>(&sm.ss[(pb + r + 8)*SS + n*8 + q4*2]) = make_float2(c[2], c[3]);
            }
        }
        __syncthreads();

        // ---- softmax (online, over p) ----
        float sreg[32];
        float lmax = -INFINITY;
#pragma unroll
        for (int i = 0; i < 32; i++) {
            sreg[i] = sm.ss[(g*32 + i)*SS + j];
            lmax = fmaxf(lmax, sreg[i]);
        }
        sm.red_m[g][j] = lmax;
        __syncthreads();

        float mt = fmaxf(fmaxf(sm.red_m[0][j], sm.red_m[1][j]),
                         fmaxf(sm.red_m[2][j], sm.red_m[3][j]));
        float mnew  = fmaxf(m, mt);
        float scale = __expf(m - mnew);
        if (tid < 64) sm.scale_s[tid] = scale;

        float lp = 0.0f;
#pragma unroll
        for (int i2 = 0; i2 < 16; i2++) {
            float e0 = __expf(sreg[2*i2    ] - mnew);
            float e1 = __expf(sreg[2*i2 + 1] - mnew);
            lp += e0 + e1;
            sm.eeb[(g*16 + i2)*ESB + j] = bf16x2pack(e1, e0);
        }
        sm.red_l[g][j] = lp;
        __syncthreads();

        l = l*scale + (sm.red_l[0][j] + sm.red_l[1][j] + sm.red_l[2][j] + sm.red_l[3][j]);
        m = mnew;

        // ---- MMA2 (bf16, k-split): G[m32,n32] += V[m32,k64] * E[k64,n32] ----
#pragma unroll
        for (int mb2 = 0; mb2 < 2; mb2++)
#pragma unroll
            for (int nb = 0; nb < 4; nb++) {
                int cb = n0 + nb*8 + q4*2;
                float s0 = sm.scale_s[cb], s1 = sm.scale_s[cb + 1];
                cacc[mb2][nb][0] *= s0; cacc[mb2][nb][1] *= s1;
                cacc[mb2][nb][2] *= s0; cacc[mb2][nb][3] *= s1;
            }
#pragma unroll
        for (int k0 = 0; k0 < 4; k0++) {
            int pu = ws_k*32 + k0*8;           // u32 (pair) index base within tile
            unsigned va[2][4];
#pragma unroll
            for (int mb2 = 0; mb2 < 2; mb2++) {
                int row = m0 + mb2*16;
                va[mb2][0] = sm.vvb[(row + r    )*VSB + pu + q4];
                va[mb2][1] = sm.vvb[(row + r + 8)*VSB + pu + q4];
                va[mb2][2] = sm.vvb[(row + r    )*VSB + pu + q4 + 4];
                va[mb2][3] = sm.vvb[(row + r + 8)*VSB + pu + q4 + 4];
            }
#pragma unroll
            for (int nb = 0; nb < 4; nb++) {
                int nn = n0 + nb*8;
                unsigned eb0 = sm.eeb[(pu + q4    )*ESB + nn + r];
                unsigned eb1 = sm.eeb[(pu + q4 + 4)*ESB + nn + r];
                mma16(cacc[0][nb], va[0], eb0, eb1);
                mma16(cacc[1][nb], va[1], eb0, eb1);
            }
        }
        __syncthreads();
    }

    // ---- publish l, merge k-split halves ----
    if (tid < 64) sm.l_s[tid] = l;
    if (ws_k == 1) {
        float* mg = &sm.ss[wt * 1024];
#pragma unroll
        for (int mb2 = 0; mb2 < 2; mb2++)
#pragma unroll
            for (int nb = 0; nb < 4; nb++)
#pragma unroll
                for (int k2 = 0; k2 < 4; k2++)
                    mg[(mb2*16 + nb*4 + k2)*32 + lane] = cacc[mb2][nb][k2];
    }
    __syncthreads();

    if (ws_k == 0) {
        const float* mg = &sm.ss[wt * 1024];
#pragma unroll
        for (int mb2 = 0; mb2 < 2; mb2++)
#pragma unroll
            for (int nb = 0; nb < 4; nb++)
#pragma unroll
                for (int k2 = 0; k2 < 4; k2++)
                    cacc[mb2][nb][k2] += mg[(mb2*16 + nb*4 + k2)*32 + lane];

        // ---- epilogue: out = delta*G/l + ftr + pooling partials ----
        float dlt = delta[0];
        float psum_[2][2], pmax_[2][2];
#pragma unroll
        for (int mb2 = 0; mb2 < 2; mb2++)
#pragma unroll
            for (int hh = 0; hh < 2; hh++) { psum_[mb2][hh] = 0.0f; pmax_[mb2][hh] = -INFINITY; }

#pragma unroll
        for (int mb2 = 0; mb2 < 2; mb2++)
#pragma unroll
            for (int nb = 0; nb < 4; nb++) {
                int cl = n0 + nb*8 + q4*2;
                float inv0 = 1.0f / sm.l_s[cl];
                float inv1 = 1.0f / sm.l_s[cl + 1];
                int row = m0 + mb2*16 + r;
                size_t base0 = ((size_t)b*CC + row)*PP + col0 + cl;
                float2 f0 = *reinterpret_cast<const float2*>(&ftr[base0]);
                float2 o0 = make_float2(dlt*cacc[mb2][nb][0]*inv0 + f0.x,
                                        dlt*cacc[mb2][nb][1]*inv1 + f0.y);
                *reinterpret_cast<float2*>(&g_out[base0]) = o0;
                psum_[mb2][0] += o0.x + o0.y;
                pmax_[mb2][0] = fmaxf(pmax_[mb2][0], fmaxf(o0.x, o0.y));

                size_t base1 = base0 + (size_t)8*PP;
                float2 f1 = *reinterpret_cast<const float2*>(&ftr[base1]);
                float2 o1 = make_float2(dlt*cacc[mb2][nb][2]*inv0 + f1.x,
                                        dlt*cacc[mb2][nb][3]*inv1 + f1.y);
                *reinterpret_cast<float2*>(&g_out[base1]) = o1;
                psum_[mb2][1] += o1.x + o1.y;
                pmax_[mb2][1] = fmaxf(pmax_[mb2][1], fmaxf(o1.x, o1.y));
            }

#pragma unroll
        for (int mb2 = 0; mb2 < 2; mb2++)
#pragma unroll
            for (int hh = 0; hh < 2; hh++) {
#pragma unroll
                for (int off = 1; off <= 2; off <<= 1) {
                    psum_[mb2][hh] += __shfl_xor_sync(0xffffffffu, psum_[mb2][hh], off);
                    pmax_[mb2][hh] = fmaxf(pmax_[mb2][hh],
                                           __shfl_xor_sync(0xffffffffu, pmax_[mb2][hh], off));
                }
                if (q4 == 0) {
                    int row = m0 + mb2*16 + r + hh*8;
                    int nhalf = wt >> 1;
                    sm.psum[row][nhalf] = psum_[mb2][hh];
                    sm.pmax[row][nhalf] = pmax_[mb2][hh];
                }
            }
    }
    __syncthreads();

    if (tid < 64) {
        float s  = sm.psum[tid][0] + sm.psum[tid][1];
        float mx = fmaxf(sm.pmax[tid][0], sm.pmax[tid][1]);
        atomicAdd(&g_sum[b*CC + tid], s);
        atomicMax(&g_maxk[b*CC + tid], fkey(mx));
    }
}

// ---------------- K3: apply gate (gate computed per-block, redundantly) ------
__global__ void final_kernel(float* __restrict__ out,
                             const float* __restrict__ w_avg1, const float* __restrict__ w_avg2,
                             const float* __restrict__ w_max1, const float* __restrict__ w_max2)
{
    __shared__ float hh[32];
    __shared__ float gate_s;
    int t = threadIdx.x;
    int blk = blockIdx.x;
    int b = blk >> 7;
    int c = (blk >> 1) & 63;

    {
        int d = t >> 3, part = t & 7;
        int branch = d >> 4, o = d & 15;
        const float* w1 = branch ? w_max1 : w_avg1;
        float acc = 0.0f;
#pragma unroll
        for (int i = 0; i < 8; i++) {
            int idx = part*8 + i;
            float f = branch ? funkey(g_maxk[b*CC + idx])
                             : g_sum[b*CC + idx] * (1.0f/(float)PP);
            acc += w1[o*64 + idx] * f;
        }
#pragma unroll
        for (int off = 1; off <= 4; off <<= 1)
            acc += __shfl_xor_sync(0xffffffffu, acc, off);
        if (part == 0) hh[d] = fmaxf(acc, 0.0f);
    }
    __syncthreads();
    if (t == 0) {
        float a = 0.0f, mm = 0.0f;
#pragma unroll
        for (int o = 0; o < 16; o++) {
            a  += w_avg2[c*16 + o] * hh[o];
            mm += w_max2[c*16 + o] * hh[16 + o];
        }
        gate_s = 1.0f / (1.0f + __expf(-(a + mm)));
    }
    __syncthreads();

    float gv = gate_s;
    int base = blk * 512 + t;
    float4 v0 = reinterpret_cast<const float4*>(g_out)[base];
    float4 v1 = reinterpret_cast<const float4*>(g_out)[base + 256];
    v0.x *= gv; v0.y *= gv; v0.z *= gv; v0.w *= gv;
    v1.x *= gv; v1.y *= gv; v1.z *= gv; v1.w *= gv;
    reinterpret_cast<float4*>(out)[base] = v0;
    reinterpret_cast<float4*>(out)[base + 256] = v1;
}

// ---------------- launch ------------------------------------------------------
extern "C" void kernel_launch(void* const* d_in, const int* in_sizes, int n_in,
                              void* d_out, int out_size)
{
    const float* ftr    = (const float*)d_in[0];
    const float* wq     = (const float*)d_in[1];
    const float* bq     = (const float*)d_in[2];
    const float* wk     = (const float*)d_in[3];
    const float* bk     = (const float*)d_in[4];
    const float* wv     = (const float*)d_in[5];
    const float* bv     = (const float*)d_in[6];
    const float* delta  = (const float*)d_in[7];
    const float* w_avg1 = (const float*)d_in[8];
    const float* w_avg2 = (const float*)d_in[9];
    const float* w_max1 = (const float*)d_in[10];
    const float* w_max2 = (const float*)d_in[11];
    float* out = (float*)d_out;

    cudaFuncSetAttribute(attn_kernel, cudaFuncAttributeMaxDynamicSharedMemorySize,
                         (int)sizeof(SmemA));

    qkv_kernel<<<dim3(PP/64, BB), 256>>>(ftr, wq, bq, wk, bk, wv, bv);
    attn_kernel<<<dim3(PP/NCOL, BB), 256, sizeof(SmemA)>>>(ftr, delta);
    final_kernel<<<512, 256>>>(out, w_avg1, w_avg2, w_max1, w_max2);
}

// round 9
// speedup vs baseline: 4.8198x; 1.1211x over previous
#include <cuda_runtime.h>
#include <cuda_bf16.h>
#include <math.h>

#define BB 4
#define CC 64
#define CI 16
#define PP 4096
#define NCOL 64
#define TP 128

// ---------------- scratch (device globals; no allocations allowed) ----------
__device__ float    g_q[BB*CI*PP];       // [b][o][p]  fp32
__device__ float    g_k[BB*CI*PP];       // [b][o][p]  fp32
__device__ unsigned g_v32[BB*CC*PP/2];   // [b][c][p/2] packed bf16x2
__device__ float    g_out[BB*CC*PP];     // pre-gate output
__device__ float    g_sum[BB*CC];
__device__ unsigned g_maxk[BB*CC];

// monotone float<->uint key for atomicMax on floats (any sign)
__device__ __forceinline__ unsigned fkey(float f) {
    unsigned u = __float_as_uint(f);
    return (u & 0x80000000u) ? ~u : (u | 0x80000000u);
}
__device__ __forceinline__ float funkey(unsigned k) {
    unsigned u = (k & 0x80000000u) ? (k & 0x7FFFFFFFu) : ~k;
    return __uint_as_float(u);
}

// ---------------- cvt / mma helpers ------------------------------------------
__device__ __forceinline__ unsigned tf32cvt(float f) {
    unsigned r;
    asm("cvt.rna.tf32.f32 %0, %1;" : "=r"(r) : "f"(f));
    return r;
}
__device__ __forceinline__ unsigned bf16x2pack(float hi, float lo) {
    unsigned r;
    asm("cvt.rn.bf16x2.f32 %0, %1, %2;" : "=r"(r) : "f"(hi), "f"(lo));
    return r;
}
__device__ __forceinline__ void mma8(float c[4],
                                     unsigned a0, unsigned a1, unsigned a2, unsigned a3,
                                     unsigned b0, unsigned b1)
{
    asm volatile(
        "mma.sync.aligned.m16n8k8.row.col.f32.tf32.tf32.f32 "
        "{%0,%1,%2,%3},{%4,%5,%6,%7},{%8,%9},{%0,%1,%2,%3};"
        : "+f"(c[0]), "+f"(c[1]), "+f"(c[2]), "+f"(c[3])
        : "r"(a0), "r"(a1), "r"(a2), "r"(a3), "r"(b0), "r"(b1));
}
__device__ __forceinline__ void mma16(float c[4],
                                      unsigned a0, unsigned a1, unsigned a2, unsigned a3,
                                      unsigned b0, unsigned b1)
{
    asm volatile(
        "mma.sync.aligned.m16n8k16.row.col.f32.bf16.bf16.f32 "
        "{%0,%1,%2,%3},{%4,%5,%6,%7},{%8,%9},{%0,%1,%2,%3};"
        : "+f"(c[0]), "+f"(c[1]), "+f"(c[2]), "+f"(c[3])
        : "r"(a0), "r"(a1), "r"(a2), "r"(a3), "r"(b0), "r"(b1));
}

// ---------------- K1: q/k/v projections (tiled smem GEMM, 2p/thread) --------
#define WTS 100
__global__ void __launch_bounds__(256)
qkv_kernel(const float* __restrict__ ftr,
           const float* __restrict__ wq, const float* __restrict__ bq,
           const float* __restrict__ wk, const float* __restrict__ bk,
           const float* __restrict__ wv, const float* __restrict__ bv)
{
    __shared__ float wt[64][WTS];  // transposed weights [c][o]  (0-15 q, 16-31 k, 32-95 v)
    __shared__ float bs[96];
    __shared__ float xs[64][64];   // x tile [c][p_local]

    int tid = threadIdx.x;
    for (int i = tid; i < 16*64; i += 256) { int o = i >> 6, c = i & 63; wt[c][o]      = wq[i]; }
    for (int i = tid; i < 16*64; i += 256) { int o = i >> 6, c = i & 63; wt[c][16 + o] = wk[i]; }
    for (int i = tid; i < 64*64; i += 256) { int o = i >> 6, c = i & 63; wt[c][32 + o] = wv[i]; }
    if (tid < 16) bs[tid] = bq[tid];
    else if (tid < 32) bs[tid] = bk[tid - 16];
    else if (tid < 96) bs[tid] = bv[tid - 32];
    if (blockIdx.x == 0 && blockIdx.y == 0 && tid < BB*CC) {
        g_sum[tid] = 0.0f;
        g_maxk[tid] = 0u;
    }

    int b  = blockIdx.y;
    int p0 = blockIdx.x * 64;
#pragma unroll
    for (int u = 0; u < 4; u++) {
        int f = tid + u*256;
        int c = f >> 4, s = f & 15;
        *reinterpret_cast<float4*>(&xs[c][s*4]) =
            *reinterpret_cast<const float4*>(ftr + ((size_t)b*CC + c)*PP + p0 + s*4);
    }
    __syncthreads();

    int pl  = tid & 31;
    int grp = tid >> 5;
    float acc[12][2];
#pragma unroll
    for (int i = 0; i < 12; i++) acc[i][0] = acc[i][1] = 0.0f;

#pragma unroll 4
    for (int c = 0; c < 64; c++) {
        float2 xv = *reinterpret_cast<const float2*>(&xs[c][pl*2]);
        float4 w0 = *reinterpret_cast<const float4*>(&wt[c][grp*12]);
        float4 w1 = *reinterpret_cast<const float4*>(&wt[c][grp*12 + 4]);
        float4 w2 = *reinterpret_cast<const float4*>(&wt[c][grp*12 + 8]);
        acc[0][0]  = fmaf(w0.x, xv.x, acc[0][0]);   acc[0][1]  = fmaf(w0.x, xv.y, acc[0][1]);
        acc[1][0]  = fmaf(w0.y, xv.x, acc[1][0]);   acc[1][1]  = fmaf(w0.y, xv.y, acc[1][1]);
        acc[2][0]  = fmaf(w0.z, xv.x, acc[2][0]);   acc[2][1]  = fmaf(w0.z, xv.y, acc[2][1]);
        acc[3][0]  = fmaf(w0.w, xv.x, acc[3][0]);   acc[3][1]  = fmaf(w0.w, xv.y, acc[3][1]);
        acc[4][0]  = fmaf(w1.x, xv.x, acc[4][0]);   acc[4][1]  = fmaf(w1.x, xv.y, acc[4][1]);
        acc[5][0]  = fmaf(w1.y, xv.x, acc[5][0]);   acc[5][1]  = fmaf(w1.y, xv.y, acc[5][1]);
        acc[6][0]  = fmaf(w1.z, xv.x, acc[6][0]);   acc[6][1]  = fmaf(w1.z, xv.y, acc[6][1]);
        acc[7][0]  = fmaf(w1.w, xv.x, acc[7][0]);   acc[7][1]  = fmaf(w1.w, xv.y, acc[7][1]);
        acc[8][0]  = fmaf(w2.x, xv.x, acc[8][0]);   acc[8][1]  = fmaf(w2.x, xv.y, acc[8][1]);
        acc[9][0]  = fmaf(w2.y, xv.x, acc[9][0]);   acc[9][1]  = fmaf(w2.y, xv.y, acc[9][1]);
        acc[10][0] = fmaf(w2.z, xv.x, acc[10][0]);  acc[10][1] = fmaf(w2.z, xv.y, acc[10][1]);
        acc[11][0] = fmaf(w2.w, xv.x, acc[11][0]);  acc[11][1] = fmaf(w2.w, xv.y, acc[11][1]);
    }

    int p = p0 + pl*2;
#pragma unroll
    for (int o = 0; o < 12; o++) {
        int go = grp*12 + o;
        float bsv = bs[go];
        float v0 = acc[o][0] + bsv;
        float v1 = acc[o][1] + bsv;
        if (go < 16) {
            *reinterpret_cast<float2*>(&g_q[((size_t)b*CI + go)*PP + p]) =
                make_float2(v0, v1);
        } else if (go < 32) {
            *reinterpret_cast<float2*>(&g_k[((size_t)b*CI + (go - 16))*PP + p]) =
                make_float2(v0, v1);
        } else {
            g_v32[(((size_t)b*CC + (go - 32))*PP + p) >> 1] = bf16x2pack(v1, v0);
        }
    }
}

// ---------------- K2: flash attention, transposed dataflow -------------------
#define KT 20     // kkT row stride (u32)
#define QT 136    // qqT row stride (u32)
#define VS 68     // vv row stride (u32)

struct SmemB {
    unsigned kkT[64*KT];     // K^T tile tf32 [j][o]          5.1 KB
    unsigned qqT[16*QT];     // Q tile tf32 [o][p]            8.7 KB
    unsigned vv[64*VS];      // V tile bf16x2 [c][pu]        17.4 KB
    float red_m[2][64];
    float red_l[2][64];
    float scale_s[64];
    float mnew_s[64];
    float m_s[64];
    float l_s[64];
    float merge[4][32][32];  // 16 KB (k-split merge)
    float wsum[4][64];
    float wmax[4][64];
};

extern __shared__ char smem_raw[];

// grid (PP/NCOL, BB), 256 threads (8 warps): warp = (jb = w&3, ph = w>>2)
__global__ void __launch_bounds__(256, 2)
attn_kernel(const float* __restrict__ ftr, const float* __restrict__ delta)
{
    SmemB& sm = *reinterpret_cast<SmemB*>(smem_raw);
    int tid  = threadIdx.x;
    int w    = tid >> 5;
    int lane = tid & 31;
    int r    = lane >> 2;
    int q4   = lane & 3;
    int b    = blockIdx.y;
    int col0 = blockIdx.x * NCOL;

    int jb = w & 3;           // j block (16 cols of S^T rows)
    int ph = w >> 2;          // p half within tile (64 p each)
    int j0 = jb*16 + r;
    int j1 = j0 + 8;

    // ---- stage K^T tile (once): kkT[j][o] = k[o][col0+j], tf32 ----
    for (int i = tid; i < 16*64; i += 256) {
        int o = i >> 6, jj = i & 63;
        sm.kkT[jj*KT + o] = tf32cvt(g_k[((size_t)(b*CI + o))*PP + col0 + jj]);
    }
    if (tid < 64) { sm.m_s[tid] = -INFINITY; sm.l_s[tid] = 0.0f; }
    __syncthreads();

    // resident K A-fragments (m=j, k=o): 8 regs
    unsigned ka[2][4];
#pragma unroll
    for (int ks = 0; ks < 2; ks++) {
        ka[ks][0] = sm.kkT[(jb*16 + r    )*KT + ks*8 + q4];
        ka[ks][1] = sm.kkT[(jb*16 + r + 8)*KT + ks*8 + q4];
        ka[ks][2] = sm.kkT[(jb*16 + r    )*KT + ks*8 + q4 + 4];
        ka[ks][3] = sm.kkT[(jb*16 + r + 8)*KT + ks*8 + q4 + 4];
    }

    // G^T accumulator: m16(j) x n64(c) x k64(p-half) per warp
    float cacc[8][4];
#pragma unroll
    for (int nb = 0; nb < 8; nb++)
#pragma unroll
        for (int k2 = 0; k2 < 4; k2++) cacc[nb][k2] = 0.0f;

    const unsigned* vbase = g_v32 + ((size_t)b*CC*PP >> 1);

    for (int t = 0; t < PP/TP; t++) {
        int p0 = t * TP;

        // ---- stage Q tile [o][p] tf32: 16 x 128 ----
#pragma unroll
        for (int u = 0; u < 2; u++) {
            int fidx = tid + u*256;          // 512 float4
            int o = fidx >> 5, p4 = fidx & 31;
            float4 qv = *reinterpret_cast<const float4*>(
                g_q + ((size_t)b*CI + o)*PP + p0 + p4*4);
            uint4 qt = { tf32cvt(qv.x), tf32cvt(qv.y), tf32cvt(qv.z), tf32cvt(qv.w) };
            *reinterpret_cast<uint4*>(&sm.qqT[o*QT + p4*4]) = qt;
        }
        // ---- stage V tile [c][pu] bf16x2: 64 x 64 u32 ----
#pragma unroll
        for (int rr = 0; rr < 4; rr++) {
            int fidx = rr*256 + tid;
            int row = fidx >> 4, c4 = fidx & 15;
            *reinterpret_cast<uint4*>(&sm.vv[row*VS + c4*4]) =
                *reinterpret_cast<const uint4*>(vbase + (size_t)row*(PP/2) + (p0 >> 1) + c4*4);
        }
        __syncthreads();

        // ---- MMA1 (tf32): S^T[j16 x p64] for this warp ----
        float sr[8][4];
#pragma unroll
        for (int nb = 0; nb < 8; nb++) {
            int pbase = ph*64 + nb*8 + r;
            unsigned b00 = sm.qqT[(q4     )*QT + pbase];
            unsigned b01 = sm.qqT[(q4 + 4 )*QT + pbase];
            unsigned b10 = sm.qqT[(8 + q4 )*QT + pbase];
            unsigned b11 = sm.qqT[(12 + q4)*QT + pbase];
            sr[nb][0] = sr[nb][1] = sr[nb][2] = sr[nb][3] = 0.0f;
            mma8(sr[nb], ka[0][0], ka[0][1], ka[0][2], ka[0][3], b00, b01);
            mma8(sr[nb], ka[1][0], ka[1][1], ka[1][2], ka[1][3], b10, b11);
        }

        // ---- per-warp max over p (in-register + 2 shfls over q4) ----
        float mr0 = -INFINITY, mr1 = -INFINITY;
#pragma unroll
        for (int nb = 0; nb < 8; nb++) {
            mr0 = fmaxf(mr0, fmaxf(sr[nb][0], sr[nb][1]));
            mr1 = fmaxf(mr1, fmaxf(sr[nb][2], sr[nb][3]));
        }
        mr0 = fmaxf(mr0, __shfl_xor_sync(0xffffffffu, mr0, 1));
        mr0 = fmaxf(mr0, __shfl_xor_sync(0xffffffffu, mr0, 2));
        mr1 = fmaxf(mr1, __shfl_xor_sync(0xffffffffu, mr1, 1));
        mr1 = fmaxf(mr1, __shfl_xor_sync(0xffffffffu, mr1, 2));
        if (q4 == 0) {
            sm.red_m[ph][j0] = mr0;
            sm.red_m[ph][j1] = mr1;
        }
        __syncthreads();

        // ---- combine stats (one thread per column j) ----
        if (tid < 64) {
            if (t > 0)
                sm.l_s[tid] = sm.l_s[tid]*sm.scale_s[tid]
                            + sm.red_l[0][tid] + sm.red_l[1][tid];
            float mn = fmaxf(sm.m_s[tid], fmaxf(sm.red_m[0][tid], sm.red_m[1][tid]));
            sm.scale_s[tid] = __expf(sm.m_s[tid] - mn);
            sm.mnew_s[tid]  = mn;
            sm.m_s[tid]     = mn;
        }
        __syncthreads();

        // ---- rescale acc, exp+pack E fragments in registers, partial l ----
        float mn0 = sm.mnew_s[j0], mn1 = sm.mnew_s[j1];
        float sc0 = sm.scale_s[j0], sc1 = sm.scale_s[j1];
#pragma unroll
        for (int nb = 0; nb < 8; nb++) {
            cacc[nb][0] *= sc0; cacc[nb][1] *= sc0;
            cacc[nb][2] *= sc1; cacc[nb][3] *= sc1;
        }
        unsigned ep[8][2];
        float ls0 = 0.0f, ls1 = 0.0f;
#pragma unroll
        for (int nb = 0; nb < 8; nb++) {
            float e0 = __expf(sr[nb][0] - mn0);
            float e1 = __expf(sr[nb][1] - mn0);
            float e2 = __expf(sr[nb][2] - mn1);
            float e3 = __expf(sr[nb][3] - mn1);
            ls0 += e0 + e1;
            ls1 += e2 + e3;
            ep[nb][0] = bf16x2pack(e1, e0);
            ep[nb][1] = bf16x2pack(e3, e2);
        }
        ls0 += __shfl_xor_sync(0xffffffffu, ls0, 1);
        ls0 += __shfl_xor_sync(0xffffffffu, ls0, 2);
        ls1 += __shfl_xor_sync(0xffffffffu, ls1, 1);
        ls1 += __shfl_xor_sync(0xffffffffu, ls1, 2);
        if (q4 == 0) {
            sm.red_l[ph][j0] = ls0;
            sm.red_l[ph][j1] = ls1;
        }

        // ---- MMA2 (bf16): G^T[j16 x c64] += E^T(regs) * V(smem) ----
#pragma unroll
        for (int kk2 = 0; kk2 < 4; kk2++) {
            int puB = ph*32 + kk2*8;
            unsigned a0 = ep[2*kk2    ][0];
            unsigned a1 = ep[2*kk2    ][1];
            unsigned a2 = ep[2*kk2 + 1][0];
            unsigned a3 = ep[2*kk2 + 1][1];
#pragma unroll
            for (int nb = 0; nb < 8; nb++) {
                unsigned b0 = sm.vv[(nb*8 + r)*VS + puB + q4];
                unsigned b1 = sm.vv[(nb*8 + r)*VS + puB + q4 + 4];
                mma16(cacc[nb], a0, a1, a2, a3, b0, b1);
            }
        }
        __syncthreads();
    }

    // ---- final l fold, k-split merge ----
    if (tid < 64)
        sm.l_s[tid] = sm.l_s[tid]*sm.scale_s[tid] + sm.red_l[0][tid] + sm.red_l[1][tid];
    if (ph == 1) {
#pragma unroll
        for (int nb = 0; nb < 8; nb++)
#pragma unroll
            for (int k2 = 0; k2 < 4; k2++)
                sm.merge[jb][nb*4 + k2][lane] = cacc[nb][k2];
    }
    __syncthreads();

    if (ph == 0) {
#pragma unroll
        for (int nb = 0; nb < 8; nb++)
#pragma unroll
            for (int k2 = 0; k2 < 4; k2++)
                cacc[nb][k2] += sm.merge[jb][nb*4 + k2][lane];

        // ---- epilogue: out = delta*G/l + ftr, pooling partials ----
        float dlt  = delta[0];
        float inv0 = 1.0f / sm.l_s[j0];
        float inv1 = 1.0f / sm.l_s[j1];
        float ps[8][2], pm[8][2];
#pragma unroll
        for (int nb = 0; nb < 8; nb++) {
            int c0 = nb*8 + q4*2;
            size_t a00 = ((size_t)b*CC + c0)*PP + col0 + j0;   // (j0, c0)
            size_t a01 = a00 + PP;                             // (j0, c1)
            size_t a10 = a00 + 8;                              // (j1, c0)
            size_t a11 = a01 + 8;                              // (j1, c1)
            float o00 = dlt*cacc[nb][0]*inv0 + ftr[a00];
            float o01 = dlt*cacc[nb][1]*inv0 + ftr[a01];
            float o10 = dlt*cacc[nb][2]*inv1 + ftr[a10];
            float o11 = dlt*cacc[nb][3]*inv1 + ftr[a11];
            g_out[a00] = o00; g_out[a01] = o01;
            g_out[a10] = o10; g_out[a11] = o11;
            ps[nb][0] = o00 + o10;  pm[nb][0] = fmaxf(o00, o10);
            ps[nb][1] = o01 + o11;  pm[nb][1] = fmaxf(o01, o11);
        }
        // reduce over j within warp (r lanes: xor 4, 8, 16)
#pragma unroll
        for (int nb = 0; nb < 8; nb++)
#pragma unroll
            for (int par = 0; par < 2; par++) {
#pragma unroll
                for (int off = 4; off <= 16; off <<= 1) {
                    ps[nb][par] += __shfl_xor_sync(0xffffffffu, ps[nb][par], off);
                    pm[nb][par] = fmaxf(pm[nb][par],
                                        __shfl_xor_sync(0xffffffffu, pm[nb][par], off));
                }
            }
        if (r == 0) {
#pragma unroll
            for (int nb = 0; nb < 8; nb++) {
                sm.wsum[jb][nb*8 + q4*2    ] = ps[nb][0];
                sm.wsum[jb][nb*8 + q4*2 + 1] = ps[nb][1];
                sm.wmax[jb][nb*8 + q4*2    ] = pm[nb][0];
                sm.wmax[jb][nb*8 + q4*2 + 1] = pm[nb][1];
            }
        }
    }
    __syncthreads();

    if (tid < 64) {
        float s  = sm.wsum[0][tid] + sm.wsum[1][tid] + sm.wsum[2][tid] + sm.wsum[3][tid];
        float mx = fmaxf(fmaxf(sm.wmax[0][tid], sm.wmax[1][tid]),
                         fmaxf(sm.wmax[2][tid], sm.wmax[3][tid]));
        atomicAdd(&g_sum[b*CC + tid], s);
        atomicMax(&g_maxk[b*CC + tid], fkey(mx));
    }
}

// ---------------- K3: apply gate (gate computed per-block, redundantly) ------
__global__ void final_kernel(float* __restrict__ out,
                             const float* __restrict__ w_avg1, const float* __restrict__ w_avg2,
                             const float* __restrict__ w_max1, const float* __restrict__ w_max2)
{
    __shared__ float hh[32];
    __shared__ float gate_s;
    int t = threadIdx.x;
    int blk = blockIdx.x;
    int b = blk >> 7;
    int c = (blk >> 1) & 63;

    {
        int d = t >> 3, part = t & 7;
        int branch = d >> 4, o = d & 15;
        const float* w1 = branch ? w_max1 : w_avg1;
        float acc = 0.0f;
#pragma unroll
        for (int i = 0; i < 8; i++) {
            int idx = part*8 + i;
            float f = branch ? funkey(g_maxk[b*CC + idx])
                             : g_sum[b*CC + idx] * (1.0f/(float)PP);
            acc += w1[o*64 + idx] * f;
        }
#pragma unroll
        for (int off = 1; off <= 4; off <<= 1)
            acc += __shfl_xor_sync(0xffffffffu, acc, off);
        if (part == 0) hh[d] = fmaxf(acc, 0.0f);
    }
    __syncthreads();
    if (t == 0) {
        float a = 0.0f, mm = 0.0f;
#pragma unroll
        for (int o = 0; o < 16; o++) {
            a  += w_avg2[c*16 + o] * hh[o];
            mm += w_max2[c*16 + o] * hh[16 + o];
        }
        gate_s = 1.0f / (1.0f + __expf(-(a + mm)));
    }
    __syncthreads();

    float gv = gate_s;
    int base = blk * 512 + t;
    float4 v0 = reinterpret_cast<const float4*>(g_out)[base];
    float4 v1 = reinterpret_cast<const float4*>(g_out)[base + 256];
    v0.x *= gv; v0.y *= gv; v0.z *= gv; v0.w *= gv;
    v1.x *= gv; v1.y *= gv; v1.z *= gv; v1.w *= gv;
    reinterpret_cast<float4*>(out)[base] = v0;
    reinterpret_cast<float4*>(out)[base + 256] = v1;
}

// ---------------- launch ------------------------------------------------------
extern "C" void kernel_launch(void* const* d_in, const int* in_sizes, int n_in,
                              void* d_out, int out_size)
{
    const float* ftr    = (const float*)d_in[0];
    const float* wq     = (const float*)d_in[1];
    const float* bq     = (const float*)d_in[2];
    const float* wk     = (const float*)d_in[3];
    const float* bk     = (const float*)d_in[4];
    const float* wv     = (const float*)d_in[5];
    const float* bv     = (const float*)d_in[6];
    const float* delta  = (const float*)d_in[7];
    const float* w_avg1 = (const float*)d_in[8];
    const float* w_avg2 = (const float*)d_in[9];
    const float* w_max1 = (const float*)d_in[10];
    const float* w_max2 = (const float*)d_in[11];
    float* out = (float*)d_out;

    cudaFuncSetAttribute(attn_kernel, cudaFuncAttributeMaxDynamicSharedMemorySize,
                         (int)sizeof(SmemB));

    qkv_kernel<<<dim3(PP/64, BB), 256>>>(ftr, wq, bq, wk, bk, wv, bv);
    attn_kernel<<<dim3(PP/NCOL, BB), 256, sizeof(SmemB)>>>(ftr, delta);
    final_kernel<<<512, 256>>>(out, w_avg1, w_avg2, w_max1, w_max2);
}

// round 10
// speedup vs baseline: 5.1561x; 1.0698x over previous
#include <cuda_runtime.h>
#include <cuda_bf16.h>
#include <math.h>

#define BB 4
#define CC 64
#define CI 16
#define PP 4096
#define NCOL 64
#define TP 128
#define NT (PP/TP)

// ---------------- scratch (device globals; no allocations allowed) ----------
__device__ float    g_q[BB*CI*PP];       // [b][o][p]  fp32
__device__ float    g_k[BB*CI*PP];       // [b][o][p]  fp32
__device__ unsigned g_v32[BB*CC*PP/2];   // [b][c][p/2] packed bf16x2
__device__ float    g_out[BB*CC*PP];     // pre-gate output
__device__ float    g_sum[BB*CC];
__device__ unsigned g_maxk[BB*CC];

__device__ __forceinline__ unsigned fkey(float f) {
    unsigned u = __float_as_uint(f);
    return (u & 0x80000000u) ? ~u : (u | 0x80000000u);
}
__device__ __forceinline__ float funkey(unsigned k) {
    unsigned u = (k & 0x80000000u) ? (k & 0x7FFFFFFFu) : ~k;
    return __uint_as_float(u);
}

// ---------------- cvt / mma / cp.async helpers --------------------------------
__device__ __forceinline__ unsigned tf32cvt(float f) {
    unsigned r;
    asm("cvt.rna.tf32.f32 %0, %1;" : "=r"(r) : "f"(f));
    return r;
}
__device__ __forceinline__ unsigned bf16x2pack(float hi, float lo) {
    unsigned r;
    asm("cvt.rn.bf16x2.f32 %0, %1, %2;" : "=r"(r) : "f"(hi), "f"(lo));
    return r;
}
__device__ __forceinline__ void mma8(float c[4],
                                     unsigned a0, unsigned a1, unsigned a2, unsigned a3,
                                     unsigned b0, unsigned b1)
{
    asm volatile(
        "mma.sync.aligned.m16n8k8.row.col.f32.tf32.tf32.f32 "
        "{%0,%1,%2,%3},{%4,%5,%6,%7},{%8,%9},{%0,%1,%2,%3};"
        : "+f"(c[0]), "+f"(c[1]), "+f"(c[2]), "+f"(c[3])
        : "r"(a0), "r"(a1), "r"(a2), "r"(a3), "r"(b0), "r"(b1));
}
__device__ __forceinline__ void mma16(float c[4],
                                      unsigned a0, unsigned a1, unsigned a2, unsigned a3,
                                      unsigned b0, unsigned b1)
{
    asm volatile(
        "mma.sync.aligned.m16n8k16.row.col.f32.bf16.bf16.f32 "
        "{%0,%1,%2,%3},{%4,%5,%6,%7},{%8,%9},{%0,%1,%2,%3};"
        : "+f"(c[0]), "+f"(c[1]), "+f"(c[2]), "+f"(c[3])
        : "r"(a0), "r"(a1), "r"(a2), "r"(a3), "r"(b0), "r"(b1));
}
__device__ __forceinline__ void cp16(void* dst, const void* src) {
    unsigned ds = (unsigned)__cvta_generic_to_shared(dst);
    asm volatile("cp.async.cg.shared.global [%0], [%1], 16;" :: "r"(ds), "l"(src));
}

// ---------------- K1: q/k/v projections (512 threads) ------------------------
#define WTS 100
__global__ void __launch_bounds__(512)
qkv_kernel(const float* __restrict__ ftr,
           const float* __restrict__ wq, const float* __restrict__ bq,
           const float* __restrict__ wk, const float* __restrict__ bk,
           const float* __restrict__ wv, const float* __restrict__ bv)
{
    __shared__ float wt[64][WTS];  // transposed weights [c][o]
    __shared__ float bs[96];
    __shared__ float xs[64][64];   // x tile [c][p_local]

    int tid = threadIdx.x;
    for (int i = tid; i < 16*64; i += 512) { int o = i >> 6, c = i & 63; wt[c][o]      = wq[i]; }
    for (int i = tid; i < 16*64; i += 512) { int o = i >> 6, c = i & 63; wt[c][16 + o] = wk[i]; }
    for (int i = tid; i < 64*64; i += 512) { int o = i >> 6, c = i & 63; wt[c][32 + o] = wv[i]; }
    if (tid < 16) bs[tid] = bq[tid];
    else if (tid < 32) bs[tid] = bk[tid - 16];
    else if (tid < 96) bs[tid] = bv[tid - 32];
    if (blockIdx.x == 0 && blockIdx.y == 0 && tid < BB*CC) {
        g_sum[tid] = 0.0f;
        g_maxk[tid] = 0u;
    }

    int b  = blockIdx.y;
    int p0 = blockIdx.x * 64;
#pragma unroll
    for (int u = 0; u < 2; u++) {
        int f = tid + u*512;               // 1024 float4
        int c = f >> 4, s = f & 15;
        *reinterpret_cast<float4*>(&xs[c][s*4]) =
            *reinterpret_cast<const float4*>(ftr + ((size_t)b*CC + c)*PP + p0 + s*4);
    }
    __syncthreads();

    int pl  = tid & 31;
    int grp = tid >> 5;                    // 0..15, 6 outputs each
    float acc[6][2];
#pragma unroll
    for (int i = 0; i < 6; i++) acc[i][0] = acc[i][1] = 0.0f;

#pragma unroll 4
    for (int c = 0; c < 64; c++) {
        float2 xv = *reinterpret_cast<const float2*>(&xs[c][pl*2]);
        float2 w0 = *reinterpret_cast<const float2*>(&wt[c][grp*6]);
        float2 w1 = *reinterpret_cast<const float2*>(&wt[c][grp*6 + 2]);
        float2 w2 = *reinterpret_cast<const float2*>(&wt[c][grp*6 + 4]);
        acc[0][0] = fmaf(w0.x, xv.x, acc[0][0]);  acc[0][1] = fmaf(w0.x, xv.y, acc[0][1]);
        acc[1][0] = fmaf(w0.y, xv.x, acc[1][0]);  acc[1][1] = fmaf(w0.y, xv.y, acc[1][1]);
        acc[2][0] = fmaf(w1.x, xv.x, acc[2][0]);  acc[2][1] = fmaf(w1.x, xv.y, acc[2][1]);
        acc[3][0] = fmaf(w1.y, xv.x, acc[3][0]);  acc[3][1] = fmaf(w1.y, xv.y, acc[3][1]);
        acc[4][0] = fmaf(w2.x, xv.x, acc[4][0]);  acc[4][1] = fmaf(w2.x, xv.y, acc[4][1]);
        acc[5][0] = fmaf(w2.y, xv.x, acc[5][0]);  acc[5][1] = fmaf(w2.y, xv.y, acc[5][1]);
    }

    int p = p0 + pl*2;
#pragma unroll
    for (int o = 0; o < 6; o++) {
        int go = grp*6 + o;
        float bsv = bs[go];
        float v0 = acc[o][0] + bsv;
        float v1 = acc[o][1] + bsv;
        if (go < 16) {
            *reinterpret_cast<float2*>(&g_q[((size_t)b*CI + go)*PP + p]) =
                make_float2(v0, v1);
        } else if (go < 32) {
            *reinterpret_cast<float2*>(&g_k[((size_t)b*CI + (go - 16))*PP + p]) =
                make_float2(v0, v1);
        } else {
            g_v32[(((size_t)b*CC + (go - 32))*PP + p) >> 1] = bf16x2pack(v1, v0);
        }
    }
}

// ---------------- K2: flash attention, transposed + double-buffered ----------
#define KT 20     // kkT row stride (u32)
#define QT 136    // qqT row stride (u32)
#define VS 68     // vv row stride (u32)

struct SmemB {
    unsigned kkT[64*KT];        // K^T tile tf32 [j][o]
    unsigned qqT[2][16*QT];     // Q tile raw fp32 [o][p], double-buffered
    unsigned vv[2][64*VS];      // V tile bf16x2 [c][pu], double-buffered
    float red_m[2][64];
    float red_l[2][64];
    float merge[4][32][32];
    float wsum[4][64];
    float wmax[4][64];
};

extern __shared__ char smem_raw[];

__device__ __forceinline__ void stage_qv(SmemB& sm, int buf, int b, int p0, int tid)
{
    // Q: 16 x 128 fp32 = 512 float4, 2 per thread
#pragma unroll
    for (int u = 0; u < 2; u++) {
        int fidx = tid + u*256;
        int o = fidx >> 5, p4 = fidx & 31;
        cp16(&sm.qqT[buf][o*QT + p4*4],
             g_q + ((size_t)b*CI + o)*PP + p0 + p4*4);
    }
    // V: 64 x 64 u32 = 1024 uint4, 4 per thread
    const unsigned* vbase = g_v32 + ((size_t)b*CC*PP >> 1) + (p0 >> 1);
#pragma unroll
    for (int rr = 0; rr < 4; rr++) {
        int fidx = rr*256 + tid;
        int row = fidx >> 4, c4 = fidx & 15;
        cp16(&sm.vv[buf][row*VS + c4*4],
             vbase + (size_t)row*(PP/2) + c4*4);
    }
}

// grid (PP/NCOL, BB), 256 threads (8 warps): warp = (jb = w&3, ph = w>>2)
__global__ void __launch_bounds__(256, 2)
attn_kernel(const float* __restrict__ ftr, const float* __restrict__ delta)
{
    SmemB& sm = *reinterpret_cast<SmemB*>(smem_raw);
    int tid  = threadIdx.x;
    int w    = tid >> 5;
    int lane = tid & 31;
    int r    = lane >> 2;
    int q4   = lane & 3;
    int b    = blockIdx.y;
    int col0 = blockIdx.x * NCOL;

    int jb = w & 3;
    int ph = w >> 2;
    int j0 = jb*16 + r;
    int j1 = j0 + 8;

    // kick off tile-0 staging
    stage_qv(sm, 0, b, 0, tid);
    asm volatile("cp.async.commit_group;");

    // stage K^T tile (once), tf32
    for (int i = tid; i < 16*64; i += 256) {
        int o = i >> 6, jj = i & 63;
        sm.kkT[jj*KT + o] = tf32cvt(g_k[((size_t)(b*CI + o))*PP + col0 + jj]);
    }
    __syncthreads();

    unsigned ka[2][4];
#pragma unroll
    for (int ks = 0; ks < 2; ks++) {
        ka[ks][0] = sm.kkT[(jb*16 + r    )*KT + ks*8 + q4];
        ka[ks][1] = sm.kkT[(jb*16 + r + 8)*KT + ks*8 + q4];
        ka[ks][2] = sm.kkT[(jb*16 + r    )*KT + ks*8 + q4 + 4];
        ka[ks][3] = sm.kkT[(jb*16 + r + 8)*KT + ks*8 + q4 + 4];
    }

    // per-thread online-softmax state for columns j0, j1
    float m0 = -INFINITY, m1 = -INFINITY;
    float l0 = 0.0f, l1 = 0.0f;
    float sc0 = 0.0f, sc1 = 0.0f;

    float cacc[8][4];
#pragma unroll
    for (int nb = 0; nb < 8; nb++)
#pragma unroll
        for (int k2 = 0; k2 < 4; k2++) cacc[nb][k2] = 0.0f;

    for (int t = 0; t < NT; t++) {
        int buf = t & 1;

        // issue next tile's staging, then wait for current
        if (t + 1 < NT) {
            stage_qv(sm, buf ^ 1, b, (t + 1)*TP, tid);
            asm volatile("cp.async.commit_group;");
            asm volatile("cp.async.wait_group 1;");
        } else {
            asm volatile("cp.async.wait_group 0;");
        }
        __syncthreads();   // A: tile-t data visible; prev tile fully consumed

        // fold l from previous tile (red_l still intact)
        if (t > 0) {
            l0 = l0*sc0 + sm.red_l[0][j0] + sm.red_l[1][j0];
            l1 = l1*sc1 + sm.red_l[0][j1] + sm.red_l[1][j1];
        }

        // ---- MMA1 (tf32): S^T[j16 x p64] ----
        float sr[8][4];
#pragma unroll
        for (int nb = 0; nb < 8; nb++) {
            int pbase = ph*64 + nb*8 + r;
            unsigned b00 = sm.qqT[buf][(q4     )*QT + pbase];
            unsigned b01 = sm.qqT[buf][(q4 + 4 )*QT + pbase];
            unsigned b10 = sm.qqT[buf][(8 + q4 )*QT + pbase];
            unsigned b11 = sm.qqT[buf][(12 + q4)*QT + pbase];
            sr[nb][0] = sr[nb][1] = sr[nb][2] = sr[nb][3] = 0.0f;
            mma8(sr[nb], ka[0][0], ka[0][1], ka[0][2], ka[0][3], b00, b01);
            mma8(sr[nb], ka[1][0], ka[1][1], ka[1][2], ka[1][3], b10, b11);
        }

        // ---- per-warp max over p ----
        float mr0 = -INFINITY, mr1 = -INFINITY;
#pragma unroll
        for (int nb = 0; nb < 8; nb++) {
            mr0 = fmaxf(mr0, fmaxf(sr[nb][0], sr[nb][1]));
            mr1 = fmaxf(mr1, fmaxf(sr[nb][2], sr[nb][3]));
        }
        mr0 = fmaxf(mr0, __shfl_xor_sync(0xffffffffu, mr0, 1));
        mr0 = fmaxf(mr0, __shfl_xor_sync(0xffffffffu, mr0, 2));
        mr1 = fmaxf(mr1, __shfl_xor_sync(0xffffffffu, mr1, 1));
        mr1 = fmaxf(mr1, __shfl_xor_sync(0xffffffffu, mr1, 2));
        if (q4 == 0) {
            sm.red_m[ph][j0] = mr0;
            sm.red_m[ph][j1] = mr1;
        }
        __syncthreads();   // B

        // ---- local stats fold (replicated per thread) ----
        float mn0 = fmaxf(m0, fmaxf(sm.red_m[0][j0], sm.red_m[1][j0]));
        float mn1 = fmaxf(m1, fmaxf(sm.red_m[0][j1], sm.red_m[1][j1]));
        sc0 = __expf(m0 - mn0);  m0 = mn0;
        sc1 = __expf(m1 - mn1);  m1 = mn1;

#pragma unroll
        for (int nb = 0; nb < 8; nb++) {
            cacc[nb][0] *= sc0; cacc[nb][1] *= sc0;
            cacc[nb][2] *= sc1; cacc[nb][3] *= sc1;
        }
        unsigned ep[8][2];
        float ls0 = 0.0f, ls1 = 0.0f;
#pragma unroll
        for (int nb = 0; nb < 8; nb++) {
            float e0 = __expf(sr[nb][0] - mn0);
            float e1 = __expf(sr[nb][1] - mn0);
            float e2 = __expf(sr[nb][2] - mn1);
            float e3 = __expf(sr[nb][3] - mn1);
            ls0 += e0 + e1;
            ls1 += e2 + e3;
            ep[nb][0] = bf16x2pack(e1, e0);
            ep[nb][1] = bf16x2pack(e3, e2);
        }
        ls0 += __shfl_xor_sync(0xffffffffu, ls0, 1);
        ls0 += __shfl_xor_sync(0xffffffffu, ls0, 2);
        ls1 += __shfl_xor_sync(0xffffffffu, ls1, 1);
        ls1 += __shfl_xor_sync(0xffffffffu, ls1, 2);
        if (q4 == 0) {
            sm.red_l[ph][j0] = ls0;
            sm.red_l[ph][j1] = ls1;
        }

        // ---- MMA2 (bf16): G^T += E^T(regs) * V(smem) ----
#pragma unroll
        for (int kk2 = 0; kk2 < 4; kk2++) {
            int puB = ph*32 + kk2*8;
            unsigned a0 = ep[2*kk2    ][0];
            unsigned a1 = ep[2*kk2    ][1];
            unsigned a2 = ep[2*kk2 + 1][0];
            unsigned a3 = ep[2*kk2 + 1][1];
#pragma unroll
            for (int nb = 0; nb < 8; nb++) {
                unsigned b0 = sm.vv[buf][(nb*8 + r)*VS + puB + q4];
                unsigned b1 = sm.vv[buf][(nb*8 + r)*VS + puB + q4 + 4];
                mma16(cacc[nb], a0, a1, a2, a3, b0, b1);
            }
        }
        __syncthreads();   // C: buf consumed; red_l complete
    }

    // final l fold
    l0 = l0*sc0 + sm.red_l[0][j0] + sm.red_l[1][j0];
    l1 = l1*sc1 + sm.red_l[0][j1] + sm.red_l[1][j1];

    // k-split merge
    if (ph == 1) {
#pragma unroll
        for (int nb = 0; nb < 8; nb++)
#pragma unroll
            for (int k2 = 0; k2 < 4; k2++)
                sm.merge[jb][nb*4 + k2][lane] = cacc[nb][k2];
    }
    __syncthreads();

    if (ph == 0) {
#pragma unroll
        for (int nb = 0; nb < 8; nb++)
#pragma unroll
            for (int k2 = 0; k2 < 4; k2++)
                cacc[nb][k2] += sm.merge[jb][nb*4 + k2][lane];

        float dlt  = delta[0];
        float inv0 = 1.0f / l0;
        float inv1 = 1.0f / l1;
        float ps[8][2], pm[8][2];
#pragma unroll
        for (int nb = 0; nb < 8; nb++) {
            int c0 = nb*8 + q4*2;
            size_t a00 = ((size_t)b*CC + c0)*PP + col0 + j0;
            size_t a01 = a00 + PP;
            size_t a10 = a00 + 8;
            size_t a11 = a01 + 8;
            float o00 = dlt*cacc[nb][0]*inv0 + ftr[a00];
            float o01 = dlt*cacc[nb][1]*inv0 + ftr[a01];
            float o10 = dlt*cacc[nb][2]*inv1 + ftr[a10];
            float o11 = dlt*cacc[nb][3]*inv1 + ftr[a11];
            g_out[a00] = o00; g_out[a01] = o01;
            g_out[a10] = o10; g_out[a11] = o11;
            ps[nb][0] = o00 + o10;  pm[nb][0] = fmaxf(o00, o10);
            ps[nb][1] = o01 + o11;  pm[nb][1] = fmaxf(o01, o11);
        }
#pragma unroll
        for (int nb = 0; nb < 8; nb++)
#pragma unroll
            for (int par = 0; par < 2; par++) {
#pragma unroll
                for (int off = 4; off <= 16; off <<= 1) {
                    ps[nb][par] += __shfl_xor_sync(0xffffffffu, ps[nb][par], off);
                    pm[nb][par] = fmaxf(pm[nb][par],
                                        __shfl_xor_sync(0xffffffffu, pm[nb][par], off));
                }
            }
        if (r == 0) {
#pragma unroll
            for (int nb = 0; nb < 8; nb++) {
                sm.wsum[jb][nb*8 + q4*2    ] = ps[nb][0];
                sm.wsum[jb][nb*8 + q4*2 + 1] = ps[nb][1];
                sm.wmax[jb][nb*8 + q4*2    ] = pm[nb][0];
                sm.wmax[jb][nb*8 + q4*2 + 1] = pm[nb][1];
            }
        }
    }
    __syncthreads();

    if (tid < 64) {
        float s  = sm.wsum[0][tid] + sm.wsum[1][tid] + sm.wsum[2][tid] + sm.wsum[3][tid];
        float mx = fmaxf(fmaxf(sm.wmax[0][tid], sm.wmax[1][tid]),
                         fmaxf(sm.wmax[2][tid], sm.wmax[3][tid]));
        atomicAdd(&g_sum[b*CC + tid], s);
        atomicMax(&g_maxk[b*CC + tid], fkey(mx));
    }
}

// ---------------- K3: apply gate (per-block gate, parallel layers) -----------
__global__ void final_kernel(float* __restrict__ out,
                             const float* __restrict__ w_avg1, const float* __restrict__ w_avg2,
                             const float* __restrict__ w_max1, const float* __restrict__ w_max2)
{
    __shared__ float hh[32];
    __shared__ float gate_s;
    int t = threadIdx.x;
    int blk = blockIdx.x;          // 0..1023; block = quarter channel (1024 floats)
    int b = blk >> 8;
    int c = (blk >> 2) & 63;

    // layer 1: 32 dots of length 64, 8 threads each
    {
        int d = t >> 3, part = t & 7;
        int branch = d >> 4, o = d & 15;
        const float* w1 = branch ? w_max1 : w_avg1;
        float acc = 0.0f;
#pragma unroll
        for (int i = 0; i < 8; i++) {
            int idx = part*8 + i;
            float f = branch ? funkey(g_maxk[b*CC + idx])
                             : g_sum[b*CC + idx] * (1.0f/(float)PP);
            acc += w1[o*64 + idx] * f;
        }
#pragma unroll
        for (int off = 1; off <= 4; off <<= 1)
            acc += __shfl_xor_sync(0xffffffffu, acc, off);
        if (part == 0) hh[d] = fmaxf(acc, 0.0f);
    }
    __syncthreads();
    // layer 2: warp 0, one partial per thread
    if (t < 32) {
        int branch = t >> 4, o = t & 15;
        const float* w2 = branch ? w_max2 : w_avg2;
        float v = w2[c*16 + o] * hh[branch*16 + o];
#pragma unroll
        for (int off = 1; off <= 16; off <<= 1)
            v += __shfl_xor_sync(0xffffffffu, v, off);
        if (t == 0) gate_s = 1.0f / (1.0f + __expf(-v));
    }
    __syncthreads();

    float gv = gate_s;
    int base = blk * 256 + t;      // float4 units
    float4 v0 = reinterpret_cast<const float4*>(g_out)[base];
    v0.x *= gv; v0.y *= gv; v0.z *= gv; v0.w *= gv;
    reinterpret_cast<float4*>(out)[base] = v0;
}

// ---------------- launch ------------------------------------------------------
extern "C" void kernel_launch(void* const* d_in, const int* in_sizes, int n_in,
                              void* d_out, int out_size)
{
    const float* ftr    = (const float*)d_in[0];
    const float* wq     = (const float*)d_in[1];
    const float* bq     = (const float*)d_in[2];
    const float* wk     = (const float*)d_in[3];
    const float* bk     = (const float*)d_in[4];
    const float* wv     = (const float*)d_in[5];
    const float* bv     = (const float*)d_in[6];
    const float* delta  = (const float*)d_in[7];
    const float* w_avg1 = (const float*)d_in[8];
    const float* w_avg2 = (const float*)d_in[9];
    const float* w_max1 = (const float*)d_in[10];
    const float* w_max2 = (const float*)d_in[11];
    float* out = (float*)d_out;

    cudaFuncSetAttribute(attn_kernel, cudaFuncAttributeMaxDynamicSharedMemorySize,
                         (int)sizeof(SmemB));

    qkv_kernel<<<dim3(PP/64, BB), 512>>>(ftr, wq, bq, wk, bk, wv, bv);
    attn_kernel<<<dim3(PP/NCOL, BB), 256, sizeof(SmemB)>>>(ftr, delta);
    final_kernel<<<1024, 256>>>(out, w_avg1, w_avg2, w_max1, w_max2);
}

// round 11
// speedup vs baseline: 5.6413x; 1.0941x over previous
#include <cuda_runtime.h>
#include <cuda_bf16.h>
#include <math.h>

#define BB 4
#define CC 64
#define CI 16
#define PP 4096
#define NCOL 64
#define TP 128
#define NT (PP/TP)
#define LOG2E 1.4426950408889634f

// ---------------- scratch (device globals; no allocations allowed) ----------
__device__ float    g_q[BB*CI*PP];       // [b][o][p]  fp32
__device__ float    g_k[BB*CI*PP];       // [b][o][p]  fp32
__device__ unsigned g_v32[BB*CC*PP/2];   // [b][c][p/2] packed bf16x2
__device__ float    g_out[BB*CC*PP];     // pre-gate output
__device__ float    g_sum[BB*CC];
__device__ unsigned g_maxk[BB*CC];

__device__ __forceinline__ unsigned fkey(float f) {
    unsigned u = __float_as_uint(f);
    return (u & 0x80000000u) ? ~u : (u | 0x80000000u);
}
__device__ __forceinline__ float funkey(unsigned k) {
    unsigned u = (k & 0x80000000u) ? (k & 0x7FFFFFFFu) : ~k;
    return __uint_as_float(u);
}

// ---------------- cvt / mma / cp.async helpers --------------------------------
__device__ __forceinline__ unsigned tf32cvt(float f) {
    unsigned r;
    asm("cvt.rna.tf32.f32 %0, %1;" : "=r"(r) : "f"(f));
    return r;
}
__device__ __forceinline__ unsigned bf16x2pack(float hi, float lo) {
    unsigned r;
    asm("cvt.rn.bf16x2.f32 %0, %1, %2;" : "=r"(r) : "f"(hi), "f"(lo));
    return r;
}
__device__ __forceinline__ float ex2(float x) {
    float y;
    asm("ex2.approx.f32 %0, %1;" : "=f"(y) : "f"(x));
    return y;
}
__device__ __forceinline__ void mma8(float c[4],
                                     unsigned a0, unsigned a1, unsigned a2, unsigned a3,
                                     unsigned b0, unsigned b1)
{
    asm volatile(
        "mma.sync.aligned.m16n8k8.row.col.f32.tf32.tf32.f32 "
        "{%0,%1,%2,%3},{%4,%5,%6,%7},{%8,%9},{%0,%1,%2,%3};"
        : "+f"(c[0]), "+f"(c[1]), "+f"(c[2]), "+f"(c[3])
        : "r"(a0), "r"(a1), "r"(a2), "r"(a3), "r"(b0), "r"(b1));
}
__device__ __forceinline__ void mma16(float c[4],
                                      unsigned a0, unsigned a1, unsigned a2, unsigned a3,
                                      unsigned b0, unsigned b1)
{
    asm volatile(
        "mma.sync.aligned.m16n8k16.row.col.f32.bf16.bf16.f32 "
        "{%0,%1,%2,%3},{%4,%5,%6,%7},{%8,%9},{%0,%1,%2,%3};"
        : "+f"(c[0]), "+f"(c[1]), "+f"(c[2]), "+f"(c[3])
        : "r"(a0), "r"(a1), "r"(a2), "r"(a3), "r"(b0), "r"(b1));
}
__device__ __forceinline__ void cp16(void* dst, const void* src) {
    unsigned ds = (unsigned)__cvta_generic_to_shared(dst);
    asm volatile("cp.async.cg.shared.global [%0], [%1], 16;" :: "r"(ds), "l"(src));
}

// ---------------- K1: q/k/v projections (512 threads) ------------------------
#define WTS 100
__global__ void __launch_bounds__(512)
qkv_kernel(const float* __restrict__ ftr,
           const float* __restrict__ wq, const float* __restrict__ bq,
           const float* __restrict__ wk, const float* __restrict__ bk,
           const float* __restrict__ wv, const float* __restrict__ bv)
{
    __shared__ float wt[64][WTS];
    __shared__ float bs[96];
    __shared__ float xs[64][64];

    int tid = threadIdx.x;
    for (int i = tid; i < 16*64; i += 512) { int o = i >> 6, c = i & 63; wt[c][o]      = wq[i]; }
    for (int i = tid; i < 16*64; i += 512) { int o = i >> 6, c = i & 63; wt[c][16 + o] = wk[i]; }
    for (int i = tid; i < 64*64; i += 512) { int o = i >> 6, c = i & 63; wt[c][32 + o] = wv[i]; }
    if (tid < 16) bs[tid] = bq[tid];
    else if (tid < 32) bs[tid] = bk[tid - 16];
    else if (tid < 96) bs[tid] = bv[tid - 32];
    if (blockIdx.x == 0 && blockIdx.y == 0 && tid < BB*CC) {
        g_sum[tid] = 0.0f;
        g_maxk[tid] = 0u;
    }

    int b  = blockIdx.y;
    int p0 = blockIdx.x * 64;
#pragma unroll
    for (int u = 0; u < 2; u++) {
        int f = tid + u*512;
        int c = f >> 4, s = f & 15;
        *reinterpret_cast<float4*>(&xs[c][s*4]) =
            *reinterpret_cast<const float4*>(ftr + ((size_t)b*CC + c)*PP + p0 + s*4);
    }
    __syncthreads();

    int pl  = tid & 31;
    int grp = tid >> 5;
    float acc[6][2];
#pragma unroll
    for (int i = 0; i < 6; i++) acc[i][0] = acc[i][1] = 0.0f;

#pragma unroll 4
    for (int c = 0; c < 64; c++) {
        float2 xv = *reinterpret_cast<const float2*>(&xs[c][pl*2]);
        float2 w0 = *reinterpret_cast<const float2*>(&wt[c][grp*6]);
        float2 w1 = *reinterpret_cast<const float2*>(&wt[c][grp*6 + 2]);
        float2 w2 = *reinterpret_cast<const float2*>(&wt[c][grp*6 + 4]);
        acc[0][0] = fmaf(w0.x, xv.x, acc[0][0]);  acc[0][1] = fmaf(w0.x, xv.y, acc[0][1]);
        acc[1][0] = fmaf(w0.y, xv.x, acc[1][0]);  acc[1][1] = fmaf(w0.y, xv.y, acc[1][1]);
        acc[2][0] = fmaf(w1.x, xv.x, acc[2][0]);  acc[2][1] = fmaf(w1.x, xv.y, acc[2][1]);
        acc[3][0] = fmaf(w1.y, xv.x, acc[3][0]);  acc[3][1] = fmaf(w1.y, xv.y, acc[3][1]);
        acc[4][0] = fmaf(w2.x, xv.x, acc[4][0]);  acc[4][1] = fmaf(w2.x, xv.y, acc[4][1]);
        acc[5][0] = fmaf(w2.y, xv.x, acc[5][0]);  acc[5][1] = fmaf(w2.y, xv.y, acc[5][1]);
    }

    int p = p0 + pl*2;
#pragma unroll
    for (int o = 0; o < 6; o++) {
        int go = grp*6 + o;
        float bsv = bs[go];
        float v0 = acc[o][0] + bsv;
        float v1 = acc[o][1] + bsv;
        if (go < 16) {
            *reinterpret_cast<float2*>(&g_q[((size_t)b*CI + go)*PP + p]) =
                make_float2(v0, v1);
        } else if (go < 32) {
            *reinterpret_cast<float2*>(&g_k[((size_t)b*CI + (go - 16))*PP + p]) =
                make_float2(v0, v1);
        } else {
            g_v32[(((size_t)b*CC + (go - 32))*PP + p) >> 1] = bf16x2pack(v1, v0);
        }
    }
}

// ---------------- K2: flash attention, split-softmax + triple buffer ---------
#define KT 20     // kkT row stride (u32)
#define QT 136    // qqT row stride (u32)
#define VS 68     // vv row stride (u32)

struct SmemB {
    unsigned kkT[64*KT];        // K^T tile tf32 [j][o], pre-scaled by log2e
    unsigned qqT[3][16*QT];     // Q tile raw fp32 [o][p], triple-buffered
    unsigned vv[3][64*VS];      // V tile bf16x2 [c][pu], triple-buffered
    float merge[4][32][32];
    float msave[64];
    float lsave[64];
    float wsum[4][64];
    float wmax[4][64];
};

extern __shared__ char smem_raw[];

__device__ __forceinline__ void stage_qv(SmemB& sm, int buf, int b, int p0, int tid)
{
#pragma unroll
    for (int u = 0; u < 2; u++) {
        int fidx = tid + u*256;
        int o = fidx >> 5, p4 = fidx & 31;
        cp16(&sm.qqT[buf][o*QT + p4*4],
             g_q + ((size_t)b*CI + o)*PP + p0 + p4*4);
    }
    const unsigned* vbase = g_v32 + ((size_t)b*CC*PP >> 1) + (p0 >> 1);
#pragma unroll
    for (int rr = 0; rr < 4; rr++) {
        int fidx = rr*256 + tid;
        int row = fidx >> 4, c4 = fidx & 15;
        cp16(&sm.vv[buf][row*VS + c4*4],
             vbase + (size_t)row*(PP/2) + c4*4);
    }
}

// grid (PP/NCOL, BB), 256 threads (8 warps): warp = (jb = w&3, ph = w>>2)
__global__ void __launch_bounds__(256, 2)
attn_kernel(const float* __restrict__ ftr, const float* __restrict__ delta)
{
    SmemB& sm = *reinterpret_cast<SmemB*>(smem_raw);
    int tid  = threadIdx.x;
    int w    = tid >> 5;
    int lane = tid & 31;
    int r    = lane >> 2;
    int q4   = lane & 3;
    int b    = blockIdx.y;
    int col0 = blockIdx.x * NCOL;

    int jb = w & 3;
    int ph = w >> 2;
    int j0 = jb*16 + r;
    int j1 = j0 + 8;

    // kick off tiles 0 and 1
    stage_qv(sm, 0, b, 0, tid);
    asm volatile("cp.async.commit_group;");
    stage_qv(sm, 1, b, TP, tid);
    asm volatile("cp.async.commit_group;");

    // stage K^T tile (once), tf32, pre-scaled by log2e (scores in log2 domain)
    for (int i = tid; i < 16*64; i += 256) {
        int o = i >> 6, jj = i & 63;
        sm.kkT[jj*KT + o] = tf32cvt(g_k[((size_t)(b*CI + o))*PP + col0 + jj] * LOG2E);
    }
    __syncthreads();

    unsigned ka[2][4];
#pragma unroll
    for (int ks = 0; ks < 2; ks++) {
        ka[ks][0] = sm.kkT[(jb*16 + r    )*KT + ks*8 + q4];
        ka[ks][1] = sm.kkT[(jb*16 + r + 8)*KT + ks*8 + q4];
        ka[ks][2] = sm.kkT[(jb*16 + r    )*KT + ks*8 + q4 + 4];
        ka[ks][3] = sm.kkT[(jb*16 + r + 8)*KT + ks*8 + q4 + 4];
    }

    // warp-local online softmax state (this warp's p-half only), log2 domain
    float m0 = -INFINITY, m1 = -INFINITY;
    float l0 = 0.0f, l1 = 0.0f;

    float cacc[8][4];
#pragma unroll
    for (int nb = 0; nb < 8; nb++)
#pragma unroll
        for (int k2 = 0; k2 < 4; k2++) cacc[nb][k2] = 0.0f;

    for (int t = 0; t < NT; t++) {
        if (t + 1 < NT) asm volatile("cp.async.wait_group 1;");
        else            asm volatile("cp.async.wait_group 0;");
        __syncthreads();   // tile t visible everywhere; compute t-1 done everywhere

        if (t + 2 < NT) {
            stage_qv(sm, (t + 2) % 3, b, (t + 2)*TP, tid);
            asm volatile("cp.async.commit_group;");
        }
        int buf = t % 3;

        // ---- MMA1 (tf32): S^T[j16 x p64], log2 domain ----
        float sr[8][4];
#pragma unroll
        for (int nb = 0; nb < 8; nb++) {
            int pbase = ph*64 + nb*8 + r;
            unsigned b00 = sm.qqT[buf][(q4     )*QT + pbase];
            unsigned b01 = sm.qqT[buf][(q4 + 4 )*QT + pbase];
            unsigned b10 = sm.qqT[buf][(8 + q4 )*QT + pbase];
            unsigned b11 = sm.qqT[buf][(12 + q4)*QT + pbase];
            sr[nb][0] = sr[nb][1] = sr[nb][2] = sr[nb][3] = 0.0f;
            mma8(sr[nb], ka[0][0], ka[0][1], ka[0][2], ka[0][3], b00, b01);
            mma8(sr[nb], ka[1][0], ka[1][1], ka[1][2], ka[1][3], b10, b11);
        }

        // ---- warp-local max over this p-half ----
        float mr0 = -INFINITY, mr1 = -INFINITY;
#pragma unroll
        for (int nb = 0; nb < 8; nb++) {
            mr0 = fmaxf(mr0, fmaxf(sr[nb][0], sr[nb][1]));
            mr1 = fmaxf(mr1, fmaxf(sr[nb][2], sr[nb][3]));
        }
        mr0 = fmaxf(mr0, __shfl_xor_sync(0xffffffffu, mr0, 1));
        mr0 = fmaxf(mr0, __shfl_xor_sync(0xffffffffu, mr0, 2));
        mr1 = fmaxf(mr1, __shfl_xor_sync(0xffffffffu, mr1, 1));
        mr1 = fmaxf(mr1, __shfl_xor_sync(0xffffffffu, mr1, 2));

        float mn0 = fmaxf(m0, mr0);
        float mn1 = fmaxf(m1, mr1);
        float sc0 = ex2(m0 - mn0);  m0 = mn0;
        float sc1 = ex2(m1 - mn1);  m1 = mn1;

#pragma unroll
        for (int nb = 0; nb < 8; nb++) {
            cacc[nb][0] *= sc0; cacc[nb][1] *= sc0;
            cacc[nb][2] *= sc1; cacc[nb][3] *= sc1;
        }
        unsigned ep[8][2];
        float ls0 = 0.0f, ls1 = 0.0f;
#pragma unroll
        for (int nb = 0; nb < 8; nb++) {
            float e0 = ex2(sr[nb][0] - mn0);
            float e1 = ex2(sr[nb][1] - mn0);
            float e2 = ex2(sr[nb][2] - mn1);
            float e3 = ex2(sr[nb][3] - mn1);
            ls0 += e0 + e1;
            ls1 += e2 + e3;
            ep[nb][0] = bf16x2pack(e1, e0);
            ep[nb][1] = bf16x2pack(e3, e2);
        }
        ls0 += __shfl_xor_sync(0xffffffffu, ls0, 1);
        ls0 += __shfl_xor_sync(0xffffffffu, ls0, 2);
        ls1 += __shfl_xor_sync(0xffffffffu, ls1, 1);
        ls1 += __shfl_xor_sync(0xffffffffu, ls1, 2);
        l0 = l0*sc0 + ls0;
        l1 = l1*sc1 + ls1;

        // ---- MMA2 (bf16): G^T += E^T(regs) * V(smem) ----
#pragma unroll
        for (int kk2 = 0; kk2 < 4; kk2++) {
            int puB = ph*32 + kk2*8;
            unsigned a0 = ep[2*kk2    ][0];
            unsigned a1 = ep[2*kk2    ][1];
            unsigned a2 = ep[2*kk2 + 1][0];
            unsigned a3 = ep[2*kk2 + 1][1];
#pragma unroll
            for (int nb = 0; nb < 8; nb++) {
                unsigned b0 = sm.vv[buf][(nb*8 + r)*VS + puB + q4];
                unsigned b1 = sm.vv[buf][(nb*8 + r)*VS + puB + q4 + 4];
                mma16(cacc[nb], a0, a1, a2, a3, b0, b1);
            }
        }
        // no trailing barrier: next iteration's top barrier covers WAR on buffers
    }

    // ---- merge the two p-half softmaxes ----
    if (ph == 1) {
#pragma unroll
        for (int nb = 0; nb < 8; nb++)
#pragma unroll
            for (int k2 = 0; k2 < 4; k2++)
                sm.merge[jb][nb*4 + k2][lane] = cacc[nb][k2];
        if (q4 == 0) {
            sm.msave[j0] = m0;  sm.lsave[j0] = l0;
            sm.msave[j1] = m1;  sm.lsave[j1] = l1;
        }
    }
    __syncthreads();

    if (ph == 0) {
        float mo0 = sm.msave[j0], mo1 = sm.msave[j1];
        float mm0 = fmaxf(m0, mo0), mm1 = fmaxf(m1, mo1);
        float a0 = ex2(m0 - mm0), b0s = ex2(mo0 - mm0);
        float a1 = ex2(m1 - mm1), b1s = ex2(mo1 - mm1);
        float lf0 = l0*a0 + sm.lsave[j0]*b0s;
        float lf1 = l1*a1 + sm.lsave[j1]*b1s;
#pragma unroll
        for (int nb = 0; nb < 8; nb++) {
            cacc[nb][0] = cacc[nb][0]*a0 + sm.merge[jb][nb*4 + 0][lane]*b0s;
            cacc[nb][1] = cacc[nb][1]*a0 + sm.merge[jb][nb*4 + 1][lane]*b0s;
            cacc[nb][2] = cacc[nb][2]*a1 + sm.merge[jb][nb*4 + 2][lane]*b1s;
            cacc[nb][3] = cacc[nb][3]*a1 + sm.merge[jb][nb*4 + 3][lane]*b1s;
        }

        float dlt  = delta[0];
        float inv0 = 1.0f / lf0;
        float inv1 = 1.0f / lf1;
        float ps[8][2], pm[8][2];
#pragma unroll
        for (int nb = 0; nb < 8; nb++) {
            int c0 = nb*8 + q4*2;
            size_t a00 = ((size_t)b*CC + c0)*PP + col0 + j0;
            size_t a01 = a00 + PP;
            size_t a10 = a00 + 8;
            size_t a11 = a01 + 8;
            float o00 = dlt*cacc[nb][0]*inv0 + ftr[a00];
            float o01 = dlt*cacc[nb][1]*inv0 + ftr[a01];
            float o10 = dlt*cacc[nb][2]*inv1 + ftr[a10];
            float o11 = dlt*cacc[nb][3]*inv1 + ftr[a11];
            g_out[a00] = o00; g_out[a01] = o01;
            g_out[a10] = o10; g_out[a11] = o11;
            ps[nb][0] = o00 + o10;  pm[nb][0] = fmaxf(o00, o10);
            ps[nb][1] = o01 + o11;  pm[nb][1] = fmaxf(o01, o11);
        }
#pragma unroll
        for (int nb = 0; nb < 8; nb++)
#pragma unroll
            for (int par = 0; par < 2; par++) {
#pragma unroll
                for (int off = 4; off <= 16; off <<= 1) {
                    ps[nb][par] += __shfl_xor_sync(0xffffffffu, ps[nb][par], off);
                    pm[nb][par] = fmaxf(pm[nb][par],
                                        __shfl_xor_sync(0xffffffffu, pm[nb][par], off));
                }
            }
        if (r == 0) {
#pragma unroll
            for (int nb = 0; nb < 8; nb++) {
                sm.wsum[jb][nb*8 + q4*2    ] = ps[nb][0];
                sm.wsum[jb][nb*8 + q4*2 + 1] = ps[nb][1];
                sm.wmax[jb][nb*8 + q4*2    ] = pm[nb][0];
                sm.wmax[jb][nb*8 + q4*2 + 1] = pm[nb][1];
            }
        }
    }
    __syncthreads();

    if (tid < 64) {
        float s  = sm.wsum[0][tid] + sm.wsum[1][tid] + sm.wsum[2][tid] + sm.wsum[3][tid];
        float mx = fmaxf(fmaxf(sm.wmax[0][tid], sm.wmax[1][tid]),
                         fmaxf(sm.wmax[2][tid], sm.wmax[3][tid]));
        atomicAdd(&g_sum[b*CC + tid], s);
        atomicMax(&g_maxk[b*CC + tid], fkey(mx));
    }
}

// ---------------- K3: apply gate (per-block gate, parallel layers) -----------
__global__ void final_kernel(float* __restrict__ out,
                             const float* __restrict__ w_avg1, const float* __restrict__ w_avg2,
                             const float* __restrict__ w_max1, const float* __restrict__ w_max2)
{
    __shared__ float hh[32];
    __shared__ float gate_s;
    int t = threadIdx.x;
    int blk = blockIdx.x;
    int b = blk >> 8;
    int c = (blk >> 2) & 63;

    {
        int d = t >> 3, part = t & 7;
        int branch = d >> 4, o = d & 15;
        const float* w1 = branch ? w_max1 : w_avg1;
        float acc = 0.0f;
#pragma unroll
        for (int i = 0; i < 8; i++) {
            int idx = part*8 + i;
            float f = branch ? funkey(g_maxk[b*CC + idx])
                             : g_sum[b*CC + idx] * (1.0f/(float)PP);
            acc += w1[o*64 + idx] * f;
        }
#pragma unroll
        for (int off = 1; off <= 4; off <<= 1)
            acc += __shfl_xor_sync(0xffffffffu, acc, off);
        if (part == 0) hh[d] = fmaxf(acc, 0.0f);
    }
    __syncthreads();
    if (t < 32) {
        int branch = t >> 4, o = t & 15;
        const float* w2 = branch ? w_max2 : w_avg2;
        float v = w2[c*16 + o] * hh[branch*16 + o];
#pragma unroll
        for (int off = 1; off <= 16; off <<= 1)
            v += __shfl_xor_sync(0xffffffffu, v, off);
        if (t == 0) gate_s = 1.0f / (1.0f + __expf(-v));
    }
    __syncthreads();

    float gv = gate_s;
    int base = blk * 256 + t;
    float4 v0 = reinterpret_cast<const float4*>(g_out)[base];
    v0.x *= gv; v0.y *= gv; v0.z *= gv; v0.w *= gv;
    reinterpret_cast<float4*>(out)[base] = v0;
}

// ---------------- launch ------------------------------------------------------
extern "C" void kernel_launch(void* const* d_in, const int* in_sizes, int n_in,
                              void* d_out, int out_size)
{
    const float* ftr    = (const float*)d_in[0];
    const float* wq     = (const float*)d_in[1];
    const float* bq     = (const float*)d_in[2];
    const float* wk     = (const float*)d_in[3];
    const float* bk     = (const float*)d_in[4];
    const float* wv     = (const float*)d_in[5];
    const float* bv     = (const float*)d_in[6];
    const float* delta  = (const float*)d_in[7];
    const float* w_avg1 = (const float*)d_in[8];
    const float* w_avg2 = (const float*)d_in[9];
    const float* w_max1 = (const float*)d_in[10];
    const float* w_max2 = (const float*)d_in[11];
    float* out = (float*)d_out;

    cudaFuncSetAttribute(attn_kernel, cudaFuncAttributeMaxDynamicSharedMemorySize,
                         (int)sizeof(SmemB));

    qkv_kernel<<<dim3(PP/64, BB), 512>>>(ftr, wq, bq, wk, bk, wv, bv);
    attn_kernel<<<dim3(PP/NCOL, BB), 256, sizeof(SmemB)>>>(ftr, delta);
    final_kernel<<<1024, 256>>>(out, w_avg1, w_avg2, w_max1, w_max2);
}

// round 12
// speedup vs baseline: 6.5932x; 1.1687x over previous
#include <cuda_runtime.h>
#include <cuda_bf16.h>
#include <math.h>

#define BB 4
#define CC 64
#define CI 16
#define PP 4096
#define NCOL 64
#define TP 128
#define NT (PP/TP)
#define LOG2E 1.4426950408889634f

// ---------------- scratch (device globals; no allocations allowed) ----------
__device__ float    g_q[BB*CI*PP];       // [b][o][p]  fp32
__device__ float    g_k[BB*CI*PP];       // [b][o][p]  fp32
__device__ unsigned g_v32[BB*CC*PP/2];   // [b][c][p/2] packed bf16x2
__device__ float    g_out[BB*CC*PP];     // pre-gate output
__device__ float    g_sum[BB*CC];
__device__ unsigned g_maxk[BB*CC];

__device__ __forceinline__ unsigned fkey(float f) {
    unsigned u = __float_as_uint(f);
    return (u & 0x80000000u) ? ~u : (u | 0x80000000u);
}
__device__ __forceinline__ float funkey(unsigned k) {
    unsigned u = (k & 0x80000000u) ? (k & 0x7FFFFFFFu) : ~k;
    return __uint_as_float(u);
}

// ---------------- cvt / mma / cp.async helpers --------------------------------
__device__ __forceinline__ unsigned tf32cvt(float f) {
    unsigned r;
    asm("cvt.rna.tf32.f32 %0, %1;" : "=r"(r) : "f"(f));
    return r;
}
__device__ __forceinline__ unsigned bf16x2pack(float hi, float lo) {
    unsigned r;
    asm("cvt.rn.bf16x2.f32 %0, %1, %2;" : "=r"(r) : "f"(hi), "f"(lo));
    return r;
}
__device__ __forceinline__ float ex2(float x) {
    float y;
    asm("ex2.approx.f32 %0, %1;" : "=f"(y) : "f"(x));
    return y;
}
__device__ __forceinline__ void mma8(float c[4],
                                     unsigned a0, unsigned a1, unsigned a2, unsigned a3,
                                     unsigned b0, unsigned b1)
{
    asm volatile(
        "mma.sync.aligned.m16n8k8.row.col.f32.tf32.tf32.f32 "
        "{%0,%1,%2,%3},{%4,%5,%6,%7},{%8,%9},{%0,%1,%2,%3};"
        : "+f"(c[0]), "+f"(c[1]), "+f"(c[2]), "+f"(c[3])
        : "r"(a0), "r"(a1), "r"(a2), "r"(a3), "r"(b0), "r"(b1));
}
__device__ __forceinline__ void mma16(float c[4],
                                      unsigned a0, unsigned a1, unsigned a2, unsigned a3,
                                      unsigned b0, unsigned b1)
{
    asm volatile(
        "mma.sync.aligned.m16n8k16.row.col.f32.bf16.bf16.f32 "
        "{%0,%1,%2,%3},{%4,%5,%6,%7},{%8,%9},{%0,%1,%2,%3};"
        : "+f"(c[0]), "+f"(c[1]), "+f"(c[2]), "+f"(c[3])
        : "r"(a0), "r"(a1), "r"(a2), "r"(a3), "r"(b0), "r"(b1));
}
__device__ __forceinline__ void cp16(void* dst, const void* src) {
    unsigned ds = (unsigned)__cvta_generic_to_shared(dst);
    asm volatile("cp.async.cg.shared.global [%0], [%1], 16;" :: "r"(ds), "l"(src));
}

// ---------------- K1: q/k/v projections on tensor cores (tf32) ---------------
// grid (PP/64, BB), 256 threads. C[96(m) x 64(n=p)] = W[96x64] * X[64x64(p)]
// m-blocks of 16: warp 0 -> q rows, warp 1 -> k rows, warps 2-5 -> v rows.
#define WS 68     // W smem row stride (floats): lane addr r*4+q4 conflict-free
#define XS 72     // X smem row stride: lane addr q4*8+r conflict-free
__global__ void __launch_bounds__(256)
qkv_kernel(const float* __restrict__ ftr,
           const float* __restrict__ wq, const float* __restrict__ bq,
           const float* __restrict__ wk, const float* __restrict__ bk,
           const float* __restrict__ wv, const float* __restrict__ bv)
{
    __shared__ float wt[96*WS];    // W tf32 [row][c]
    __shared__ float xs[64*XS];    // X tf32 [c][p_local]
    __shared__ float bs[96];

    int tid = threadIdx.x;
    for (int i = tid; i < 16*64; i += 256)
        wt[(i >> 6)*WS + (i & 63)]        = __uint_as_float(tf32cvt(wq[i]));
    for (int i = tid; i < 16*64; i += 256)
        wt[(16 + (i >> 6))*WS + (i & 63)] = __uint_as_float(tf32cvt(wk[i]));
    for (int i = tid; i < 64*64; i += 256)
        wt[(32 + (i >> 6))*WS + (i & 63)] = __uint_as_float(tf32cvt(wv[i]));
    if (tid < 16) bs[tid] = bq[tid];
    else if (tid < 32) bs[tid] = bk[tid - 16];
    else if (tid < 96) bs[tid] = bv[tid - 32];
    if (blockIdx.x == 0 && blockIdx.y == 0 && tid < BB*CC) {
        g_sum[tid] = 0.0f;
        g_maxk[tid] = 0u;
    }

    int b  = blockIdx.y;
    int p0 = blockIdx.x * 64;
    // stage X: 64 rows x 64 floats = 1024 float4, 4 per thread, tf32-converted
#pragma unroll
    for (int u = 0; u < 4; u++) {
        int f = tid + u*256;
        int c = f >> 4, s = f & 15;
        float4 xv = *reinterpret_cast<const float4*>(ftr + ((size_t)b*CC + c)*PP + p0 + s*4);
        xs[c*XS + s*4    ] = __uint_as_float(tf32cvt(xv.x));
        xs[c*XS + s*4 + 1] = __uint_as_float(tf32cvt(xv.y));
        xs[c*XS + s*4 + 2] = __uint_as_float(tf32cvt(xv.z));
        xs[c*XS + s*4 + 3] = __uint_as_float(tf32cvt(xv.w));
    }
    __syncthreads();

    int w = tid >> 5;
    if (w >= 6) return;                     // staging-only warps
    int lane = tid & 31, r = lane >> 2, q4 = lane & 3;
    int m0 = w * 16;

    // resident A-frags: W rows [m0, m0+16), k = 64 in 8 steps
    unsigned a[8][4];
#pragma unroll
    for (int ks = 0; ks < 8; ks++) {
        a[ks][0] = __float_as_uint(wt[(m0 + r    )*WS + ks*8 + q4]);
        a[ks][1] = __float_as_uint(wt[(m0 + r + 8)*WS + ks*8 + q4]);
        a[ks][2] = __float_as_uint(wt[(m0 + r    )*WS + ks*8 + q4 + 4]);
        a[ks][3] = __float_as_uint(wt[(m0 + r + 8)*WS + ks*8 + q4 + 4]);
    }

    float c8[8][4];
#pragma unroll
    for (int nb = 0; nb < 8; nb++)
#pragma unroll
        for (int k2 = 0; k2 < 4; k2++) c8[nb][k2] = 0.0f;

#pragma unroll
    for (int ks = 0; ks < 8; ks++)
#pragma unroll
        for (int nb = 0; nb < 8; nb++) {
            unsigned b0 = __float_as_uint(xs[(ks*8 + q4    )*XS + nb*8 + r]);
            unsigned b1 = __float_as_uint(xs[(ks*8 + q4 + 4)*XS + nb*8 + r]);
            mma8(c8[nb], a[ks][0], a[ks][1], a[ks][2], a[ks][3], b0, b1);
        }

    float bias0 = bs[m0 + r], bias1 = bs[m0 + r + 8];
#pragma unroll
    for (int nb = 0; nb < 8; nb++) {
        int col = p0 + nb*8 + q4*2;
        int row0 = m0 + r, row1 = m0 + r + 8;
        float v00 = c8[nb][0] + bias0, v01 = c8[nb][1] + bias0;
        float v10 = c8[nb][2] + bias1, v11 = c8[nb][3] + bias1;
        if (row0 < 16) {
            *reinterpret_cast<float2*>(&g_q[((size_t)b*CI + row0)*PP + col]) = make_float2(v00, v01);
            *reinterpret_cast<float2*>(&g_q[((size_t)b*CI + row1)*PP + col]) = make_float2(v10, v11);
        } else if (row0 < 32) {
            *reinterpret_cast<float2*>(&g_k[((size_t)b*CI + row0 - 16)*PP + col]) = make_float2(v00, v01);
            *reinterpret_cast<float2*>(&g_k[((size_t)b*CI + row1 - 16)*PP + col]) = make_float2(v10, v11);
        } else {
            g_v32[(((size_t)b*CC + row0 - 32)*PP + col) >> 1] = bf16x2pack(v01, v00);
            g_v32[(((size_t)b*CC + row1 - 32)*PP + col) >> 1] = bf16x2pack(v11, v10);
        }
    }
}

// ---------------- K2: flash attention, no-max softmax ------------------------
#define KT 20     // kkT row stride (u32)
#define QT 136    // qqT row stride (u32)
#define VS 68     // vv row stride (u32)

struct SmemB {
    unsigned kkT[64*KT];        // K^T tile tf32 [j][o], pre-scaled by log2e
    unsigned qqT[3][16*QT];     // Q tile raw fp32 [o][p], triple-buffered
    unsigned vv[3][64*VS];      // V tile bf16x2 [c][pu], triple-buffered
    float merge[4][32][32];
    float lsave[64];
    float wsum[4][64];
    float wmax[4][64];
};

extern __shared__ char smem_raw[];

__device__ __forceinline__ void stage_qv(SmemB& sm, int buf, int b, int p0, int tid)
{
#pragma unroll
    for (int u = 0; u < 2; u++) {
        int fidx = tid + u*256;
        int o = fidx >> 5, p4 = fidx & 31;
        cp16(&sm.qqT[buf][o*QT + p4*4],
             g_q + ((size_t)b*CI + o)*PP + p0 + p4*4);
    }
    const unsigned* vbase = g_v32 + ((size_t)b*CC*PP >> 1) + (p0 >> 1);
#pragma unroll
    for (int rr = 0; rr < 4; rr++) {
        int fidx = rr*256 + tid;
        int row = fidx >> 4, c4 = fidx & 15;
        cp16(&sm.vv[buf][row*VS + c4*4],
             vbase + (size_t)row*(PP/2) + c4*4);
    }
}

// grid (PP/NCOL, BB), 256 threads (8 warps): warp = (jb = w&3, ph = w>>2)
__global__ void __launch_bounds__(256, 2)
attn_kernel(const float* __restrict__ ftr, const float* __restrict__ delta)
{
    SmemB& sm = *reinterpret_cast<SmemB*>(smem_raw);
    int tid  = threadIdx.x;
    int w    = tid >> 5;
    int lane = tid & 31;
    int r    = lane >> 2;
    int q4   = lane & 3;
    int b    = blockIdx.y;
    int col0 = blockIdx.x * NCOL;

    int jb = w & 3;
    int ph = w >> 2;
    int j0 = jb*16 + r;
    int j1 = j0 + 8;

    stage_qv(sm, 0, b, 0, tid);
    asm volatile("cp.async.commit_group;");
    stage_qv(sm, 1, b, TP, tid);
    asm volatile("cp.async.commit_group;");

    // stage K^T tile (once), tf32, pre-scaled by log2e
    for (int i = tid; i < 16*64; i += 256) {
        int o = i >> 6, jj = i & 63;
        sm.kkT[jj*KT + o] = tf32cvt(g_k[((size_t)(b*CI + o))*PP + col0 + jj] * LOG2E);
    }
    __syncthreads();

    unsigned ka[2][4];
#pragma unroll
    for (int ks = 0; ks < 2; ks++) {
        ka[ks][0] = sm.kkT[(jb*16 + r    )*KT + ks*8 + q4];
        ka[ks][1] = sm.kkT[(jb*16 + r + 8)*KT + ks*8 + q4];
        ka[ks][2] = sm.kkT[(jb*16 + r    )*KT + ks*8 + q4 + 4];
        ka[ks][3] = sm.kkT[(jb*16 + r + 8)*KT + ks*8 + q4 + 4];
    }

    // no-max softmax: plain exp sums (log2 domain), deferred reduction
    float l0 = 0.0f, l1 = 0.0f;

    float cacc[8][4];
#pragma unroll
    for (int nb = 0; nb < 8; nb++)
#pragma unroll
        for (int k2 = 0; k2 < 4; k2++) cacc[nb][k2] = 0.0f;

    for (int t = 0; t < NT; t++) {
        if (t + 1 < NT) asm volatile("cp.async.wait_group 1;");
        else            asm volatile("cp.async.wait_group 0;");
        __syncthreads();

        if (t + 2 < NT) {
            stage_qv(sm, (t + 2) % 3, b, (t + 2)*TP, tid);
            asm volatile("cp.async.commit_group;");
        }
        int buf = t % 3;

        // ---- MMA1 (tf32): S^T[j16 x p64], log2 domain ----
        float sr[8][4];
#pragma unroll
        for (int nb = 0; nb < 8; nb++) {
            int pbase = ph*64 + nb*8 + r;
            unsigned b00 = sm.qqT[buf][(q4     )*QT + pbase];
            unsigned b01 = sm.qqT[buf][(q4 + 4 )*QT + pbase];
            unsigned b10 = sm.qqT[buf][(8 + q4 )*QT + pbase];
            unsigned b11 = sm.qqT[buf][(12 + q4)*QT + pbase];
            sr[nb][0] = sr[nb][1] = sr[nb][2] = sr[nb][3] = 0.0f;
            mma8(sr[nb], ka[0][0], ka[0][1], ka[0][2], ka[0][3], b00, b01);
            mma8(sr[nb], ka[1][0], ka[1][1], ka[1][2], ka[1][3], b10, b11);
        }

        // ---- fused exp + MMA2, one k-chunk at a time (pipe interleave) ----
#pragma unroll
        for (int kk2 = 0; kk2 < 4; kk2++) {
            int nA = 2*kk2, nB = 2*kk2 + 1;
            float eA0 = ex2(fminf(sr[nA][0], 80.0f));
            float eA1 = ex2(fminf(sr[nA][1], 80.0f));
            float eA2 = ex2(fminf(sr[nA][2], 80.0f));
            float eA3 = ex2(fminf(sr[nA][3], 80.0f));
            float eB0 = ex2(fminf(sr[nB][0], 80.0f));
            float eB1 = ex2(fminf(sr[nB][1], 80.0f));
            float eB2 = ex2(fminf(sr[nB][2], 80.0f));
            float eB3 = ex2(fminf(sr[nB][3], 80.0f));
            l0 += (eA0 + eA1) + (eB0 + eB1);
            l1 += (eA2 + eA3) + (eB2 + eB3);
            unsigned a0 = bf16x2pack(eA1, eA0);
            unsigned a1 = bf16x2pack(eA3, eA2);
            unsigned a2 = bf16x2pack(eB1, eB0);
            unsigned a3 = bf16x2pack(eB3, eB2);
            int puB = ph*32 + kk2*8;
#pragma unroll
            for (int nb = 0; nb < 8; nb++) {
                unsigned b0 = sm.vv[buf][(nb*8 + r)*VS + puB + q4];
                unsigned b1 = sm.vv[buf][(nb*8 + r)*VS + puB + q4 + 4];
                mma16(cacc[nb], a0, a1, a2, a3, b0, b1);
            }
        }
        // next iteration's barrier covers WAR on buffers
    }

    // ---- deferred l reduction over q4 lanes ----
    l0 += __shfl_xor_sync(0xffffffffu, l0, 1);
    l0 += __shfl_xor_sync(0xffffffffu, l0, 2);
    l1 += __shfl_xor_sync(0xffffffffu, l1, 1);
    l1 += __shfl_xor_sync(0xffffffffu, l1, 2);

    // ---- merge the two p-halves (plain add) ----
    if (ph == 1) {
#pragma unroll
        for (int nb = 0; nb < 8; nb++)
#pragma unroll
            for (int k2 = 0; k2 < 4; k2++)
                sm.merge[jb][nb*4 + k2][lane] = cacc[nb][k2];
        if (q4 == 0) {
            sm.lsave[j0] = l0;
            sm.lsave[j1] = l1;
        }
    }
    __syncthreads();

    if (ph == 0) {
        float lf0 = l0 + sm.lsave[j0];
        float lf1 = l1 + sm.lsave[j1];
#pragma unroll
        for (int nb = 0; nb < 8; nb++)
#pragma unroll
            for (int k2 = 0; k2 < 4; k2++)
                cacc[nb][k2] += sm.merge[jb][nb*4 + k2][lane];

        float dlt  = delta[0];
        float inv0 = 1.0f / lf0;
        float inv1 = 1.0f / lf1;
        float ps[8][2], pm[8][2];
#pragma unroll
        for (int nb = 0; nb < 8; nb++) {
            int c0 = nb*8 + q4*2;
            size_t a00 = ((size_t)b*CC + c0)*PP + col0 + j0;
            size_t a01 = a00 + PP;
            size_t a10 = a00 + 8;
            size_t a11 = a01 + 8;
            float o00 = dlt*cacc[nb][0]*inv0 + ftr[a00];
            float o01 = dlt*cacc[nb][1]*inv0 + ftr[a01];
            float o10 = dlt*cacc[nb][2]*inv1 + ftr[a10];
            float o11 = dlt*cacc[nb][3]*inv1 + ftr[a11];
            g_out[a00] = o00; g_out[a01] = o01;
            g_out[a10] = o10; g_out[a11] = o11;
            ps[nb][0] = o00 + o10;  pm[nb][0] = fmaxf(o00, o10);
            ps[nb][1] = o01 + o11;  pm[nb][1] = fmaxf(o01, o11);
        }
#pragma unroll
        for (int nb = 0; nb < 8; nb++)
#pragma unroll
            for (int par = 0; par < 2; par++) {
#pragma unroll
                for (int off = 4; off <= 16; off <<= 1) {
                    ps[nb][par] += __shfl_xor_sync(0xffffffffu, ps[nb][par], off);
                    pm[nb][par] = fmaxf(pm[nb][par],
                                        __shfl_xor_sync(0xffffffffu, pm[nb][par], off));
                }
            }
        if (r == 0) {
#pragma unroll
            for (int nb = 0; nb < 8; nb++) {
                sm.wsum[jb][nb*8 + q4*2    ] = ps[nb][0];
                sm.wsum[jb][nb*8 + q4*2 + 1] = ps[nb][1];
                sm.wmax[jb][nb*8 + q4*2    ] = pm[nb][0];
                sm.wmax[jb][nb*8 + q4*2 + 1] = pm[nb][1];
            }
        }
    }
    __syncthreads();

    if (tid < 64) {
        float s  = sm.wsum[0][tid] + sm.wsum[1][tid] + sm.wsum[2][tid] + sm.wsum[3][tid];
        float mx = fmaxf(fmaxf(sm.wmax[0][tid], sm.wmax[1][tid]),
                         fmaxf(sm.wmax[2][tid], sm.wmax[3][tid]));
        atomicAdd(&g_sum[b*CC + tid], s);
        atomicMax(&g_maxk[b*CC + tid], fkey(mx));
    }
}

// ---------------- K3: apply gate (per-block gate, parallel layers) -----------
__global__ void final_kernel(float* __restrict__ out,
                             const float* __restrict__ w_avg1, const float* __restrict__ w_avg2,
                             const float* __restrict__ w_max1, const float* __restrict__ w_max2)
{
    __shared__ float hh[32];
    __shared__ float gate_s;
    int t = threadIdx.x;
    int blk = blockIdx.x;
    int b = blk >> 8;
    int c = (blk >> 2) & 63;

    {
        int d = t >> 3, part = t & 7;
        int branch = d >> 4, o = d & 15;
        const float* w1 = branch ? w_max1 : w_avg1;
        float acc = 0.0f;
#pragma unroll
        for (int i = 0; i < 8; i++) {
            int idx = part*8 + i;
            float f = branch ? funkey(g_maxk[b*CC + idx])
                             : g_sum[b*CC + idx] * (1.0f/(float)PP);
            acc += w1[o*64 + idx] * f;
        }
#pragma unroll
        for (int off = 1; off <= 4; off <<= 1)
            acc += __shfl_xor_sync(0xffffffffu, acc, off);
        if (part == 0) hh[d] = fmaxf(acc, 0.0f);
    }
    __syncthreads();
    if (t < 32) {
        int branch = t >> 4, o = t & 15;
        const float* w2 = branch ? w_max2 : w_avg2;
        float v = w2[c*16 + o] * hh[branch*16 + o];
#pragma unroll
        for (int off = 1; off <= 16; off <<= 1)
            v += __shfl_xor_sync(0xffffffffu, v, off);
        if (t == 0) gate_s = 1.0f / (1.0f + __expf(-v));
    }
    __syncthreads();

    float gv = gate_s;
    int base = blk * 256 + t;
    float4 v0 = reinterpret_cast<const float4*>(g_out)[base];
    v0.x *= gv; v0.y *= gv; v0.z *= gv; v0.w *= gv;
    reinterpret_cast<float4*>(out)[base] = v0;
}

// ---------------- launch ------------------------------------------------------
extern "C" void kernel_launch(void* const* d_in, const int* in_sizes, int n_in,
                              void* d_out, int out_size)
{
    const float* ftr    = (const float*)d_in[0];
    const float* wq     = (const float*)d_in[1];
    const float* bq     = (const float*)d_in[2];
    const float* wk     = (const float*)d_in[3];
    const float* bk     = (const float*)d_in[4];
    const float* wv     = (const float*)d_in[5];
    const float* bv     = (const float*)d_in[6];
    const float* delta  = (const float*)d_in[7];
    const float* w_avg1 = (const float*)d_in[8];
    const float* w_avg2 = (const float*)d_in[9];
    const float* w_max1 = (const float*)d_in[10];
    const float* w_max2 = (const float*)d_in[11];
    float* out = (float*)d_out;

    cudaFuncSetAttribute(attn_kernel, cudaFuncAttributeMaxDynamicSharedMemorySize,
                         (int)sizeof(SmemB));

    qkv_kernel<<<dim3(PP/64, BB), 256>>>(ftr, wq, bq, wk, bk, wv, bv);
    attn_kernel<<<dim3(PP/NCOL, BB), 256, sizeof(SmemB)>>>(ftr, delta);
    final_kernel<<<1024, 256>>>(out, w_avg1, w_avg2, w_max1, w_max2);
}

// round 13
// speedup vs baseline: 7.0146x; 1.0639x over previous
#include <cuda_runtime.h>
#include <cuda_bf16.h>
#include <math.h>

#define BB 4
#define CC 64
#define CI 16
#define PP 4096
#define NCOL 64
#define TP 128
#define NT (PP/TP)
#define LOG2E 1.4426950408889634f

// ---------------- scratch (device globals; no allocations allowed) ----------
__device__ float    g_q[BB*CI*PP];       // [b][o][p]  fp32
__device__ float    g_k[BB*CI*PP];       // [b][o][p]  fp32
__device__ unsigned g_v32[BB*CC*PP/2];   // [b][c][p/2] packed bf16x2
__device__ float    g_out[BB*CC*PP];     // pre-gate output
__device__ float    g_sum[BB*CC];
__device__ unsigned g_maxk[BB*CC];

__device__ __forceinline__ unsigned fkey(float f) {
    unsigned u = __float_as_uint(f);
    return (u & 0x80000000u) ? ~u : (u | 0x80000000u);
}
__device__ __forceinline__ float funkey(unsigned k) {
    unsigned u = (k & 0x80000000u) ? (k & 0x7FFFFFFFu) : ~k;
    return __uint_as_float(u);
}

// ---------------- cvt / mma / cp.async helpers --------------------------------
__device__ __forceinline__ unsigned tf32cvt(float f) {
    unsigned r;
    asm("cvt.rna.tf32.f32 %0, %1;" : "=r"(r) : "f"(f));
    return r;
}
__device__ __forceinline__ unsigned bf16x2pack(float hi, float lo) {
    unsigned r;
    asm("cvt.rn.bf16x2.f32 %0, %1, %2;" : "=r"(r) : "f"(hi), "f"(lo));
    return r;
}
__device__ __forceinline__ float ex2(float x) {
    float y;
    asm("ex2.approx.f32 %0, %1;" : "=f"(y) : "f"(x));
    return y;
}
__device__ __forceinline__ void mma8(float c[4],
                                     unsigned a0, unsigned a1, unsigned a2, unsigned a3,
                                     unsigned b0, unsigned b1)
{
    asm volatile(
        "mma.sync.aligned.m16n8k8.row.col.f32.tf32.tf32.f32 "
        "{%0,%1,%2,%3},{%4,%5,%6,%7},{%8,%9},{%0,%1,%2,%3};"
        : "+f"(c[0]), "+f"(c[1]), "+f"(c[2]), "+f"(c[3])
        : "r"(a0), "r"(a1), "r"(a2), "r"(a3), "r"(b0), "r"(b1));
}
__device__ __forceinline__ void mma16(float c[4],
                                      unsigned a0, unsigned a1, unsigned a2, unsigned a3,
                                      unsigned b0, unsigned b1)
{
    asm volatile(
        "mma.sync.aligned.m16n8k16.row.col.f32.bf16.bf16.f32 "
        "{%0,%1,%2,%3},{%4,%5,%6,%7},{%8,%9},{%0,%1,%2,%3};"
        : "+f"(c[0]), "+f"(c[1]), "+f"(c[2]), "+f"(c[3])
        : "r"(a0), "r"(a1), "r"(a2), "r"(a3), "r"(b0), "r"(b1));
}
__device__ __forceinline__ void cp16(void* dst, const void* src) {
    unsigned ds = (unsigned)__cvta_generic_to_shared(dst);
    asm volatile("cp.async.cg.shared.global [%0], [%1], 16;" :: "r"(ds), "l"(src));
}
__device__ __forceinline__ unsigned sm_u32(const void* p) {
    return (unsigned)__cvta_generic_to_shared(p);
}

// ---------------- K1: q/k/v projections, tensor cores, async staging ---------
// grid (PP/64, BB), 384 threads = 12 warps: mb = w>>1 (m16 block), nh = w&1 (n32 half)
#define WS 68     // W smem row stride (floats)
#define XS 72     // X smem row stride (floats)
__global__ void __launch_bounds__(384)
qkv_kernel(const float* __restrict__ ftr,
           const float* __restrict__ wq, const float* __restrict__ bq,
           const float* __restrict__ wk, const float* __restrict__ bk,
           const float* __restrict__ wv, const float* __restrict__ bv)
{
    __shared__ float wt[96*WS];    // W raw fp32 [row][c] (tf32 by HMMA truncation)
    __shared__ float xs[64*XS];    // X raw fp32 [c][p_local]
    __shared__ float bs[96];

    int tid = threadIdx.x;
    int b   = blockIdx.y;
    int p0  = blockIdx.x * 64;

    // stage W (raw, cp.async): wq 16 rows, wk 16 rows, wv 64 rows (16 float4/row)
    for (int f = tid; f < 256; f += 384) {
        int row = f >> 4, s = f & 15;
        cp16(&wt[row*WS + s*4], wq + row*64 + s*4);
    }
    for (int f = tid; f < 256; f += 384) {
        int row = f >> 4, s = f & 15;
        cp16(&wt[(16 + row)*WS + s*4], wk + row*64 + s*4);
    }
    for (int f = tid; f < 1024; f += 384) {
        int row = f >> 4, s = f & 15;
        cp16(&wt[(32 + row)*WS + s*4], wv + row*64 + s*4);
    }
    // stage X (raw): 64 rows x 16 float4
    for (int f = tid; f < 1024; f += 384) {
        int c = f >> 4, s = f & 15;
        cp16(&xs[c*XS + s*4], ftr + ((size_t)b*CC + c)*PP + p0 + s*4);
    }
    asm volatile("cp.async.commit_group;");

    if (tid < 16) bs[tid] = bq[tid];
    else if (tid < 32) bs[tid] = bk[tid - 16];
    else if (tid < 96) bs[tid] = bv[tid - 32];
    if (blockIdx.x == 0 && blockIdx.y == 0 && tid < BB*CC) {
        g_sum[tid] = 0.0f;
        g_maxk[tid] = 0u;
    }
    asm volatile("cp.async.wait_group 0;");
    __syncthreads();

    int w = tid >> 5;
    int lane = tid & 31, r = lane >> 2, q4 = lane & 3;
    int mb = w >> 1, nh = w & 1;
    int m0 = mb * 16, n0 = nh * 32;

    // resident A-frags: W rows [m0, m0+16), k = 64 in 8 steps
    unsigned a[8][4];
#pragma unroll
    for (int ks = 0; ks < 8; ks++) {
        a[ks][0] = __float_as_uint(wt[(m0 + r    )*WS + ks*8 + q4]);
        a[ks][1] = __float_as_uint(wt[(m0 + r + 8)*WS + ks*8 + q4]);
        a[ks][2] = __float_as_uint(wt[(m0 + r    )*WS + ks*8 + q4 + 4]);
        a[ks][3] = __float_as_uint(wt[(m0 + r + 8)*WS + ks*8 + q4 + 4]);
    }

    float c8[4][4];
#pragma unroll
    for (int nb = 0; nb < 4; nb++)
#pragma unroll
        for (int k2 = 0; k2 < 4; k2++) c8[nb][k2] = 0.0f;

#pragma unroll
    for (int ks = 0; ks < 8; ks++)
#pragma unroll
        for (int nb = 0; nb < 4; nb++) {
            unsigned b0 = __float_as_uint(xs[(ks*8 + q4    )*XS + n0 + nb*8 + r]);
            unsigned b1 = __float_as_uint(xs[(ks*8 + q4 + 4)*XS + n0 + nb*8 + r]);
            mma8(c8[nb], a[ks][0], a[ks][1], a[ks][2], a[ks][3], b0, b1);
        }

    float bias0 = bs[m0 + r], bias1 = bs[m0 + r + 8];
#pragma unroll
    for (int nb = 0; nb < 4; nb++) {
        int col = p0 + n0 + nb*8 + q4*2;
        int row0 = m0 + r, row1 = m0 + r + 8;
        float v00 = c8[nb][0] + bias0, v01 = c8[nb][1] + bias0;
        float v10 = c8[nb][2] + bias1, v11 = c8[nb][3] + bias1;
        if (row0 < 16) {
            *reinterpret_cast<float2*>(&g_q[((size_t)b*CI + row0)*PP + col]) = make_float2(v00, v01);
            *reinterpret_cast<float2*>(&g_q[((size_t)b*CI + row1)*PP + col]) = make_float2(v10, v11);
        } else if (row0 < 32) {
            *reinterpret_cast<float2*>(&g_k[((size_t)b*CI + row0 - 16)*PP + col]) = make_float2(v00, v01);
            *reinterpret_cast<float2*>(&g_k[((size_t)b*CI + row1 - 16)*PP + col]) = make_float2(v10, v11);
        } else {
            g_v32[(((size_t)b*CC + row0 - 32)*PP + col) >> 1] = bf16x2pack(v01, v00);
            g_v32[(((size_t)b*CC + row1 - 32)*PP + col) >> 1] = bf16x2pack(v11, v10);
        }
    }
}

// ---------------- K2: flash attention, no-max softmax + LDSM -----------------
#define KT 20     // kkT row stride (u32)
#define QT 136    // qqT row stride (u32)
#define VS 68     // vv row stride (u32)

struct SmemB {
    unsigned kkT[64*KT];
    unsigned qqT[3][16*QT];
    unsigned vv[3][64*VS];
    float merge[4][32][32];
    float lsave[64];
    float wsum[4][64];
    float wmax[4][64];
};

extern __shared__ char smem_raw[];

__device__ __forceinline__ void stage_qv(SmemB& sm, int buf, int b, int p0, int tid)
{
#pragma unroll
    for (int u = 0; u < 2; u++) {
        int fidx = tid + u*256;
        int o = fidx >> 5, p4 = fidx & 31;
        cp16(&sm.qqT[buf][o*QT + p4*4],
             g_q + ((size_t)b*CI + o)*PP + p0 + p4*4);
    }
    const unsigned* vbase = g_v32 + ((size_t)b*CC*PP >> 1) + (p0 >> 1);
#pragma unroll
    for (int rr = 0; rr < 4; rr++) {
        int fidx = rr*256 + tid;
        int row = fidx >> 4, c4 = fidx & 15;
        cp16(&sm.vv[buf][row*VS + c4*4],
             vbase + (size_t)row*(PP/2) + c4*4);
    }
}

// grid (PP/NCOL, BB), 256 threads (8 warps): warp = (jb = w&3, ph = w>>2)
__global__ void __launch_bounds__(256, 2)
attn_kernel(const float* __restrict__ ftr, const float* __restrict__ delta)
{
    SmemB& sm = *reinterpret_cast<SmemB*>(smem_raw);
    int tid  = threadIdx.x;
    int w    = tid >> 5;
    int lane = tid & 31;
    int r    = lane >> 2;
    int q4   = lane & 3;
    int b    = blockIdx.y;
    int col0 = blockIdx.x * NCOL;

    int jb = w & 3;
    int ph = w >> 2;
    int j0 = jb*16 + r;
    int j1 = j0 + 8;

    stage_qv(sm, 0, b, 0, tid);
    asm volatile("cp.async.commit_group;");
    stage_qv(sm, 1, b, TP, tid);
    asm volatile("cp.async.commit_group;");

    for (int i = tid; i < 16*64; i += 256) {
        int o = i >> 6, jj = i & 63;
        sm.kkT[jj*KT + o] = tf32cvt(g_k[((size_t)(b*CI + o))*PP + col0 + jj] * LOG2E);
    }
    __syncthreads();

    unsigned ka[2][4];
#pragma unroll
    for (int ks = 0; ks < 2; ks++) {
        ka[ks][0] = sm.kkT[(jb*16 + r    )*KT + ks*8 + q4];
        ka[ks][1] = sm.kkT[(jb*16 + r + 8)*KT + ks*8 + q4];
        ka[ks][2] = sm.kkT[(jb*16 + r    )*KT + ks*8 + q4 + 4];
        ka[ks][3] = sm.kkT[(jb*16 + r + 8)*KT + ks*8 + q4 + 4];
    }

    // ldmatrix lane base: row-within-16-group + 16B-half select
    // matrix order per x4: (nb=2j,b0), (nb=2j,b1), (nb=2j+1,b0), (nb=2j+1,b1)
    unsigned vv_lane = sm_u32(&sm.vv[0][0])
        + ((((lane >> 4)*8 + (lane & 7))*VS + ((lane >> 3) & 1)*4) << 2);

    float l0 = 0.0f, l1 = 0.0f;

    float cacc[8][4];
#pragma unroll
    for (int nb = 0; nb < 8; nb++)
#pragma unroll
        for (int k2 = 0; k2 < 4; k2++) cacc[nb][k2] = 0.0f;

    for (int t = 0; t < NT; t++) {
        if (t + 1 < NT) asm volatile("cp.async.wait_group 1;");
        else            asm volatile("cp.async.wait_group 0;");
        __syncthreads();

        if (t + 2 < NT) {
            stage_qv(sm, (t + 2) % 3, b, (t + 2)*TP, tid);
            asm volatile("cp.async.commit_group;");
        }
        int buf = t % 3;
        unsigned vbuf = vv_lane + buf*(64*VS*4);

        // ---- MMA1 (tf32): S^T[j16 x p64], log2 domain ----
        float sr[8][4];
#pragma unroll
        for (int nb = 0; nb < 8; nb++) {
            int pbase = ph*64 + nb*8 + r;
            unsigned b00 = sm.qqT[buf][(q4     )*QT + pbase];
            unsigned b01 = sm.qqT[buf][(q4 + 4 )*QT + pbase];
            unsigned b10 = sm.qqT[buf][(8 + q4 )*QT + pbase];
            unsigned b11 = sm.qqT[buf][(12 + q4)*QT + pbase];
            sr[nb][0] = sr[nb][1] = sr[nb][2] = sr[nb][3] = 0.0f;
            mma8(sr[nb], ka[0][0], ka[0][1], ka[0][2], ka[0][3], b00, b01);
            mma8(sr[nb], ka[1][0], ka[1][1], ka[1][2], ka[1][3], b10, b11);
        }

        // ---- fused exp + MMA2 with ldmatrix B-frags ----
#pragma unroll
        for (int kk2 = 0; kk2 < 4; kk2++) {
            int nA = 2*kk2, nB = 2*kk2 + 1;
            float eA0 = ex2(fminf(sr[nA][0], 80.0f));
            float eA1 = ex2(fminf(sr[nA][1], 80.0f));
            float eA2 = ex2(fminf(sr[nA][2], 80.0f));
            float eA3 = ex2(fminf(sr[nA][3], 80.0f));
            float eB0 = ex2(fminf(sr[nB][0], 80.0f));
            float eB1 = ex2(fminf(sr[nB][1], 80.0f));
            float eB2 = ex2(fminf(sr[nB][2], 80.0f));
            float eB3 = ex2(fminf(sr[nB][3], 80.0f));
            l0 += (eA0 + eA1) + (eB0 + eB1);
            l1 += (eA2 + eA3) + (eB2 + eB3);
            unsigned a0 = bf16x2pack(eA1, eA0);
            unsigned a1 = bf16x2pack(eA3, eA2);
            unsigned a2 = bf16x2pack(eB1, eB0);
            unsigned a3 = bf16x2pack(eB3, eB2);
            unsigned vk = vbuf + ((ph*32 + kk2*8) << 2);
#pragma unroll
            for (int j = 0; j < 4; j++) {
                unsigned bb0, bb1, bb2, bb3;
                asm volatile(
                    "ldmatrix.sync.aligned.m8n8.x4.shared.b16 {%0,%1,%2,%3}, [%4];"
                    : "=r"(bb0), "=r"(bb1), "=r"(bb2), "=r"(bb3)
                    : "r"(vk + (unsigned)(j*16*VS*4)));
                mma16(cacc[2*j    ], a0, a1, a2, a3, bb0, bb1);
                mma16(cacc[2*j + 1], a0, a1, a2, a3, bb2, bb3);
            }
        }
    }

    l0 += __shfl_xor_sync(0xffffffffu, l0, 1);
    l0 += __shfl_xor_sync(0xffffffffu, l0, 2);
    l1 += __shfl_xor_sync(0xffffffffu, l1, 1);
    l1 += __shfl_xor_sync(0xffffffffu, l1, 2);

    if (ph == 1) {
#pragma unroll
        for (int nb = 0; nb < 8; nb++)
#pragma unroll
            for (int k2 = 0; k2 < 4; k2++)
                sm.merge[jb][nb*4 + k2][lane] = cacc[nb][k2];
        if (q4 == 0) {
            sm.lsave[j0] = l0;
            sm.lsave[j1] = l1;
        }
    }
    __syncthreads();

    if (ph == 0) {
        float lf0 = l0 + sm.lsave[j0];
        float lf1 = l1 + sm.lsave[j1];
#pragma unroll
        for (int nb = 0; nb < 8; nb++)
#pragma unroll
            for (int k2 = 0; k2 < 4; k2++)
                cacc[nb][k2] += sm.merge[jb][nb*4 + k2][lane];

        float dlt  = delta[0];
        float inv0 = 1.0f / lf0;
        float inv1 = 1.0f / lf1;
        float ps[8][2], pm[8][2];
#pragma unroll
        for (int nb = 0; nb < 8; nb++) {
            int c0 = nb*8 + q4*2;
            size_t a00 = ((size_t)b*CC + c0)*PP + col0 + j0;
            size_t a01 = a00 + PP;
            size_t a10 = a00 + 8;
            size_t a11 = a01 + 8;
            float o00 = dlt*cacc[nb][0]*inv0 + ftr[a00];
            float o01 = dlt*cacc[nb][1]*inv0 + ftr[a01];
            float o10 = dlt*cacc[nb][2]*inv1 + ftr[a10];
            float o11 = dlt*cacc[nb][3]*inv1 + ftr[a11];
            g_out[a00] = o00; g_out[a01] = o01;
            g_out[a10] = o10; g_out[a11] = o11;
            ps[nb][0] = o00 + o10;  pm[nb][0] = fmaxf(o00, o10);
            ps[nb][1] = o01 + o11;  pm[nb][1] = fmaxf(o01, o11);
        }
#pragma unroll
        for (int nb = 0; nb < 8; nb++)
#pragma unroll
            for (int par = 0; par < 2; par++) {
#pragma unroll
                for (int off = 4; off <= 16; off <<= 1) {
                    ps[nb][par] += __shfl_xor_sync(0xffffffffu, ps[nb][par], off);
                    pm[nb][par] = fmaxf(pm[nb][par],
                                        __shfl_xor_sync(0xffffffffu, pm[nb][par], off));
                }
            }
        if (r == 0) {
#pragma unroll
            for (int nb = 0; nb < 8; nb++) {
                sm.wsum[jb][nb*8 + q4*2    ] = ps[nb][0];
                sm.wsum[jb][nb*8 + q4*2 + 1] = ps[nb][1];
                sm.wmax[jb][nb*8 + q4*2    ] = pm[nb][0];
                sm.wmax[jb][nb*8 + q4*2 + 1] = pm[nb][1];
            }
        }
    }
    __syncthreads();

    if (tid < 64) {
        float s  = sm.wsum[0][tid] + sm.wsum[1][tid] + sm.wsum[2][tid] + sm.wsum[3][tid];
        float mx = fmaxf(fmaxf(sm.wmax[0][tid], sm.wmax[1][tid]),
                         fmaxf(sm.wmax[2][tid], sm.wmax[3][tid]));
        atomicAdd(&g_sum[b*CC + tid], s);
        atomicMax(&g_maxk[b*CC + tid], fkey(mx));
    }
}

// ---------------- K3: apply gate (per-block gate, parallel layers) -----------
__global__ void final_kernel(float* __restrict__ out,
                             const float* __restrict__ w_avg1, const float* __restrict__ w_avg2,
                             const float* __restrict__ w_max1, const float* __restrict__ w_max2)
{
    __shared__ float hh[32];
    __shared__ float gate_s;
    int t = threadIdx.x;
    int blk = blockIdx.x;
    int b = blk >> 8;
    int c = (blk >> 2) & 63;

    {
        int d = t >> 3, part = t & 7;
        int branch = d >> 4, o = d & 15;
        const float* w1 = branch ? w_max1 : w_avg1;
        float acc = 0.0f;
#pragma unroll
        for (int i = 0; i < 8; i++) {
            int idx = part*8 + i;
            float f = branch ? funkey(g_maxk[b*CC + idx])
                             : g_sum[b*CC + idx] * (1.0f/(float)PP);
            acc += w1[o*64 + idx] * f;
        }
#pragma unroll
        for (int off = 1; off <= 4; off <<= 1)
            acc += __shfl_xor_sync(0xffffffffu, acc, off);
        if (part == 0) hh[d] = fmaxf(acc, 0.0f);
    }
    __syncthreads();
    if (t < 32) {
        int branch = t >> 4, o = t & 15;
        const float* w2 = branch ? w_max2 : w_avg2;
        float v = w2[c*16 + o] * hh[branch*16 + o];
#pragma unroll
        for (int off = 1; off <= 16; off <<= 1)
            v += __shfl_xor_sync(0xffffffffu, v, off);
        if (t == 0) gate_s = 1.0f / (1.0f + __expf(-v));
    }
    __syncthreads();

    float gv = gate_s;
    int base = blk * 256 + t;
    float4 v0 = reinterpret_cast<const float4*>(g_out)[base];
    v0.x *= gv; v0.y *= gv; v0.z *= gv; v0.w *= gv;
    reinterpret_cast<float4*>(out)[base] = v0;
}

// ---------------- launch ------------------------------------------------------
extern "C" void kernel_launch(void* const* d_in, const int* in_sizes, int n_in,
                              void* d_out, int out_size)
{
    const float* ftr    = (const float*)d_in[0];
    const float* wq     = (const float*)d_in[1];
    const float* bq     = (const float*)d_in[2];
    const float* wk     = (const float*)d_in[3];
    const float* bk     = (const float*)d_in[4];
    const float* wv     = (const float*)d_in[5];
    const float* bv     = (const float*)d_in[6];
    const float* delta  = (const float*)d_in[7];
    const float* w_avg1 = (const float*)d_in[8];
    const float* w_avg2 = (const float*)d_in[9];
    const float* w_max1 = (const float*)d_in[10];
    const float* w_max2 = (const float*)d_in[11];
    float* out = (float*)d_out;

    cudaFuncSetAttribute(attn_kernel, cudaFuncAttributeMaxDynamicSharedMemorySize,
                         (int)sizeof(SmemB));

    qkv_kernel<<<dim3(PP/64, BB), 384>>>(ftr, wq, bq, wk, bk, wv, bv);
    attn_kernel<<<dim3(PP/NCOL, BB), 256, sizeof(SmemB)>>>(ftr, delta);
    final_kernel<<<1024, 256>>>(out, w_avg1, w_avg2, w_max1, w_max2);
}

// round 14
// speedup vs baseline: 7.4635x; 1.0640x over previous
#include <cuda_runtime.h>
#include <cuda_bf16.h>
#include <math.h>

#define BB 4
#define CC 64
#define CI 16
#define PP 4096
#define NCOL 128
#define TP 128
#define NT (PP/TP)
#define LOG2E 1.4426950408889634f

// ---------------- scratch (device globals; no allocations allowed) ----------
__device__ float    g_q[BB*CI*PP];       // [b][o][p]  fp32
__device__ float    g_k[BB*CI*PP];       // [b][o][p]  fp32
__device__ unsigned g_v32[BB*CC*PP/2];   // [b][c][p/2] packed bf16x2
__device__ float    g_out[BB*CC*PP];     // pre-gate output
__device__ float    g_sum[BB*CC];
__device__ unsigned g_maxk[BB*CC];

__device__ __forceinline__ unsigned fkey(float f) {
    unsigned u = __float_as_uint(f);
    return (u & 0x80000000u) ? ~u : (u | 0x80000000u);
}
__device__ __forceinline__ float funkey(unsigned k) {
    unsigned u = (k & 0x80000000u) ? (k & 0x7FFFFFFFu) : ~k;
    return __uint_as_float(u);
}

// ---------------- cvt / mma / cp.async helpers --------------------------------
__device__ __forceinline__ unsigned tf32cvt(float f) {
    unsigned r;
    asm("cvt.rna.tf32.f32 %0, %1;" : "=r"(r) : "f"(f));
    return r;
}
__device__ __forceinline__ unsigned bf16x2pack(float hi, float lo) {
    unsigned r;
    asm("cvt.rn.bf16x2.f32 %0, %1, %2;" : "=r"(r) : "f"(hi), "f"(lo));
    return r;
}
__device__ __forceinline__ float ex2(float x) {
    float y;
    asm("ex2.approx.f32 %0, %1;" : "=f"(y) : "f"(x));
    return y;
}
__device__ __forceinline__ void mma8(float c[4],
                                     unsigned a0, unsigned a1, unsigned a2, unsigned a3,
                                     unsigned b0, unsigned b1)
{
    asm volatile(
        "mma.sync.aligned.m16n8k8.row.col.f32.tf32.tf32.f32 "
        "{%0,%1,%2,%3},{%4,%5,%6,%7},{%8,%9},{%0,%1,%2,%3};"
        : "+f"(c[0]), "+f"(c[1]), "+f"(c[2]), "+f"(c[3])
        : "r"(a0), "r"(a1), "r"(a2), "r"(a3), "r"(b0), "r"(b1));
}
__device__ __forceinline__ void mma16(float c[4],
                                      unsigned a0, unsigned a1, unsigned a2, unsigned a3,
                                      unsigned b0, unsigned b1)
{
    asm volatile(
        "mma.sync.aligned.m16n8k16.row.col.f32.bf16.bf16.f32 "
        "{%0,%1,%2,%3},{%4,%5,%6,%7},{%8,%9},{%0,%1,%2,%3};"
        : "+f"(c[0]), "+f"(c[1]), "+f"(c[2]), "+f"(c[3])
        : "r"(a0), "r"(a1), "r"(a2), "r"(a3), "r"(b0), "r"(b1));
}
__device__ __forceinline__ void cp16(void* dst, const void* src) {
    unsigned ds = (unsigned)__cvta_generic_to_shared(dst);
    asm volatile("cp.async.cg.shared.global [%0], [%1], 16;" :: "r"(ds), "l"(src));
}
__device__ __forceinline__ unsigned sm_u32(const void* p) {
    return (unsigned)__cvta_generic_to_shared(p);
}

// ---------------- K1: q/k/v projections, tensor cores, async staging ---------
// grid (PP/64, BB), 384 threads = 12 warps: mb = w>>1 (m16 block), nh = w&1 (n32 half)
#define WS 68     // W smem row stride (floats)
#define XS 72     // X smem row stride (floats)
__global__ void __launch_bounds__(384)
qkv_kernel(const float* __restrict__ ftr,
           const float* __restrict__ wq, const float* __restrict__ bq,
           const float* __restrict__ wk, const float* __restrict__ bk,
           const float* __restrict__ wv, const float* __restrict__ bv)
{
    __shared__ float wt[96*WS];    // W raw fp32 [row][c] (tf32 by HMMA truncation)
    __shared__ float xs[64*XS];    // X raw fp32 [c][p_local]
    __shared__ float bs[96];

    int tid = threadIdx.x;
    int b   = blockIdx.y;
    int p0  = blockIdx.x * 64;

    for (int f = tid; f < 256; f += 384) {
        int row = f >> 4, s = f & 15;
        cp16(&wt[row*WS + s*4], wq + row*64 + s*4);
    }
    for (int f = tid; f < 256; f += 384) {
        int row = f >> 4, s = f & 15;
        cp16(&wt[(16 + row)*WS + s*4], wk + row*64 + s*4);
    }
    for (int f = tid; f < 1024; f += 384) {
        int row = f >> 4, s = f & 15;
        cp16(&wt[(32 + row)*WS + s*4], wv + row*64 + s*4);
    }
    for (int f = tid; f < 1024; f += 384) {
        int c = f >> 4, s = f & 15;
        cp16(&xs[c*XS + s*4], ftr + ((size_t)b*CC + c)*PP + p0 + s*4);
    }
    asm volatile("cp.async.commit_group;");

    if (tid < 16) bs[tid] = bq[tid];
    else if (tid < 32) bs[tid] = bk[tid - 16];
    else if (tid < 96) bs[tid] = bv[tid - 32];
    if (blockIdx.x == 0 && blockIdx.y == 0 && tid < BB*CC) {
        g_sum[tid] = 0.0f;
        g_maxk[tid] = 0u;
    }
    asm volatile("cp.async.wait_group 0;");
    __syncthreads();

    int w = tid >> 5;
    int lane = tid & 31, r = lane >> 2, q4 = lane & 3;
    int mb = w >> 1, nh = w & 1;
    int m0 = mb * 16, n0 = nh * 32;

    unsigned a[8][4];
#pragma unroll
    for (int ks = 0; ks < 8; ks++) {
        a[ks][0] = __float_as_uint(wt[(m0 + r    )*WS + ks*8 + q4]);
        a[ks][1] = __float_as_uint(wt[(m0 + r + 8)*WS + ks*8 + q4]);
        a[ks][2] = __float_as_uint(wt[(m0 + r    )*WS + ks*8 + q4 + 4]);
        a[ks][3] = __float_as_uint(wt[(m0 + r + 8)*WS + ks*8 + q4 + 4]);
    }

    float c8[4][4];
#pragma unroll
    for (int nb = 0; nb < 4; nb++)
#pragma unroll
        for (int k2 = 0; k2 < 4; k2++) c8[nb][k2] = 0.0f;

#pragma unroll
    for (int ks = 0; ks < 8; ks++)
#pragma unroll
        for (int nb = 0; nb < 4; nb++) {
            unsigned b0 = __float_as_uint(xs[(ks*8 + q4    )*XS + n0 + nb*8 + r]);
            unsigned b1 = __float_as_uint(xs[(ks*8 + q4 + 4)*XS + n0 + nb*8 + r]);
            mma8(c8[nb], a[ks][0], a[ks][1], a[ks][2], a[ks][3], b0, b1);
        }

    float bias0 = bs[m0 + r], bias1 = bs[m0 + r + 8];
#pragma unroll
    for (int nb = 0; nb < 4; nb++) {
        int col = p0 + n0 + nb*8 + q4*2;
        int row0 = m0 + r, row1 = m0 + r + 8;
        float v00 = c8[nb][0] + bias0, v01 = c8[nb][1] + bias0;
        float v10 = c8[nb][2] + bias1, v11 = c8[nb][3] + bias1;
        if (row0 < 16) {
            *reinterpret_cast<float2*>(&g_q[((size_t)b*CI + row0)*PP + col]) = make_float2(v00, v01);
            *reinterpret_cast<float2*>(&g_q[((size_t)b*CI + row1)*PP + col]) = make_float2(v10, v11);
        } else if (row0 < 32) {
            *reinterpret_cast<float2*>(&g_k[((size_t)b*CI + row0 - 16)*PP + col]) = make_float2(v00, v01);
            *reinterpret_cast<float2*>(&g_k[((size_t)b*CI + row1 - 16)*PP + col]) = make_float2(v10, v11);
        } else {
            g_v32[(((size_t)b*CC + row0 - 32)*PP + col) >> 1] = bf16x2pack(v01, v00);
            g_v32[(((size_t)b*CC + row1 - 32)*PP + col) >> 1] = bf16x2pack(v11, v10);
        }
    }
}

// ---------------- K2: flash attention, 128 columns/CTA -----------------------
#define KT 20     // kkT row stride (u32)
#define QT 136    // qqT row stride (u32)
#define VS 68     // vv row stride (u32)

struct SmemB {
    unsigned kkT[NCOL*KT];      // K^T tile tf32 [j][o], pre-scaled (10 KB)
    unsigned qqT[3][16*QT];     // Q tile raw fp32 [o][p]  (26 KB)
    unsigned vv[3][64*VS];      // V tile bf16x2 [c][pu]   (52 KB)
    float merge[8][32][32];     // (32 KB)
    float lsave[NCOL];
    float wsum[8][64];
    float wmax[8][64];
};

extern __shared__ char smem_raw[];

__device__ __forceinline__ void stage_qv(SmemB& sm, int buf, int b, int p0, int tid)
{
    // Q: 512 float4, 1 per thread
    {
        int o = tid >> 5, p4 = tid & 31;
        cp16(&sm.qqT[buf][o*QT + p4*4],
             g_q + ((size_t)b*CI + o)*PP + p0 + p4*4);
    }
    // V: 1024 uint4, 2 per thread
    const unsigned* vbase = g_v32 + ((size_t)b*CC*PP >> 1) + (p0 >> 1);
#pragma unroll
    for (int rr = 0; rr < 2; rr++) {
        int fidx = rr*512 + tid;
        int row = fidx >> 4, c4 = fidx & 15;
        cp16(&sm.vv[buf][row*VS + c4*4],
             vbase + (size_t)row*(PP/2) + c4*4);
    }
}

// grid (PP/NCOL, BB), 512 threads (16 warps): warp = (jb = w&7, ph = w>>3)
__global__ void __launch_bounds__(512, 1)
attn_kernel(const float* __restrict__ ftr, const float* __restrict__ delta)
{
    SmemB& sm = *reinterpret_cast<SmemB*>(smem_raw);
    int tid  = threadIdx.x;
    int w    = tid >> 5;
    int lane = tid & 31;
    int r    = lane >> 2;
    int q4   = lane & 3;
    int b    = blockIdx.y;
    int col0 = blockIdx.x * NCOL;

    int jb = w & 7;
    int ph = w >> 3;
    int j0 = jb*16 + r;
    int j1 = j0 + 8;

    stage_qv(sm, 0, b, 0, tid);
    asm volatile("cp.async.commit_group;");
    stage_qv(sm, 1, b, TP, tid);
    asm volatile("cp.async.commit_group;");

    // stage K^T tile (once), tf32, pre-scaled by log2e: 128 cols x 16 o
    for (int i = tid; i < 16*NCOL; i += 512) {
        int o = i >> 7, jj = i & 127;
        sm.kkT[jj*KT + o] = tf32cvt(g_k[((size_t)(b*CI + o))*PP + col0 + jj] * LOG2E);
    }
    __syncthreads();

    unsigned ka[2][4];
#pragma unroll
    for (int ks = 0; ks < 2; ks++) {
        ka[ks][0] = sm.kkT[(jb*16 + r    )*KT + ks*8 + q4];
        ka[ks][1] = sm.kkT[(jb*16 + r + 8)*KT + ks*8 + q4];
        ka[ks][2] = sm.kkT[(jb*16 + r    )*KT + ks*8 + q4 + 4];
        ka[ks][3] = sm.kkT[(jb*16 + r + 8)*KT + ks*8 + q4 + 4];
    }

    unsigned vv_lane = sm_u32(&sm.vv[0][0])
        + ((((lane >> 4)*8 + (lane & 7))*VS + ((lane >> 3) & 1)*4) << 2);

    float l0 = 0.0f, l1 = 0.0f;

    float cacc[8][4];
#pragma unroll
    for (int nb = 0; nb < 8; nb++)
#pragma unroll
        for (int k2 = 0; k2 < 4; k2++) cacc[nb][k2] = 0.0f;

    for (int t = 0; t < NT; t++) {
        if (t + 1 < NT) asm volatile("cp.async.wait_group 1;");
        else            asm volatile("cp.async.wait_group 0;");
        __syncthreads();

        if (t + 2 < NT) {
            stage_qv(sm, (t + 2) % 3, b, (t + 2)*TP, tid);
            asm volatile("cp.async.commit_group;");
        }
        int buf = t % 3;
        unsigned vbuf = vv_lane + buf*(64*VS*4);

        // ---- MMA1 (tf32): S^T[j16 x p64], log2 domain ----
        float sr[8][4];
#pragma unroll
        for (int nb = 0; nb < 8; nb++) {
            int pbase = ph*64 + nb*8 + r;
            unsigned b00 = sm.qqT[buf][(q4     )*QT + pbase];
            unsigned b01 = sm.qqT[buf][(q4 + 4 )*QT + pbase];
            unsigned b10 = sm.qqT[buf][(8 + q4 )*QT + pbase];
            unsigned b11 = sm.qqT[buf][(12 + q4)*QT + pbase];
            sr[nb][0] = sr[nb][1] = sr[nb][2] = sr[nb][3] = 0.0f;
            mma8(sr[nb], ka[0][0], ka[0][1], ka[0][2], ka[0][3], b00, b01);
            mma8(sr[nb], ka[1][0], ka[1][1], ka[1][2], ka[1][3], b10, b11);
        }

        // ---- fused exp + MMA2 with ldmatrix B-frags ----
#pragma unroll
        for (int kk2 = 0; kk2 < 4; kk2++) {
            int nA = 2*kk2, nB = 2*kk2 + 1;
            float eA0 = ex2(fminf(sr[nA][0], 80.0f));
            float eA1 = ex2(fminf(sr[nA][1], 80.0f));
            float eA2 = ex2(fminf(sr[nA][2], 80.0f));
            float eA3 = ex2(fminf(sr[nA][3], 80.0f));
            float eB0 = ex2(fminf(sr[nB][0], 80.0f));
            float eB1 = ex2(fminf(sr[nB][1], 80.0f));
            float eB2 = ex2(fminf(sr[nB][2], 80.0f));
            float eB3 = ex2(fminf(sr[nB][3], 80.0f));
            l0 += (eA0 + eA1) + (eB0 + eB1);
            l1 += (eA2 + eA3) + (eB2 + eB3);
            unsigned a0 = bf16x2pack(eA1, eA0);
            unsigned a1 = bf16x2pack(eA3, eA2);
            unsigned a2 = bf16x2pack(eB1, eB0);
            unsigned a3 = bf16x2pack(eB3, eB2);
            unsigned vk = vbuf + ((ph*32 + kk2*8) << 2);
#pragma unroll
            for (int j = 0; j < 4; j++) {
                unsigned bb0, bb1, bb2, bb3;
                asm volatile(
                    "ldmatrix.sync.aligned.m8n8.x4.shared.b16 {%0,%1,%2,%3}, [%4];"
                    : "=r"(bb0), "=r"(bb1), "=r"(bb2), "=r"(bb3)
                    : "r"(vk + (unsigned)(j*16*VS*4)));
                mma16(cacc[2*j    ], a0, a1, a2, a3, bb0, bb1);
                mma16(cacc[2*j + 1], a0, a1, a2, a3, bb2, bb3);
            }
        }
    }

    l0 += __shfl_xor_sync(0xffffffffu, l0, 1);
    l0 += __shfl_xor_sync(0xffffffffu, l0, 2);
    l1 += __shfl_xor_sync(0xffffffffu, l1, 1);
    l1 += __shfl_xor_sync(0xffffffffu, l1, 2);

    // ---- merge the two p-halves (plain add) ----
    if (ph == 1) {
#pragma unroll
        for (int nb = 0; nb < 8; nb++)
#pragma unroll
            for (int k2 = 0; k2 < 4; k2++)
                sm.merge[jb][nb*4 + k2][lane] = cacc[nb][k2];
        if (q4 == 0) {
            sm.lsave[j0] = l0;
            sm.lsave[j1] = l1;
        }
    }
    __syncthreads();

    if (ph == 0) {
        float lf0 = l0 + sm.lsave[j0];
        float lf1 = l1 + sm.lsave[j1];
#pragma unroll
        for (int nb = 0; nb < 8; nb++)
#pragma unroll
            for (int k2 = 0; k2 < 4; k2++)
                cacc[nb][k2] += sm.merge[jb][nb*4 + k2][lane];

        float dlt  = delta[0];
        float inv0 = 1.0f / lf0;
        float inv1 = 1.0f / lf1;
        float ps[8][2], pm[8][2];
#pragma unroll
        for (int nb = 0; nb < 8; nb++) {
            int c0 = nb*8 + q4*2;
            size_t a00 = ((size_t)b*CC + c0)*PP + col0 + j0;
            size_t a01 = a00 + PP;
            size_t a10 = a00 + 8;
            size_t a11 = a01 + 8;
            float o00 = dlt*cacc[nb][0]*inv0 + ftr[a00];
            float o01 = dlt*cacc[nb][1]*inv0 + ftr[a01];
            float o10 = dlt*cacc[nb][2]*inv1 + ftr[a10];
            float o11 = dlt*cacc[nb][3]*inv1 + ftr[a11];
            g_out[a00] = o00; g_out[a01] = o01;
            g_out[a10] = o10; g_out[a11] = o11;
            ps[nb][0] = o00 + o10;  pm[nb][0] = fmaxf(o00, o10);
            ps[nb][1] = o01 + o11;  pm[nb][1] = fmaxf(o01, o11);
        }
#pragma unroll
        for (int nb = 0; nb < 8; nb++)
#pragma unroll
            for (int par = 0; par < 2; par++) {
#pragma unroll
                for (int off = 4; off <= 16; off <<= 1) {
                    ps[nb][par] += __shfl_xor_sync(0xffffffffu, ps[nb][par], off);
                    pm[nb][par] = fmaxf(pm[nb][par],
                                        __shfl_xor_sync(0xffffffffu, pm[nb][par], off));
                }
            }
        if (r == 0) {
#pragma unroll
            for (int nb = 0; nb < 8; nb++) {
                sm.wsum[jb][nb*8 + q4*2    ] = ps[nb][0];
                sm.wsum[jb][nb*8 + q4*2 + 1] = ps[nb][1];
                sm.wmax[jb][nb*8 + q4*2    ] = pm[nb][0];
                sm.wmax[jb][nb*8 + q4*2 + 1] = pm[nb][1];
            }
        }
    }
    __syncthreads();

    if (tid < 64) {
        float s  = 0.0f;
        float mx = -INFINITY;
#pragma unroll
        for (int g = 0; g < 8; g++) {
            s += sm.wsum[g][tid];
            mx = fmaxf(mx, sm.wmax[g][tid]);
        }
        atomicAdd(&g_sum[b*CC + tid], s);
        atomicMax(&g_maxk[b*CC + tid], fkey(mx));
    }
}

// ---------------- K3: apply gate (per-block gate, parallel layers) -----------
__global__ void final_kernel(float* __restrict__ out,
                             const float* __restrict__ w_avg1, const float* __restrict__ w_avg2,
                             const float* __restrict__ w_max1, const float* __restrict__ w_max2)
{
    __shared__ float hh[32];
    __shared__ float gate_s;
    int t = threadIdx.x;
    int blk = blockIdx.x;
    int b = blk >> 8;
    int c = (blk >> 2) & 63;

    {
        int d = t >> 3, part = t & 7;
        int branch = d >> 4, o = d & 15;
        const float* w1 = branch ? w_max1 : w_avg1;
        float acc = 0.0f;
#pragma unroll
        for (int i = 0; i < 8; i++) {
            int idx = part*8 + i;
            float f = branch ? funkey(g_maxk[b*CC + idx])
                             : g_sum[b*CC + idx] * (1.0f/(float)PP);
            acc += w1[o*64 + idx] * f;
        }
#pragma unroll
        for (int off = 1; off <= 4; off <<= 1)
            acc += __shfl_xor_sync(0xffffffffu, acc, off);
        if (part == 0) hh[d] = fmaxf(acc, 0.0f);
    }
    __syncthreads();
    if (t < 32) {
        int branch = t >> 4, o = t & 15;
        const float* w2 = branch ? w_max2 : w_avg2;
        float v = w2[c*16 + o] * hh[branch*16 + o];
#pragma unroll
        for (int off = 1; off <= 16; off <<= 1)
            v += __shfl_xor_sync(0xffffffffu, v, off);
        if (t == 0) gate_s = 1.0f / (1.0f + __expf(-v));
    }
    __syncthreads();

    float gv = gate_s;
    int base = blk * 256 + t;
    float4 v0 = reinterpret_cast<const float4*>(g_out)[base];
    v0.x *= gv; v0.y *= gv; v0.z *= gv; v0.w *= gv;
    reinterpret_cast<float4*>(out)[base] = v0;
}

// ---------------- launch ------------------------------------------------------
extern "C" void kernel_launch(void* const* d_in, const int* in_sizes, int n_in,
                              void* d_out, int out_size)
{
    const float* ftr    = (const float*)d_in[0];
    const float* wq     = (const float*)d_in[1];
    const float* bq     = (const float*)d_in[2];
    const float* wk     = (const float*)d_in[3];
    const float* bk     = (const float*)d_in[4];
    const float* wv     = (const float*)d_in[5];
    const float* bv     = (const float*)d_in[6];
    const float* delta  = (const float*)d_in[7];
    const float* w_avg1 = (const float*)d_in[8];
    const float* w_avg2 = (const float*)d_in[9];
    const float* w_max1 = (const float*)d_in[10];
    const float* w_max2 = (const float*)d_in[11];
    float* out = (float*)d_out;

    cudaFuncSetAttribute(attn_kernel, cudaFuncAttributeMaxDynamicSharedMemorySize,
                         (int)sizeof(SmemB));

    qkv_kernel<<<dim3(PP/64, BB), 384>>>(ftr, wq, bq, wk, bk, wv, bv);
    attn_kernel<<<dim3(PP/NCOL, BB), 512, sizeof(SmemB)>>>(ftr, delta);
    final_kernel<<<1024, 256>>>(out, w_avg1, w_avg2, w_max1, w_max2);
}

// round 15
// speedup vs baseline: 7.4747x; 1.0015x over previous
#include <cuda_runtime.h>
#include <cuda_bf16.h>
#include <math.h>

#define BB 4
#define CC 64
#define CI 16
#define PP 4096
#define NCOL 128
#define TP 128
#define NT (PP/TP)
#define LOG2E 1.4426950408889634f

// ---------------- scratch (device globals; no allocations allowed) ----------
__device__ float    g_q[BB*CI*PP];       // [b][o][p]  fp32
__device__ float    g_k[BB*CI*PP];       // [b][o][p]  fp32
__device__ unsigned g_v32[BB*CC*PP/2];   // [b][c][p/2] packed bf16x2
__device__ float    g_out[BB*CC*PP];     // pre-gate output
__device__ float    g_sum[BB*CC];
__device__ unsigned g_maxk[BB*CC];

__device__ __forceinline__ unsigned fkey(float f) {
    unsigned u = __float_as_uint(f);
    return (u & 0x80000000u) ? ~u : (u | 0x80000000u);
}
__device__ __forceinline__ float funkey(unsigned k) {
    unsigned u = (k & 0x80000000u) ? (k & 0x7FFFFFFFu) : ~k;
    return __uint_as_float(u);
}

// ---------------- cvt / mma / cp.async helpers --------------------------------
__device__ __forceinline__ unsigned tf32cvt(float f) {
    unsigned r;
    asm("cvt.rna.tf32.f32 %0, %1;" : "=r"(r) : "f"(f));
    return r;
}
__device__ __forceinline__ unsigned bf16x2pack(float hi, float lo) {
    unsigned r;
    asm("cvt.rn.bf16x2.f32 %0, %1, %2;" : "=r"(r) : "f"(hi), "f"(lo));
    return r;
}
__device__ __forceinline__ float ex2(float x) {
    float y;
    asm("ex2.approx.f32 %0, %1;" : "=f"(y) : "f"(x));
    return y;
}
__device__ __forceinline__ void mma8(float c[4],
                                     unsigned a0, unsigned a1, unsigned a2, unsigned a3,
                                     unsigned b0, unsigned b1)
{
    asm volatile(
        "mma.sync.aligned.m16n8k8.row.col.f32.tf32.tf32.f32 "
        "{%0,%1,%2,%3},{%4,%5,%6,%7},{%8,%9},{%0,%1,%2,%3};"
        : "+f"(c[0]), "+f"(c[1]), "+f"(c[2]), "+f"(c[3])
        : "r"(a0), "r"(a1), "r"(a2), "r"(a3), "r"(b0), "r"(b1));
}
__device__ __forceinline__ void mma16(float c[4],
                                      unsigned a0, unsigned a1, unsigned a2, unsigned a3,
                                      unsigned b0, unsigned b1)
{
    asm volatile(
        "mma.sync.aligned.m16n8k16.row.col.f32.bf16.bf16.f32 "
        "{%0,%1,%2,%3},{%4,%5,%6,%7},{%8,%9},{%0,%1,%2,%3};"
        : "+f"(c[0]), "+f"(c[1]), "+f"(c[2]), "+f"(c[3])
        : "r"(a0), "r"(a1), "r"(a2), "r"(a3), "r"(b0), "r"(b1));
}
__device__ __forceinline__ void cp16(void* dst, const void* src) {
    unsigned ds = (unsigned)__cvta_generic_to_shared(dst);
    asm volatile("cp.async.cg.shared.global [%0], [%1], 16;" :: "r"(ds), "l"(src));
}
__device__ __forceinline__ unsigned sm_u32(const void* p) {
    return (unsigned)__cvta_generic_to_shared(p);
}

// ---------------- K1: q/k/v projections, tensor cores, async staging ---------
#define WS 68     // W smem row stride (floats)
#define XS 72     // X smem row stride (floats)
__global__ void __launch_bounds__(384)
qkv_kernel(const float* __restrict__ ftr,
           const float* __restrict__ wq, const float* __restrict__ bq,
           const float* __restrict__ wk, const float* __restrict__ bk,
           const float* __restrict__ wv, const float* __restrict__ bv)
{
    __shared__ float wt[96*WS];    // W raw fp32 [row][c] (tf32 by HMMA truncation)
    __shared__ float xs[64*XS];    // X raw fp32 [c][p_local]
    __shared__ float bs[96];

    int tid = threadIdx.x;
    int b   = blockIdx.y;
    int p0  = blockIdx.x * 64;

    for (int f = tid; f < 256; f += 384) {
        int row = f >> 4, s = f & 15;
        cp16(&wt[row*WS + s*4], wq + row*64 + s*4);
    }
    for (int f = tid; f < 256; f += 384) {
        int row = f >> 4, s = f & 15;
        cp16(&wt[(16 + row)*WS + s*4], wk + row*64 + s*4);
    }
    for (int f = tid; f < 1024; f += 384) {
        int row = f >> 4, s = f & 15;
        cp16(&wt[(32 + row)*WS + s*4], wv + row*64 + s*4);
    }
    for (int f = tid; f < 1024; f += 384) {
        int c = f >> 4, s = f & 15;
        cp16(&xs[c*XS + s*4], ftr + ((size_t)b*CC + c)*PP + p0 + s*4);
    }
    asm volatile("cp.async.commit_group;");

    if (tid < 16) bs[tid] = bq[tid];
    else if (tid < 32) bs[tid] = bk[tid - 16];
    else if (tid < 96) bs[tid] = bv[tid - 32];
    if (blockIdx.x == 0 && blockIdx.y == 0 && tid < BB*CC) {
        g_sum[tid] = 0.0f;
        g_maxk[tid] = 0u;
    }
    asm volatile("cp.async.wait_group 0;");
    __syncthreads();

    int w = tid >> 5;
    int lane = tid & 31, r = lane >> 2, q4 = lane & 3;
    int mb = w >> 1, nh = w & 1;
    int m0 = mb * 16, n0 = nh * 32;

    unsigned a[8][4];
#pragma unroll
    for (int ks = 0; ks < 8; ks++) {
        a[ks][0] = __float_as_uint(wt[(m0 + r    )*WS + ks*8 + q4]);
        a[ks][1] = __float_as_uint(wt[(m0 + r + 8)*WS + ks*8 + q4]);
        a[ks][2] = __float_as_uint(wt[(m0 + r    )*WS + ks*8 + q4 + 4]);
        a[ks][3] = __float_as_uint(wt[(m0 + r + 8)*WS + ks*8 + q4 + 4]);
    }

    float c8[4][4];
#pragma unroll
    for (int nb = 0; nb < 4; nb++)
#pragma unroll
        for (int k2 = 0; k2 < 4; k2++) c8[nb][k2] = 0.0f;

#pragma unroll
    for (int ks = 0; ks < 8; ks++)
#pragma unroll
        for (int nb = 0; nb < 4; nb++) {
            unsigned b0 = __float_as_uint(xs[(ks*8 + q4    )*XS + n0 + nb*8 + r]);
            unsigned b1 = __float_as_uint(xs[(ks*8 + q4 + 4)*XS + n0 + nb*8 + r]);
            mma8(c8[nb], a[ks][0], a[ks][1], a[ks][2], a[ks][3], b0, b1);
        }

    float bias0 = bs[m0 + r], bias1 = bs[m0 + r + 8];
#pragma unroll
    for (int nb = 0; nb < 4; nb++) {
        int col = p0 + n0 + nb*8 + q4*2;
        int row0 = m0 + r, row1 = m0 + r + 8;
        float v00 = c8[nb][0] + bias0, v01 = c8[nb][1] + bias0;
        float v10 = c8[nb][2] + bias1, v11 = c8[nb][3] + bias1;
        if (row0 < 16) {
            *reinterpret_cast<float2*>(&g_q[((size_t)b*CI + row0)*PP + col]) = make_float2(v00, v01);
            *reinterpret_cast<float2*>(&g_q[((size_t)b*CI + row1)*PP + col]) = make_float2(v10, v11);
        } else if (row0 < 32) {
            *reinterpret_cast<float2*>(&g_k[((size_t)b*CI + row0 - 16)*PP + col]) = make_float2(v00, v01);
            *reinterpret_cast<float2*>(&g_k[((size_t)b*CI + row1 - 16)*PP + col]) = make_float2(v10, v11);
        } else {
            g_v32[(((size_t)b*CC + row0 - 32)*PP + col) >> 1] = bf16x2pack(v01, v00);
            g_v32[(((size_t)b*CC + row1 - 32)*PP + col) >> 1] = bf16x2pack(v11, v10);
        }
    }
}

// ---------------- K2: flash attention, 128 columns/CTA, chunk-pipelined ------
#define KT 20     // kkT row stride (u32)
#define QT 136    // qqT row stride (u32)
#define VS 68     // vv row stride (u32)

struct SmemB {
    unsigned kkT[NCOL*KT];
    unsigned qqT[3][16*QT];
    unsigned vv[3][64*VS];
    float merge[8][32][32];
    float lsave[NCOL];
    float wsum[8][64];
    float wmax[8][64];
};

extern __shared__ char smem_raw[];

__device__ __forceinline__ void stage_qv(SmemB& sm, int buf, int b, int p0, int tid)
{
    {
        int o = tid >> 5, p4 = tid & 31;
        cp16(&sm.qqT[buf][o*QT + p4*4],
             g_q + ((size_t)b*CI + o)*PP + p0 + p4*4);
    }
    const unsigned* vbase = g_v32 + ((size_t)b*CC*PP >> 1) + (p0 >> 1);
#pragma unroll
    for (int rr = 0; rr < 2; rr++) {
        int fidx = rr*512 + tid;
        int row = fidx >> 4, c4 = fidx & 15;
        cp16(&sm.vv[buf][row*VS + c4*4],
             vbase + (size_t)row*(PP/2) + c4*4);
    }
}

// grid (PP/NCOL, BB), 512 threads (16 warps): warp = (jb = w&7, ph = w>>3)
__global__ void __launch_bounds__(512, 1)
attn_kernel(const float* __restrict__ ftr, const float* __restrict__ delta)
{
    SmemB& sm = *reinterpret_cast<SmemB*>(smem_raw);
    int tid  = threadIdx.x;
    int w    = tid >> 5;
    int lane = tid & 31;
    int r    = lane >> 2;
    int q4   = lane & 3;
    int b    = blockIdx.y;
    int col0 = blockIdx.x * NCOL;

    int jb = w & 7;
    int ph = w >> 3;
    int j0 = jb*16 + r;
    int j1 = j0 + 8;

    stage_qv(sm, 0, b, 0, tid);
    asm volatile("cp.async.commit_group;");
    stage_qv(sm, 1, b, TP, tid);
    asm volatile("cp.async.commit_group;");

    for (int i = tid; i < 16*NCOL; i += 512) {
        int o = i >> 7, jj = i & 127;
        sm.kkT[jj*KT + o] = tf32cvt(g_k[((size_t)(b*CI + o))*PP + col0 + jj] * LOG2E);
    }
    __syncthreads();

    unsigned ka[2][4];
#pragma unroll
    for (int ks = 0; ks < 2; ks++) {
        ka[ks][0] = sm.kkT[(jb*16 + r    )*KT + ks*8 + q4];
        ka[ks][1] = sm.kkT[(jb*16 + r + 8)*KT + ks*8 + q4];
        ka[ks][2] = sm.kkT[(jb*16 + r    )*KT + ks*8 + q4 + 4];
        ka[ks][3] = sm.kkT[(jb*16 + r + 8)*KT + ks*8 + q4 + 4];
    }

    unsigned vv_lane = sm_u32(&sm.vv[0][0])
        + ((((lane >> 4)*8 + (lane & 7))*VS + ((lane >> 3) & 1)*4) << 2);

    float l0 = 0.0f, l1 = 0.0f;

    float cacc[8][4];
#pragma unroll
    for (int nb = 0; nb < 8; nb++)
#pragma unroll
        for (int k2 = 0; k2 < 4; k2++) cacc[nb][k2] = 0.0f;

    for (int t = 0; t < NT; t++) {
        if (t + 1 < NT) asm volatile("cp.async.wait_group 1;");
        else            asm volatile("cp.async.wait_group 0;");
        __syncthreads();

        if (t + 2 < NT) {
            stage_qv(sm, (t + 2) % 3, b, (t + 2)*TP, tid);
            asm volatile("cp.async.commit_group;");
        }
        int buf = t % 3;
        unsigned vbuf = vv_lane + buf*(64*VS*4);

        float sr[8][4];
        // MMA1 for score-pair chunk c (nb = 2c, 2c+1)
        auto mma1_pair = [&](int c) {
#pragma unroll
            for (int u = 0; u < 2; u++) {
                int nb = 2*c + u;
                int pbase = ph*64 + nb*8 + r;
                unsigned b00 = sm.qqT[buf][(q4     )*QT + pbase];
                unsigned b01 = sm.qqT[buf][(q4 + 4 )*QT + pbase];
                unsigned b10 = sm.qqT[buf][(8 + q4 )*QT + pbase];
                unsigned b11 = sm.qqT[buf][(12 + q4)*QT + pbase];
                sr[nb][0] = sr[nb][1] = sr[nb][2] = sr[nb][3] = 0.0f;
                mma8(sr[nb], ka[0][0], ka[0][1], ka[0][2], ka[0][3], b00, b01);
                mma8(sr[nb], ka[1][0], ka[1][1], ka[1][2], ka[1][3], b10, b11);
            }
        };

        // software pipeline: MMA1(c+1) issues between exp(c) and MMA2(c)
        mma1_pair(0);
#pragma unroll
        for (int kk2 = 0; kk2 < 4; kk2++) {
            if (kk2 < 3) mma1_pair(kk2 + 1);

            int nA = 2*kk2, nB = 2*kk2 + 1;
            float eA0 = ex2(sr[nA][0]);
            float eA1 = ex2(sr[nA][1]);
            float eA2 = ex2(sr[nA][2]);
            float eA3 = ex2(sr[nA][3]);
            float eB0 = ex2(sr[nB][0]);
            float eB1 = ex2(sr[nB][1]);
            float eB2 = ex2(sr[nB][2]);
            float eB3 = ex2(sr[nB][3]);
            l0 += (eA0 + eA1) + (eB0 + eB1);
            l1 += (eA2 + eA3) + (eB2 + eB3);
            unsigned a0 = bf16x2pack(eA1, eA0);
            unsigned a1 = bf16x2pack(eA3, eA2);
            unsigned a2 = bf16x2pack(eB1, eB0);
            unsigned a3 = bf16x2pack(eB3, eB2);
            unsigned vk = vbuf + ((ph*32 + kk2*8) << 2);
#pragma unroll
            for (int j = 0; j < 4; j++) {
                unsigned bb0, bb1, bb2, bb3;
                asm volatile(
                    "ldmatrix.sync.aligned.m8n8.x4.shared.b16 {%0,%1,%2,%3}, [%4];"
                    : "=r"(bb0), "=r"(bb1), "=r"(bb2), "=r"(bb3)
                    : "r"(vk + (unsigned)(j*16*VS*4)));
                mma16(cacc[2*j    ], a0, a1, a2, a3, bb0, bb1);
                mma16(cacc[2*j + 1], a0, a1, a2, a3, bb2, bb3);
            }
        }
    }

    l0 += __shfl_xor_sync(0xffffffffu, l0, 1);
    l0 += __shfl_xor_sync(0xffffffffu, l0, 2);
    l1 += __shfl_xor_sync(0xffffffffu, l1, 1);
    l1 += __shfl_xor_sync(0xffffffffu, l1, 2);

    if (ph == 1) {
#pragma unroll
        for (int nb = 0; nb < 8; nb++)
#pragma unroll
            for (int k2 = 0; k2 < 4; k2++)
                sm.merge[jb][nb*4 + k2][lane] = cacc[nb][k2];
        if (q4 == 0) {
            sm.lsave[j0] = l0;
            sm.lsave[j1] = l1;
        }
    }
    __syncthreads();

    if (ph == 0) {
        float lf0 = l0 + sm.lsave[j0];
        float lf1 = l1 + sm.lsave[j1];
#pragma unroll
        for (int nb = 0; nb < 8; nb++)
#pragma unroll
            for (int k2 = 0; k2 < 4; k2++)
                cacc[nb][k2] += sm.merge[jb][nb*4 + k2][lane];

        float dlt  = delta[0];
        float inv0 = 1.0f / lf0;
        float inv1 = 1.0f / lf1;
        float ps[8][2], pm[8][2];
#pragma unroll
        for (int nb = 0; nb < 8; nb++) {
            int c0 = nb*8 + q4*2;
            size_t a00 = ((size_t)b*CC + c0)*PP + col0 + j0;
            size_t a01 = a00 + PP;
            size_t a10 = a00 + 8;
            size_t a11 = a01 + 8;
            float o00 = dlt*cacc[nb][0]*inv0 + ftr[a00];
            float o01 = dlt*cacc[nb][1]*inv0 + ftr[a01];
            float o10 = dlt*cacc[nb][2]*inv1 + ftr[a10];
            float o11 = dlt*cacc[nb][3]*inv1 + ftr[a11];
            g_out[a00] = o00; g_out[a01] = o01;
            g_out[a10] = o10; g_out[a11] = o11;
            ps[nb][0] = o00 + o10;  pm[nb][0] = fmaxf(o00, o10);
            ps[nb][1] = o01 + o11;  pm[nb][1] = fmaxf(o01, o11);
        }
#pragma unroll
        for (int nb = 0; nb < 8; nb++)
#pragma unroll
            for (int par = 0; par < 2; par++) {
#pragma unroll
                for (int off = 4; off <= 16; off <<= 1) {
                    ps[nb][par] += __shfl_xor_sync(0xffffffffu, ps[nb][par], off);
                    pm[nb][par] = fmaxf(pm[nb][par],
                                        __shfl_xor_sync(0xffffffffu, pm[nb][par], off));
                }
            }
        if (r == 0) {
#pragma unroll
            for (int nb = 0; nb < 8; nb++) {
                sm.wsum[jb][nb*8 + q4*2    ] = ps[nb][0];
                sm.wsum[jb][nb*8 + q4*2 + 1] = ps[nb][1];
                sm.wmax[jb][nb*8 + q4*2    ] = pm[nb][0];
                sm.wmax[jb][nb*8 + q4*2 + 1] = pm[nb][1];
            }
        }
    }
    __syncthreads();

    if (tid < 64) {
        float s  = 0.0f;
        float mx = -INFINITY;
#pragma unroll
        for (int g = 0; g < 8; g++) {
            s += sm.wsum[g][tid];
            mx = fmaxf(mx, sm.wmax[g][tid]);
        }
        atomicAdd(&g_sum[b*CC + tid], s);
        atomicMax(&g_maxk[b*CC + tid], fkey(mx));
    }
}

// ---------------- K3: apply gate (per-block gate, parallel layers) -----------
__global__ void final_kernel(float* __restrict__ out,
                             const float* __restrict__ w_avg1, const float* __restrict__ w_avg2,
                             const float* __restrict__ w_max1, const float* __restrict__ w_max2)
{
    __shared__ float hh[32];
    __shared__ float gate_s;
    int t = threadIdx.x;
    int blk = blockIdx.x;
    int b = blk >> 8;
    int c = (blk >> 2) & 63;

    {
        int d = t >> 3, part = t & 7;
        int branch = d >> 4, o = d & 15;
        const float* w1 = branch ? w_max1 : w_avg1;
        float acc = 0.0f;
#pragma unroll
        for (int i = 0; i < 8; i++) {
            int idx = part*8 + i;
            float f = branch ? funkey(g_maxk[b*CC + idx])
                             : g_sum[b*CC + idx] * (1.0f/(float)PP);
            acc += w1[o*64 + idx] * f;
        }
#pragma unroll
        for (int off = 1; off <= 4; off <<= 1)
            acc += __shfl_xor_sync(0xffffffffu, acc, off);
        if (part == 0) hh[d] = fmaxf(acc, 0.0f);
    }
    __syncthreads();
    if (t < 32) {
        int branch = t >> 4, o = t & 15;
        const float* w2 = branch ? w_max2 : w_avg2;
        float v = w2[c*16 + o] * hh[branch*16 + o];
#pragma unroll
        for (int off = 1; off <= 16; off <<= 1)
            v += __shfl_xor_sync(0xffffffffu, v, off);
        if (t == 0) gate_s = 1.0f / (1.0f + __expf(-v));
    }
    __syncthreads();

    float gv = gate_s;
    int base = blk * 256 + t;
    float4 v0 = reinterpret_cast<const float4*>(g_out)[base];
    v0.x *= gv; v0.y *= gv; v0.z *= gv; v0.w *= gv;
    reinterpret_cast<float4*>(out)[base] = v0;
}

// ---------------- launch ------------------------------------------------------
extern "C" void kernel_launch(void* const* d_in, const int* in_sizes, int n_in,
                              void* d_out, int out_size)
{
    const float* ftr    = (const float*)d_in[0];
    const float* wq     = (const float*)d_in[1];
    const float* bq     = (const float*)d_in[2];
    const float* wk     = (const float*)d_in[3];
    const float* bk     = (const float*)d_in[4];
    const float* wv     = (const float*)d_in[5];
    const float* bv     = (const float*)d_in[6];
    const float* delta  = (const float*)d_in[7];
    const float* w_avg1 = (const float*)d_in[8];
    const float* w_avg2 = (const float*)d_in[9];
    const float* w_max1 = (const float*)d_in[10];
    const float* w_max2 = (const float*)d_in[11];
    float* out = (float*)d_out;

    cudaFuncSetAttribute(attn_kernel, cudaFuncAttributeMaxDynamicSharedMemorySize,
                         (int)sizeof(SmemB));

    qkv_kernel<<<dim3(PP/64, BB), 384>>>(ftr, wq, bq, wk, bk, wv, bv);
    attn_kernel<<<dim3(PP/NCOL, BB), 512, sizeof(SmemB)>>>(ftr, delta);
    final_kernel<<<1024, 256>>>(out, w_avg1, w_avg2, w_max1, w_max2);
}

// round 16
// speedup vs baseline: 7.7543x; 1.0374x over previous
#include <cuda_runtime.h>
#include <cuda_bf16.h>
#include <math.h>

#define BB 4
#define CC 64
#define CI 16
#define PP 4096
#define NCOL 128
#define TP 256
#define NT (PP/TP)
#define LOG2E 1.4426950408889634f
#define ONES16 0x3F803F80u

// ---------------- scratch (device globals; no allocations allowed) ----------
__device__ float    g_q[BB*CI*PP];       // [b][o][p]  fp32
__device__ float    g_k[BB*CI*PP];       // [b][o][p]  fp32
__device__ unsigned g_v32[BB*CC*PP/2];   // [b][c][p/2] packed bf16x2
__device__ float    g_out[BB*CC*PP];     // pre-gate output
__device__ float    g_sum[BB*CC];
__device__ unsigned g_maxk[BB*CC];

__device__ __forceinline__ unsigned fkey(float f) {
    unsigned u = __float_as_uint(f);
    return (u & 0x80000000u) ? ~u : (u | 0x80000000u);
}
__device__ __forceinline__ float funkey(unsigned k) {
    unsigned u = (k & 0x80000000u) ? (k & 0x7FFFFFFFu) : ~k;
    return __uint_as_float(u);
}

// ---------------- cvt / mma / cp.async helpers --------------------------------
__device__ __forceinline__ unsigned tf32cvt(float f) {
    unsigned r;
    asm("cvt.rna.tf32.f32 %0, %1;" : "=r"(r) : "f"(f));
    return r;
}
__device__ __forceinline__ unsigned bf16x2pack(float hi, float lo) {
    unsigned r;
    asm("cvt.rn.bf16x2.f32 %0, %1, %2;" : "=r"(r) : "f"(hi), "f"(lo));
    return r;
}
__device__ __forceinline__ float ex2(float x) {
    float y;
    asm("ex2.approx.f32 %0, %1;" : "=f"(y) : "f"(x));
    return y;
}
__device__ __forceinline__ void mma8(float c[4],
                                     unsigned a0, unsigned a1, unsigned a2, unsigned a3,
                                     unsigned b0, unsigned b1)
{
    asm volatile(
        "mma.sync.aligned.m16n8k8.row.col.f32.tf32.tf32.f32 "
        "{%0,%1,%2,%3},{%4,%5,%6,%7},{%8,%9},{%0,%1,%2,%3};"
        : "+f"(c[0]), "+f"(c[1]), "+f"(c[2]), "+f"(c[3])
        : "r"(a0), "r"(a1), "r"(a2), "r"(a3), "r"(b0), "r"(b1));
}
__device__ __forceinline__ void mma16(float c[4],
                                      unsigned a0, unsigned a1, unsigned a2, unsigned a3,
                                      unsigned b0, unsigned b1)
{
    asm volatile(
        "mma.sync.aligned.m16n8k16.row.col.f32.bf16.bf16.f32 "
        "{%0,%1,%2,%3},{%4,%5,%6,%7},{%8,%9},{%0,%1,%2,%3};"
        : "+f"(c[0]), "+f"(c[1]), "+f"(c[2]), "+f"(c[3])
        : "r"(a0), "r"(a1), "r"(a2), "r"(a3), "r"(b0), "r"(b1));
}
__device__ __forceinline__ void cp16(void* dst, const void* src) {
    unsigned ds = (unsigned)__cvta_generic_to_shared(dst);
    asm volatile("cp.async.cg.shared.global [%0], [%1], 16;" :: "r"(ds), "l"(src));
}
__device__ __forceinline__ unsigned sm_u32(const void* p) {
    return (unsigned)__cvta_generic_to_shared(p);
}

// ---------------- K1: q/k/v projections, tensor cores, async staging ---------
#define WS 68     // W smem row stride (floats)
#define XS 72     // X smem row stride (floats)
__global__ void __launch_bounds__(384)
qkv_kernel(const float* __restrict__ ftr,
           const float* __restrict__ wq, const float* __restrict__ bq,
           const float* __restrict__ wk, const float* __restrict__ bk,
           const float* __restrict__ wv, const float* __restrict__ bv)
{
    __shared__ float wt[96*WS];    // W raw fp32 [row][c] (tf32 by HMMA truncation)
    __shared__ float xs[64*XS];    // X raw fp32 [c][p_local]
    __shared__ float bs[96];

    int tid = threadIdx.x;
    int b   = blockIdx.y;
    int p0  = blockIdx.x * 64;

    for (int f = tid; f < 256; f += 384) {
        int row = f >> 4, s = f & 15;
        cp16(&wt[row*WS + s*4], wq + row*64 + s*4);
    }
    for (int f = tid; f < 256; f += 384) {
        int row = f >> 4, s = f & 15;
        cp16(&wt[(16 + row)*WS + s*4], wk + row*64 + s*4);
    }
    for (int f = tid; f < 1024; f += 384) {
        int row = f >> 4, s = f & 15;
        cp16(&wt[(32 + row)*WS + s*4], wv + row*64 + s*4);
    }
    for (int f = tid; f < 1024; f += 384) {
        int c = f >> 4, s = f & 15;
        cp16(&xs[c*XS + s*4], ftr + ((size_t)b*CC + c)*PP + p0 + s*4);
    }
    asm volatile("cp.async.commit_group;");

    if (tid < 16) bs[tid] = bq[tid];
    else if (tid < 32) bs[tid] = bk[tid - 16];
    else if (tid < 96) bs[tid] = bv[tid - 32];
    if (blockIdx.x == 0 && blockIdx.y == 0 && tid < BB*CC) {
        g_sum[tid] = 0.0f;
        g_maxk[tid] = 0u;
    }
    asm volatile("cp.async.wait_group 0;");
    __syncthreads();

    int w = tid >> 5;
    int lane = tid & 31, r = lane >> 2, q4 = lane & 3;
    int mb = w >> 1, nh = w & 1;
    int m0 = mb * 16, n0 = nh * 32;

    unsigned a[8][4];
#pragma unroll
    for (int ks = 0; ks < 8; ks++) {
        a[ks][0] = __float_as_uint(wt[(m0 + r    )*WS + ks*8 + q4]);
        a[ks][1] = __float_as_uint(wt[(m0 + r + 8)*WS + ks*8 + q4]);
        a[ks][2] = __float_as_uint(wt[(m0 + r    )*WS + ks*8 + q4 + 4]);
        a[ks][3] = __float_as_uint(wt[(m0 + r + 8)*WS + ks*8 + q4 + 4]);
    }

    float c8[4][4];
#pragma unroll
    for (int nb = 0; nb < 4; nb++)
#pragma unroll
        for (int k2 = 0; k2 < 4; k2++) c8[nb][k2] = 0.0f;

#pragma unroll
    for (int ks = 0; ks < 8; ks++)
#pragma unroll
        for (int nb = 0; nb < 4; nb++) {
            unsigned b0 = __float_as_uint(xs[(ks*8 + q4    )*XS + n0 + nb*8 + r]);
            unsigned b1 = __float_as_uint(xs[(ks*8 + q4 + 4)*XS + n0 + nb*8 + r]);
            mma8(c8[nb], a[ks][0], a[ks][1], a[ks][2], a[ks][3], b0, b1);
        }

    float bias0 = bs[m0 + r], bias1 = bs[m0 + r + 8];
#pragma unroll
    for (int nb = 0; nb < 4; nb++) {
        int col = p0 + n0 + nb*8 + q4*2;
        int row0 = m0 + r, row1 = m0 + r + 8;
        float v00 = c8[nb][0] + bias0, v01 = c8[nb][1] + bias0;
        float v10 = c8[nb][2] + bias1, v11 = c8[nb][3] + bias1;
        if (row0 < 16) {
            *reinterpret_cast<float2*>(&g_q[((size_t)b*CI + row0)*PP + col]) = make_float2(v00, v01);
            *reinterpret_cast<float2*>(&g_q[((size_t)b*CI + row1)*PP + col]) = make_float2(v10, v11);
        } else if (row0 < 32) {
            *reinterpret_cast<float2*>(&g_k[((size_t)b*CI + row0 - 16)*PP + col]) = make_float2(v00, v01);
            *reinterpret_cast<float2*>(&g_k[((size_t)b*CI + row1 - 16)*PP + col]) = make_float2(v10, v11);
        } else {
            g_v32[(((size_t)b*CC + row0 - 32)*PP + col) >> 1] = bf16x2pack(v01, v00);
            g_v32[(((size_t)b*CC + row1 - 32)*PP + col) >> 1] = bf16x2pack(v11, v10);
        }
    }
}

// ---------------- K2: flash attention, TP=256, l via ones-MMA ----------------
#define KT 20     // kkT row stride (u32)
#define QT 264    // qqT row stride (u32), 256 floats + pad (264*4 % 32banks = 8 -> conflict-free)
#define VS 132    // vv row stride (u32), 128 pairs + pad (132*4/16 = 33 -> wide-bank stride 1)

struct SmemB {
    unsigned kkT[NCOL*KT];       // 10.2 KB
    unsigned qqT[3][16*QT];      // 50.7 KB (Q tile fp32 [o][p], 256 p)
    unsigned vv[3][64*VS];       // 101.4 KB (V tile bf16x2 [c][pu], 128 pairs)
    float merge[8][32][32];      // 32.8 KB
    float lsave[NCOL];
    float wsum[8][64];
    float wmax[8][64];
};

extern __shared__ char smem_raw[];

__device__ __forceinline__ void stage_qv(SmemB& sm, int buf, int b, int p0, int tid)
{
    // Q: 16 x 256 fp32 = 1024 float4, 2 per thread
#pragma unroll
    for (int u = 0; u < 2; u++) {
        int fidx = tid + u*512;
        int o = fidx >> 6, p4 = fidx & 63;
        cp16(&sm.qqT[buf][o*QT + p4*4],
             g_q + ((size_t)b*CI + o)*PP + p0 + p4*4);
    }
    // V: 64 x 128 u32 = 2048 uint4, 4 per thread
    const unsigned* vbase = g_v32 + ((size_t)b*CC*PP >> 1) + (p0 >> 1);
#pragma unroll
    for (int rr = 0; rr < 4; rr++) {
        int fidx = rr*512 + tid;
        int row = fidx >> 5, c4 = fidx & 31;
        cp16(&sm.vv[buf][row*VS + c4*4],
             vbase + (size_t)row*(PP/2) + c4*4);
    }
}

// grid (PP/NCOL, BB), 512 threads (16 warps): warp = (jb = w&7, ph = w>>3)
__global__ void __launch_bounds__(512, 1)
attn_kernel(const float* __restrict__ ftr, const float* __restrict__ delta)
{
    SmemB& sm = *reinterpret_cast<SmemB*>(smem_raw);
    int tid  = threadIdx.x;
    int w    = tid >> 5;
    int lane = tid & 31;
    int r    = lane >> 2;
    int q4   = lane & 3;
    int b    = blockIdx.y;
    int col0 = blockIdx.x * NCOL;

    int jb = w & 7;
    int ph = w >> 3;
    int j0 = jb*16 + r;
    int j1 = j0 + 8;

    stage_qv(sm, 0, b, 0, tid);
    asm volatile("cp.async.commit_group;");
    stage_qv(sm, 1, b, TP, tid);
    asm volatile("cp.async.commit_group;");

    for (int i = tid; i < 16*NCOL; i += 512) {
        int o = i >> 7, jj = i & 127;
        sm.kkT[jj*KT + o] = tf32cvt(g_k[((size_t)(b*CI + o))*PP + col0 + jj] * LOG2E);
    }
    __syncthreads();

    unsigned ka[2][4];
#pragma unroll
    for (int ks = 0; ks < 2; ks++) {
        ka[ks][0] = sm.kkT[(jb*16 + r    )*KT + ks*8 + q4];
        ka[ks][1] = sm.kkT[(jb*16 + r + 8)*KT + ks*8 + q4];
        ka[ks][2] = sm.kkT[(jb*16 + r    )*KT + ks*8 + q4 + 4];
        ka[ks][3] = sm.kkT[(jb*16 + r + 8)*KT + ks*8 + q4 + 4];
    }

    unsigned vv_lane = sm_u32(&sm.vv[0][0])
        + ((((lane >> 4)*8 + (lane & 7))*VS + ((lane >> 3) & 1)*4) << 2);

    float cacc[8][4];
#pragma unroll
    for (int nb = 0; nb < 8; nb++)
#pragma unroll
        for (int k2 = 0; k2 < 4; k2++) cacc[nb][k2] = 0.0f;
    float lcc[4] = {0.0f, 0.0f, 0.0f, 0.0f};   // l accumulator via ones-MMA

    for (int t = 0; t < NT; t++) {
        if (t + 1 < NT) asm volatile("cp.async.wait_group 1;");
        else            asm volatile("cp.async.wait_group 0;");
        __syncthreads();

        if (t + 2 < NT) {
            stage_qv(sm, (t + 2) % 3, b, (t + 2)*TP, tid);
            asm volatile("cp.async.commit_group;");
        }
        int buf = t % 3;
        unsigned vbuf = vv_lane + buf*(64*VS*4);
        const unsigned* qq = &sm.qqT[buf][0];

        // rolling score buffers: srP[pp][u][4] (chunk pair = 16 p-columns of S^T)
        float srP[2][2][4];
        auto mma1_pair = [&](int c, int pp) {
#pragma unroll
            for (int u = 0; u < 2; u++) {
                int nb = 2*c + u;
                int pbase = ph*128 + nb*8 + r;
                unsigned b00 = qq[(q4     )*QT + pbase];
                unsigned b01 = qq[(q4 + 4 )*QT + pbase];
                unsigned b10 = qq[(8 + q4 )*QT + pbase];
                unsigned b11 = qq[(12 + q4)*QT + pbase];
                float* s = srP[pp][u];
                s[0] = s[1] = s[2] = s[3] = 0.0f;
                mma8(s, ka[0][0], ka[0][1], ka[0][2], ka[0][3], b00, b01);
                mma8(s, ka[1][0], ka[1][1], ka[1][2], ka[1][3], b10, b11);
            }
        };

        mma1_pair(0, 0);
#pragma unroll
        for (int c = 0; c < 8; c++) {
            int cur = c & 1;
            if (c < 7) mma1_pair(c + 1, cur ^ 1);

            const float* sA = srP[cur][0];
            const float* sB = srP[cur][1];
            float eA0 = ex2(sA[0]);
            float eA1 = ex2(sA[1]);
            float eA2 = ex2(sA[2]);
            float eA3 = ex2(sA[3]);
            float eB0 = ex2(sB[0]);
            float eB1 = ex2(sB[1]);
            float eB2 = ex2(sB[2]);
            float eB3 = ex2(sB[3]);
            unsigned a0 = bf16x2pack(eA1, eA0);
            unsigned a1 = bf16x2pack(eA3, eA2);
            unsigned a2 = bf16x2pack(eB1, eB0);
            unsigned a3 = bf16x2pack(eB3, eB2);

            // l accumulation on the tensor pipe: B = ones
            mma16(lcc, a0, a1, a2, a3, ONES16, ONES16);

            unsigned vk = vbuf + ((ph*64 + c*8) << 2);
#pragma unroll
            for (int j = 0; j < 4; j++) {
                unsigned bb0, bb1, bb2, bb3;
                asm volatile(
                    "ldmatrix.sync.aligned.m8n8.x4.shared.b16 {%0,%1,%2,%3}, [%4];"
                    : "=r"(bb0), "=r"(bb1), "=r"(bb2), "=r"(bb3)
                    : "r"(vk + (unsigned)(j*16*VS*4)));
                mma16(cacc[2*j    ], a0, a1, a2, a3, bb0, bb1);
                mma16(cacc[2*j + 1], a0, a1, a2, a3, bb2, bb3);
            }
        }
    }

    // l from ones-MMA: lcc[0] = l(j0), lcc[2] = l(j1) (identical across quad lanes)
    float l0 = lcc[0];
    float l1 = lcc[2];

    if (ph == 1) {
#pragma unroll
        for (int nb = 0; nb < 8; nb++)
#pragma unroll
            for (int k2 = 0; k2 < 4; k2++)
                sm.merge[jb][nb*4 + k2][lane] = cacc[nb][k2];
        if (q4 == 0) {
            sm.lsave[j0] = l0;
            sm.lsave[j1] = l1;
        }
    }
    __syncthreads();

    if (ph == 0) {
        float lf0 = l0 + sm.lsave[j0];
        float lf1 = l1 + sm.lsave[j1];
#pragma unroll
        for (int nb = 0; nb < 8; nb++)
#pragma unroll
            for (int k2 = 0; k2 < 4; k2++)
                cacc[nb][k2] += sm.merge[jb][nb*4 + k2][lane];

        float dlt  = delta[0];
        float inv0 = 1.0f / lf0;
        float inv1 = 1.0f / lf1;
        float ps[8][2], pm[8][2];
#pragma unroll
        for (int nb = 0; nb < 8; nb++) {
            int c0 = nb*8 + q4*2;
            size_t a00 = ((size_t)b*CC + c0)*PP + col0 + j0;
            size_t a01 = a00 + PP;
            size_t a10 = a00 + 8;
            size_t a11 = a01 + 8;
            float o00 = dlt*cacc[nb][0]*inv0 + ftr[a00];
            float o01 = dlt*cacc[nb][1]*inv0 + ftr[a01];
            float o10 = dlt*cacc[nb][2]*inv1 + ftr[a10];
            float o11 = dlt*cacc[nb][3]*inv1 + ftr[a11];
            g_out[a00] = o00; g_out[a01] = o01;
            g_out[a10] = o10; g_out[a11] = o11;
            ps[nb][0] = o00 + o10;  pm[nb][0] = fmaxf(o00, o10);
            ps[nb][1] = o01 + o11;  pm[nb][1] = fmaxf(o01, o11);
        }
#pragma unroll
        for (int nb = 0; nb < 8; nb++)
#pragma unroll
            for (int par = 0; par < 2; par++) {
#pragma unroll
                for (int off = 4; off <= 16; off <<= 1) {
                    ps[nb][par] += __shfl_xor_sync(0xffffffffu, ps[nb][par], off);
                    pm[nb][par] = fmaxf(pm[nb][par],
                                        __shfl_xor_sync(0xffffffffu, pm[nb][par], off));
                }
            }
        if (r == 0) {
#pragma unroll
            for (int nb = 0; nb < 8; nb++) {
                sm.wsum[jb][nb*8 + q4*2    ] = ps[nb][0];
                sm.wsum[jb][nb*8 + q4*2 + 1] = ps[nb][1];
                sm.wmax[jb][nb*8 + q4*2    ] = pm[nb][0];
                sm.wmax[jb][nb*8 + q4*2 + 1] = pm[nb][1];
            }
        }
    }
    __syncthreads();

    if (tid < 64) {
        float s  = 0.0f;
        float mx = -INFINITY;
#pragma unroll
        for (int g = 0; g < 8; g++) {
            s += sm.wsum[g][tid];
            mx = fmaxf(mx, sm.wmax[g][tid]);
        }
        atomicAdd(&g_sum[b*CC + tid], s);
        atomicMax(&g_maxk[b*CC + tid], fkey(mx));
    }
}

// ---------------- K3: apply gate (per-block gate, parallel layers) -----------
__global__ void final_kernel(float* __restrict__ out,
                             const float* __restrict__ w_avg1, const float* __restrict__ w_avg2,
                             const float* __restrict__ w_max1, const float* __restrict__ w_max2)
{
    __shared__ float hh[32];
    __shared__ float gate_s;
    int t = threadIdx.x;
    int blk = blockIdx.x;
    int b = blk >> 8;
    int c = (blk >> 2) & 63;

    {
        int d = t >> 3, part = t & 7;
        int branch = d >> 4, o = d & 15;
        const float* w1 = branch ? w_max1 : w_avg1;
        float acc = 0.0f;
#pragma unroll
        for (int i = 0; i < 8; i++) {
            int idx = part*8 + i;
            float f = branch ? funkey(g_maxk[b*CC + idx])
                             : g_sum[b*CC + idx] * (1.0f/(float)PP);
            acc += w1[o*64 + idx] * f;
        }
#pragma unroll
        for (int off = 1; off <= 4; off <<= 1)
            acc += __shfl_xor_sync(0xffffffffu, acc, off);
        if (part == 0) hh[d] = fmaxf(acc, 0.0f);
    }
    __syncthreads();
    if (t < 32) {
        int branch = t >> 4, o = t & 15;
        const float* w2 = branch ? w_max2 : w_avg2;
        float v = w2[c*16 + o] * hh[branch*16 + o];
#pragma unroll
        for (int off = 1; off <= 16; off <<= 1)
            v += __shfl_xor_sync(0xffffffffu, v, off);
        if (t == 0) gate_s = 1.0f / (1.0f + __expf(-v));
    }
    __syncthreads();

    float gv = gate_s;
    int base = blk * 256 + t;
    float4 v0 = reinterpret_cast<const float4*>(g_out)[base];
    v0.x *= gv; v0.y *= gv; v0.z *= gv; v0.w *= gv;
    reinterpret_cast<float4*>(out)[base] = v0;
}

// ---------------- launch ------------------------------------------------------
extern "C" void kernel_launch(void* const* d_in, const int* in_sizes, int n_in,
                              void* d_out, int out_size)
{
    const float* ftr    = (const float*)d_in[0];
    const float* wq     = (const float*)d_in[1];
    const float* bq     = (const float*)d_in[2];
    const float* wk     = (const float*)d_in[3];
    const float* bk     = (const float*)d_in[4];
    const float* wv     = (const float*)d_in[5];
    const float* bv     = (const float*)d_in[6];
    const float* delta  = (const float*)d_in[7];
    const float* w_avg1 = (const float*)d_in[8];
    const float* w_avg2 = (const float*)d_in[9];
    const float* w_max1 = (const float*)d_in[10];
    const float* w_max2 = (const float*)d_in[11];
    float* out = (float*)d_out;

    cudaFuncSetAttribute(attn_kernel, cudaFuncAttributeMaxDynamicSharedMemorySize,
                         (int)sizeof(SmemB));

    qkv_kernel<<<dim3(PP/64, BB), 384>>>(ftr, wq, bq, wk, bk, wv, bv);
    attn_kernel<<<dim3(PP/NCOL, BB), 512, sizeof(SmemB)>>>(ftr, delta);
    final_kernel<<<1024, 256>>>(out, w_avg1, w_avg2, w_max1, w_max2);
}